// round 12
// baseline (speedup 1.0000x reference)
#include <cuda_runtime.h>
#include <cuda_bf16.h>
#include <cfloat>
#include <math.h>
#include <cstdint>

#if defined(__CUDA_ARCH__) && defined(__CUDA_ARCH_FEAT_SM103_ALL)
#define HAS_TC 1
#else
#define HAS_TC 0
#endif

// ---------------- problem constants ----------------
#define BB    4
#define NN    2048
#define KNB   21
#define CIN   64
#define CO    256
#define HEADS 7
#define WCH   64
#define FUSC  (HEADS*WCH)          /* 448 */
#define MTOT  (BB*NN)              /* 8192 */
#define RTOT  (MTOT*KNB)           /* 172032 */
#define EPSB  1e-5f
#define NFEATCTA (RTOT/128)        /* 1344 */
#define NGEOREG  2048              /* geo stat regions (4 points each) */

// ---------------- scratch ----------------
__device__ int    g_idx[RTOT];
__device__ float  g_ft[MTOT*CIN];
__device__ float  g_act[(size_t)RTOT*CO];
__device__ float  g_featv[MTOT*CO];
__device__ float  g_q[MTOT*CO];
__device__ float  g_k[MTOT*CO];
__device__ float  g_v[MTOT*CO];
__device__ float  g_rowstat[BB*HEADS*NN*2];
__device__ float  g_fp[MTOT*CO];
__device__ float  g_f2[MTOT*CO];
__device__ float  g_partf[256*2*CO];
__device__ float  g_msc[6*2*CO];
__device__ float  g_geo_part[(size_t)NGEOREG*2*128];
__device__ float  g_feat_part[(size_t)NFEATCTA*2*128];
// bf16 hi/lo splits
__device__ __nv_bfloat16 g_ginh[(size_t)RTOT*128], g_ginl[(size_t)RTOT*128];
__device__ __nv_bfloat16 g_xh[MTOT*CO],  g_xl[MTOT*CO];
__device__ __nv_bfloat16 g_qh[MTOT*CO],  g_ql[MTOT*CO];
__device__ __nv_bfloat16 g_kh[MTOT*CO],  g_kl[MTOT*CO];
__device__ __nv_bfloat16 g_yh[MTOT*CO],  g_yl[MTOT*CO];
__device__ __nv_bfloat16 g_Oh[MTOT*FUSC], g_Ol[MTOT*FUSC];
__device__ __nv_bfloat16 g_vth[(size_t)BB*HEADS*WCH*NN], g_vtl[(size_t)BB*HEADS*WCH*NN];
__device__ __nv_bfloat16 g_wfh[128*128],  g_wfl[128*128];
__device__ __nv_bfloat16 g_wqh[CO*CO],    g_wql[CO*CO];
__device__ __nv_bfloat16 g_wkh[CO*CO],    g_wkl[CO*CO];
__device__ __nv_bfloat16 g_wvh[CO*CO],    g_wvl[CO*CO];
__device__ __nv_bfloat16 g_wfush[CO*FUSC],g_wfusl[CO*FUSC];
__device__ __nv_bfloat16 g_wmh[CO*CO],    g_wml[CO*CO];

// ---------------- helpers ----------------
__device__ __forceinline__ uint32_t smem_u32(const void* p) {
    uint32_t a;
    asm("{ .reg .u64 t; cvta.to.shared.u64 t, %1; cvt.u32.u64 %0, t; }" : "=r"(a) : "l"(p));
    return a;
}
__device__ __forceinline__ uint32_t swz(uint32_t o) { return o ^ ((o >> 3) & 0x70); }
__device__ __forceinline__ uint32_t bpackh(__nv_bfloat16 a, __nv_bfloat16 b) {
    __nv_bfloat162 t = __halves2bfloat162(a, b);
    return *reinterpret_cast<uint32_t*>(&t);
}

#if HAS_TC
__device__ __forceinline__ uint32_t elect_one_pred() {
    uint32_t pred;
    asm volatile("{\n\t.reg .pred p;\n\telect.sync _|p, 0xFFFFFFFF;\n\tselp.b32 %0, 1, 0, p;\n\t}" : "=r"(pred));
    return pred;
}

#define MBARRIER_INIT(addr, cnt) \
    asm volatile("mbarrier.init.shared.b64 [%0], %1;" :: "r"((uint32_t)(addr)), "r"((uint32_t)(cnt)) : "memory")

#define MBARRIER_WAIT_PARITY(mbar_smem_addr, phase_parity) do { \
    uint32_t _mbar = (uint32_t)(mbar_smem_addr); \
    uint32_t _parity = (uint32_t)(phase_parity); \
    uint32_t _done; \
    asm volatile("{\n\t.reg .pred p;\n\t" \
        "mbarrier.try_wait.parity.acquire.cta.shared::cta.b64 p, [%1], %2;\n\t" \
        "selp.b32 %0, 1, 0, p;\n\t}" : "=r"(_done) : "r"(_mbar), "r"(_parity) : "memory"); \
    if (!_done) { \
        asm volatile("{\n\t.reg .pred P1;\n\t" \
            "WAIT_LOOP_%=:\n\t" \
            "mbarrier.try_wait.parity.acquire.cta.shared::cta.b64 P1, [%0], %1, 0x989680;\n\t" \
            "@P1 bra.uni WAIT_DONE_%=;\n\t" \
            "bra.uni WAIT_LOOP_%=;\n\t" \
            "WAIT_DONE_%=:\n\t}" :: "r"(_mbar), "r"(_parity) : "memory"); \
    } \
} while(0)

#define TCGEN05_ALLOC(sm, n) \
    asm volatile("tcgen05.alloc.cta_group::1.sync.aligned.shared::cta.b32 [%0], %1;" \
                 :: "r"((uint32_t)(sm)), "r"((uint32_t)(n)) : "memory")
#define TCGEN05_RELINQ() \
    asm volatile("tcgen05.relinquish_alloc_permit.cta_group::1.sync.aligned;")
#define TCGEN05_DEALLOC(t, n) \
    asm volatile("tcgen05.dealloc.cta_group::1.sync.aligned.b32 %0, %1;" :: "r"(t), "r"(n))
#define TCGEN05_COMMIT(mbar) \
    asm volatile("tcgen05.commit.cta_group::1.mbarrier::arrive::one.shared::cluster.b64 [%0];" \
                 :: "r"((uint32_t)(mbar)) : "memory")
#define TCGEN05_FENCE_AFTER()  asm volatile("tcgen05.fence::after_thread_sync;" ::: "memory")
#define TCGEN05_FENCE_BEFORE() asm volatile("tcgen05.fence::before_thread_sync;" ::: "memory")
#define TCGEN05_WAIT_LD()      asm volatile("tcgen05.wait::ld.sync.aligned;" ::: "memory")
#define FENCE_ASYNC_SHARED()   asm volatile("fence.proxy.async.shared::cta;" ::: "memory")

#define TCGEN05_LD_X32(r, addr) \
    asm volatile("tcgen05.ld.sync.aligned.32x32b.x32.b32 " \
        "{%0, %1, %2, %3, %4, %5, %6, %7, %8, %9, %10, %11, %12, %13, %14, %15, " \
        " %16, %17, %18, %19, %20, %21, %22, %23, %24, %25, %26, %27, %28, %29, %30, %31}, [%32];" \
        : "=r"((r)[0]),  "=r"((r)[1]),  "=r"((r)[2]),  "=r"((r)[3]), \
          "=r"((r)[4]),  "=r"((r)[5]),  "=r"((r)[6]),  "=r"((r)[7]), \
          "=r"((r)[8]),  "=r"((r)[9]),  "=r"((r)[10]), "=r"((r)[11]), \
          "=r"((r)[12]), "=r"((r)[13]), "=r"((r)[14]), "=r"((r)[15]), \
          "=r"((r)[16]), "=r"((r)[17]), "=r"((r)[18]), "=r"((r)[19]), \
          "=r"((r)[20]), "=r"((r)[21]), "=r"((r)[22]), "=r"((r)[23]), \
          "=r"((r)[24]), "=r"((r)[25]), "=r"((r)[26]), "=r"((r)[27]), \
          "=r"((r)[28]), "=r"((r)[29]), "=r"((r)[30]), "=r"((r)[31]) \
        : "r"(addr))

static __device__ __forceinline__ uint64_t make_desc(uint32_t addr) {
    const uint64_t base =
        (uint64_t(2) << 61) | (uint64_t(1) << 46) | (uint64_t(64) << 32) | (uint64_t(1) << 16);
    return base | ((uint64_t)(addr >> 4) & 0x3FFF);
}

__device__ __forceinline__ void mma_f16_ss(uint32_t d, uint64_t a, uint64_t b,
                                           uint32_t idesc, uint32_t en) {
    asm volatile(
        "{\n\t.reg .pred p;\n\tsetp.ne.u32 p, %5, 0;\n\t"
        "tcgen05.mma.cta_group::1.kind::f16 [%0], %1, %2, %3, {%4, %4, %4, %4}, p;\n\t}"
        :: "r"(d), "l"(a), "l"(b), "r"(idesc), "r"(0u), "r"(en) : "memory");
}

#define IDESC_N128 ((1u<<4)|(1u<<7)|(1u<<10)|((128u/8)<<17)|((128u/16)<<24))
#define IDESC_N64  ((1u<<4)|(1u<<7)|(1u<<10)|(( 64u/8)<<17)|((128u/16)<<24))

// ---- tensor-GEMM core with register prefetch: 128x128 out, K chunks of 64 ----
__device__ __forceinline__ void tgemm_core(char* sb, uint32_t base,
    const __nv_bfloat16* __restrict__ Ah, const __nv_bfloat16* __restrict__ Al,
    const __nv_bfloat16* __restrict__ Bh, const __nv_bfloat16* __restrict__ Bl,
    float* __restrict__ C, int lda, int ldb, int ldc, int nkc, int m0, int n0)
{
    uint32_t ctrl = base + 65536;
    uint32_t mbar = ctrl + 8;
    int t = threadIdx.x;

    if (t == 0) MBARRIER_INIT(mbar, 1);
    if (t < 32) { TCGEN05_ALLOC(ctrl, 128); TCGEN05_RELINQ(); }
    __syncthreads();
    uint32_t tmem;
    asm volatile("ld.shared.b32 %0, [%1];" : "=r"(tmem) : "r"(ctrl));

    Ah += (size_t)m0 * lda; Al += (size_t)m0 * lda;
    Bh += (size_t)n0 * ldb; Bl += (size_t)n0 * ldb;

    uint64_t dAh = make_desc(base + 0*16384);
    uint64_t dAl = make_desc(base + 1*16384);
    uint64_t dBh = make_desc(base + 2*16384);
    uint64_t dBl = make_desc(base + 3*16384);

    int rb = t >> 4, kq = t & 15;
    uint2 rA[8], rB[8], rC8[8], rD[8];

    auto ldchunk = [&](int kc) {
        int k0 = kc*64;
#pragma unroll
        for (int i = 0; i < 8; i++) {
            int r = rb + i*16;
            rA[i]  = *(const uint2*)(Ah + (size_t)r*lda + k0 + kq*4);
            rB[i]  = *(const uint2*)(Al + (size_t)r*lda + k0 + kq*4);
            rC8[i] = *(const uint2*)(Bh + (size_t)r*ldb + k0 + kq*4);
            rD[i]  = *(const uint2*)(Bl + (size_t)r*ldb + k0 + kq*4);
        }
    };
    auto stchunk = [&]() {
#pragma unroll
        for (int i = 0; i < 8; i++) {
            int r = rb + i*16;
            uint32_t so = swz((uint32_t)(r*128 + kq*8));
            *(uint2*)(sb + 0*16384 + so) = rA[i];
            *(uint2*)(sb + 1*16384 + so) = rB[i];
            *(uint2*)(sb + 2*16384 + so) = rC8[i];
            *(uint2*)(sb + 3*16384 + so) = rD[i];
        }
    };

    ldchunk(0);
    for (int kc = 0; kc < nkc; kc++) {
        if (kc > 0) MBARRIER_WAIT_PARITY(mbar, (kc-1) & 1);
        stchunk();
        __syncthreads();
        if (t < 32) {
            if (elect_one_pred()) {
                FENCE_ASYNC_SHARED();
#pragma unroll
                for (int ks = 0; ks < 4; ks++) {
                    uint64_t o = ks*2;
                    mma_f16_ss(tmem, dAh+o, dBh+o, IDESC_N128, (kc > 0 || ks > 0) ? 1u : 0u);
                    mma_f16_ss(tmem, dAh+o, dBl+o, IDESC_N128, 1u);
                    mma_f16_ss(tmem, dAl+o, dBh+o, IDESC_N128, 1u);
                }
                TCGEN05_COMMIT(mbar);
            }
        }
        if (kc + 1 < nkc) ldchunk(kc + 1);   // overlap LDG with MMA
    }
    MBARRIER_WAIT_PARITY(mbar, (nkc-1) & 1);
    TCGEN05_FENCE_AFTER();

    int w = t >> 5, lane = t & 31;
    int sub = w & 3, half = w >> 2;
    float* Crow = C + (size_t)(m0 + sub*32 + lane)*ldc + n0;
#pragma unroll
    for (int gi = 0; gi < 2; gi++) {
        int g = half*2 + gi;
        uint32_t r[32];
        TCGEN05_LD_X32(r, tmem + g*32);
        TCGEN05_WAIT_LD();
        TCGEN05_FENCE_BEFORE();
#pragma unroll
        for (int j = 0; j < 8; j++)
            *(float4*)(Crow + g*32 + j*4) = make_float4(
                __uint_as_float(r[j*4+0]), __uint_as_float(r[j*4+1]),
                __uint_as_float(r[j*4+2]), __uint_as_float(r[j*4+3]));
    }
    __syncthreads();
    if (t < 32) TCGEN05_DEALLOC(tmem, 128);
}
#else
__device__ __forceinline__ void tgemm_core_simt(
    const __nv_bfloat16* Ah, const __nv_bfloat16* Al,
    const __nv_bfloat16* Bh, const __nv_bfloat16* Bl,
    float* C, int lda, int ldb, int ldc, int nkc, int m0, int n0)
{
    int t = threadIdx.x;
    int m = m0 + (t >> 1);
    int nb = (t & 1) * 64;
    for (int n = nb; n < nb + 64; n++) {
        float acc = 0.0f;
        for (int k = 0; k < nkc*64; k++) {
            float a = __bfloat162float(Ah[(size_t)m*lda+k]) + __bfloat162float(Al[(size_t)m*lda+k]);
            float b = __bfloat162float(Bh[(size_t)(n0+n)*ldb+k]) + __bfloat162float(Bl[(size_t)(n0+n)*ldb+k]);
            acc = fmaf(a, b, acc);
        }
        C[(size_t)m*ldc + n0 + n] = acc;
    }
}
#endif // HAS_TC

#define TG_SMEM (1024 + 4*16384 + 64)

// =====================================================================
// KNN
// =====================================================================
__global__ void knn_kernel(const float* __restrict__ xyz)
{
    __shared__ float d2s[NN];
    __shared__ float rv[256];
    __shared__ int   ri[256];
    int m = blockIdx.x;
    int b = m >> 11;
    int t = threadIdx.x;
    const float* base = xyz + (size_t)(b << 11) * 3;

    float qx = xyz[m*3+0], qy = xyz[m*3+1], qz = xyz[m*3+2];
    float sqq = qx*qx + qy*qy + qz*qz;

    for (int j = t; j < NN; j += 256) {
        float px = base[j*3+0], py = base[j*3+1], pz = base[j*3+2];
        float sqp = px*px + py*py + pz*pz;
        float dot = qx*px + qy*py + qz*pz;
        d2s[j] = sqq + sqp - 2.0f*dot;
    }
    __syncthreads();

    for (int it = 0; it < KNB; it++) {
        float bv = FLT_MAX; int bi = 0x3fffffff;
        for (int j = t; j < NN; j += 256) {
            float v = d2s[j];
            if (v < bv) { bv = v; bi = j; }
        }
        rv[t] = bv; ri[t] = bi;
        __syncthreads();
        for (int s = 128; s; s >>= 1) {
            if (t < s) {
                float ov = rv[t+s]; int oi = ri[t+s];
                if (ov < rv[t] || (ov == rv[t] && oi < ri[t])) { rv[t] = ov; ri[t] = oi; }
            }
            __syncthreads();
        }
        if (t == 0) { g_idx[(size_t)m*KNB + it] = ri[0]; d2s[ri[0]] = FLT_MAX; }
        __syncthreads();
    }
}

// =====================================================================
// transpose f
// =====================================================================
__global__ void transpose_f(const float* __restrict__ f)
{
    __shared__ float tile[32][33];
    int b  = blockIdx.z;
    int n0 = blockIdx.x * 32;
    int c0 = blockIdx.y * 32;
    int tx = threadIdx.x, ty = threadIdx.y;
#pragma unroll
    for (int i = 0; i < 32; i += 8)
        tile[ty+i][tx] = f[((size_t)b*CIN + c0 + ty + i)*NN + n0 + tx];
    __syncthreads();
#pragma unroll
    for (int i = 0; i < 32; i += 8)
        g_ft[((size_t)b*NN + n0 + ty + i)*CIN + c0 + tx] = tile[tx][ty+i];
}

// =====================================================================
// geo pre-activation + fused fp32 stat partials
// grid NGEOREG=2048 regions x 128 threads (channel); 4 points per region
// =====================================================================
__global__ void geo_pre(const float* __restrict__ xyz, const float* __restrict__ Wg)
{
    __shared__ float nb3[KNB*3];
    int region = blockIdx.x;
    int c = threadIdx.x;
    float w0 = Wg[c*6+0], w1 = Wg[c*6+1], w2 = Wg[c*6+2];
    float w3 = Wg[c*6+3], w4 = Wg[c*6+4], w5 = Wg[c*6+5];
    float s = 0.0f, s2 = 0.0f;

    for (int p = 0; p < 4; p++) {
        int m = region*4 + p;
        int b = m >> 11;
        __syncthreads();
        if (c < KNB) {
            int nb = g_idx[(size_t)m*KNB + c];
            const float* pp = xyz + (size_t)((b << 11) + nb)*3;
            nb3[c*3+0] = pp[0]; nb3[c*3+1] = pp[1]; nb3[c*3+2] = pp[2];
        }
        __syncthreads();
        float cx = xyz[m*3+0], cy = xyz[m*3+1], cz = xyz[m*3+2];
        float base = w0*cx + w1*cy + w2*cz;
        float* dst = g_act + (size_t)m*KNB*CO + c;
#pragma unroll 3
        for (int k = 0; k < KNB; k++) {
            float dx = nb3[k*3+0]-cx, dy = nb3[k*3+1]-cy, dz = nb3[k*3+2]-cz;
            float z = base + w3*dx + w4*dy + w5*dz;
            dst[(size_t)k*CO] = z;
            s += z; s2 = fmaf(z, z, s2);
        }
    }
    g_geo_part[(size_t)region*256 + c]       = s;
    g_geo_part[(size_t)region*256 + 128 + c] = s2;
}

// =====================================================================
// gather feat_in -> bf16 split
// =====================================================================
__global__ void gather_feat()
{
    uint32_t tid = blockIdx.x*256u + threadIdx.x;
    uint32_t r = tid >> 5;
    uint32_t c4 = (tid & 31u) * 4u;
    uint32_t m = r / KNB;
    uint32_t b = m >> 11;
    float4 v;
    if (c4 < 64u) {
        uint32_t nb = (uint32_t)g_idx[r];
        v = *(const float4*)(g_ft + (size_t)((b << 11) + nb)*CIN + c4);
    } else {
        v = *(const float4*)(g_ft + (size_t)m*CIN + (c4 - 64u));
    }
    __nv_bfloat16 h0 = __float2bfloat16(v.x);
    __nv_bfloat16 h1 = __float2bfloat16(v.y);
    __nv_bfloat16 h2 = __float2bfloat16(v.z);
    __nv_bfloat16 h3 = __float2bfloat16(v.w);
    size_t o = (size_t)r*128 + c4;
    *(uint2*)(g_ginh + o) = make_uint2(bpackh(h0,h1), bpackh(h2,h3));
    *(uint2*)(g_ginl + o) = make_uint2(
        bpackh(__float2bfloat16(v.x - __bfloat162float(h0)),
               __float2bfloat16(v.y - __bfloat162float(h1))),
        bpackh(__float2bfloat16(v.z - __bfloat162float(h2)),
               __float2bfloat16(v.w - __bfloat162float(h3))));
}

// =====================================================================
// feat GEMM with fused stat partials. grid (1, NFEATCTA), 256 threads
// =====================================================================
#define FEAT_SMEM (1024 + 69632 + 64)

__global__ void __launch_bounds__(256, 1)
feat_gemm()
{
#if HAS_TC
    extern __shared__ char sm[];
    uint32_t raw = smem_u32(sm);
    uint32_t base = (raw + 1023) & ~1023u;
    char* sb = sm + (base - raw);
    uint32_t ctrl = base + 69632;
    uint32_t mbar = ctrl + 8;
    int t = threadIdx.x;
    int m0 = blockIdx.y * 128;

    if (t == 0) MBARRIER_INIT(mbar, 1);
    if (t < 32) { TCGEN05_ALLOC(ctrl, 128); TCGEN05_RELINQ(); }
    __syncthreads();
    uint32_t tmem;
    asm volatile("ld.shared.b32 %0, [%1];" : "=r"(tmem) : "r"(ctrl));

    const __nv_bfloat16* Ah = g_ginh + (size_t)m0*128;
    const __nv_bfloat16* Al = g_ginl + (size_t)m0*128;
    const __nv_bfloat16* Bh = g_wfh;
    const __nv_bfloat16* Bl = g_wfl;

    uint64_t dAh = make_desc(base + 0*16384);
    uint64_t dAl = make_desc(base + 1*16384);
    uint64_t dBh = make_desc(base + 2*16384);
    uint64_t dBl = make_desc(base + 3*16384);

    int rb = t >> 4, kq = t & 15;
    uint2 rA[8], rB[8], rC8[8], rD[8];
    auto ldchunk = [&](int kc) {
        int k0 = kc*64;
#pragma unroll
        for (int i = 0; i < 8; i++) {
            int r = rb + i*16;
            rA[i]  = *(const uint2*)(Ah + (size_t)r*128 + k0 + kq*4);
            rB[i]  = *(const uint2*)(Al + (size_t)r*128 + k0 + kq*4);
            rC8[i] = *(const uint2*)(Bh + (size_t)r*128 + k0 + kq*4);
            rD[i]  = *(const uint2*)(Bl + (size_t)r*128 + k0 + kq*4);
        }
    };
    ldchunk(0);
    for (int kc = 0; kc < 2; kc++) {
        if (kc > 0) MBARRIER_WAIT_PARITY(mbar, 0);
#pragma unroll
        for (int i = 0; i < 8; i++) {
            int r = rb + i*16;
            uint32_t so = swz((uint32_t)(r*128 + kq*8));
            *(uint2*)(sb + 0*16384 + so) = rA[i];
            *(uint2*)(sb + 1*16384 + so) = rB[i];
            *(uint2*)(sb + 2*16384 + so) = rC8[i];
            *(uint2*)(sb + 3*16384 + so) = rD[i];
        }
        __syncthreads();
        if (t < 32) {
            if (elect_one_pred()) {
                FENCE_ASYNC_SHARED();
#pragma unroll
                for (int ks = 0; ks < 4; ks++) {
                    uint64_t o = ks*2;
                    mma_f16_ss(tmem, dAh+o, dBh+o, IDESC_N128, (kc > 0 || ks > 0) ? 1u : 0u);
                    mma_f16_ss(tmem, dAh+o, dBl+o, IDESC_N128, 1u);
                    mma_f16_ss(tmem, dAl+o, dBh+o, IDESC_N128, 1u);
                }
                TCGEN05_COMMIT(mbar);
            }
        }
        if (kc == 0) ldchunk(1);
    }
    MBARRIER_WAIT_PARITY(mbar, 1);
    TCGEN05_FENCE_AFTER();

    int w = t >> 5, lane = t & 31;
    int sub = w & 3, half = w >> 2;
    int row = sub*32 + lane;
    float* Crow = g_act + (size_t)(m0 + row)*CO + 128;
    float* stile = (float*)sb;   // [128][132], inputs dead now
#pragma unroll
    for (int gi = 0; gi < 2; gi++) {
        int g = half*2 + gi;
        uint32_t r[32];
        TCGEN05_LD_X32(r, tmem + g*32);
        TCGEN05_WAIT_LD();
        TCGEN05_FENCE_BEFORE();
#pragma unroll
        for (int j = 0; j < 8; j++) {
            float4 v = make_float4(
                __uint_as_float(r[j*4+0]), __uint_as_float(r[j*4+1]),
                __uint_as_float(r[j*4+2]), __uint_as_float(r[j*4+3]));
            *(float4*)(Crow + g*32 + j*4) = v;
            *(float4*)(stile + row*132 + g*32 + j*4) = v;
        }
    }
    __syncthreads();
    if (t < 128) {
        float a0=0,a1=0, q0=0,q1=0;
        for (int rr = 0; rr < 128; rr += 2) {
            float v0 = stile[rr*132 + t], v1 = stile[(rr+1)*132 + t];
            a0 += v0; q0 = fmaf(v0,v0,q0);
            a1 += v1; q1 = fmaf(v1,v1,q1);
        }
        g_feat_part[(size_t)blockIdx.y*256 + t]       = a0 + a1;
        g_feat_part[(size_t)blockIdx.y*256 + 128 + t] = q0 + q1;
    }
    __syncthreads();
    if (t < 32) TCGEN05_DEALLOC(tmem, 128);
#else
    int t = threadIdx.x;
    int m0 = blockIdx.y*128;
    int m = m0 + (t >> 1);
    int nb = (t & 1) * 64;
    for (int n = nb; n < nb + 64; n++) {
        float acc = 0.0f;
        for (int k = 0; k < 128; k++) {
            float a = __bfloat162float(g_ginh[(size_t)m*128+k]) + __bfloat162float(g_ginl[(size_t)m*128+k]);
            float b = __bfloat162float(g_wfh[(size_t)n*128+k]) + __bfloat162float(g_wfl[(size_t)n*128+k]);
            acc = fmaf(a, b, acc);
        }
        g_act[(size_t)m*CO + 128 + n] = acc;
    }
    __syncthreads();
    if (t < 128) {
        float s = 0, q = 0;
        for (int rr = 0; rr < 128; rr++) {
            float v = g_act[(size_t)(m0+rr)*CO + 128 + t];
            s += v; q = fmaf(v,v,q);
        }
        g_feat_part[(size_t)blockIdx.y*256 + t] = s;
        g_feat_part[(size_t)blockIdx.y*256 + 128 + t] = q;
    }
#endif
}

// =====================================================================
// combine act stats (geo NGEOREG regions | feat NFEATCTA regions)
// =====================================================================
__global__ void bn_stats_act(float* msc)
{
    int c = threadIdx.x;
    double s = 0.0, s2 = 0.0;
    if (c < 128) {
        for (int r = 0; r < NGEOREG; r++) {
            s  += (double)g_geo_part[(size_t)r*256 + c];
            s2 += (double)g_geo_part[(size_t)r*256 + 128 + c];
        }
    } else {
        int cc = c - 128;
        for (int r = 0; r < NFEATCTA; r++) {
            s  += (double)g_feat_part[(size_t)r*256 + cc];
            s2 += (double)g_feat_part[(size_t)r*256 + 128 + cc];
        }
    }
    double mean = s / (double)RTOT;
    double var  = s2 / (double)RTOT - mean*mean;
    msc[c]      = (float)mean;
    msc[CO + c] = (float)(1.0 / sqrt(var + (double)EPSB));
}

// =====================================================================
// tensor GEMM wrappers
// =====================================================================
__global__ void __launch_bounds__(256, 1)
tgemm(const __nv_bfloat16* __restrict__ Ah, const __nv_bfloat16* __restrict__ Al,
      const __nv_bfloat16* __restrict__ Bh, const __nv_bfloat16* __restrict__ Bl,
      float* __restrict__ C, int lda, int ldb, int ldc, int nkc)
{
#if HAS_TC
    extern __shared__ char sm[];
    uint32_t raw = smem_u32(sm);
    uint32_t base = (raw + 1023) & ~1023u;
    tgemm_core(sm + (base - raw), base, Ah, Al, Bh, Bl, C, lda, ldb, ldc, nkc,
               blockIdx.y*128, blockIdx.x*128);
#else
    tgemm_core_simt(Ah, Al, Bh, Bl, C, lda, ldb, ldc, nkc, blockIdx.y*128, blockIdx.x*128);
#endif
}

__global__ void __launch_bounds__(256, 1)
qkv_gemm()
{
    int z = blockIdx.z;
    const __nv_bfloat16* Bh = (z==0) ? g_wqh : (z==1) ? g_wkh : g_wvh;
    const __nv_bfloat16* Bl = (z==0) ? g_wql : (z==1) ? g_wkl : g_wvl;
    float* C = (z==0) ? g_q : (z==1) ? g_k : g_v;
#if HAS_TC
    extern __shared__ char sm[];
    uint32_t raw = smem_u32(sm);
    uint32_t base = (raw + 1023) & ~1023u;
    tgemm_core(sm + (base - raw), base, g_xh, g_xl, Bh, Bl, C, CO, CO, CO, 4,
               blockIdx.y*128, blockIdx.x*128);
#else
    tgemm_core_simt(g_xh, g_xl, Bh, Bl, C, CO, CO, CO, 4, blockIdx.y*128, blockIdx.x*128);
#endif
}

// =====================================================================
// BN stats (fp32 partials, double combine) — small tensors only
// =====================================================================
__device__ __forceinline__ void bn_partial_region(const float* X, long rows,
                                                  int nblk, int blk, int region)
{
    int c = threadIdx.x;
    long per = (rows + nblk - 1) / nblk;
    long r0 = (long)blk * per;
    long r1 = r0 + per; if (r1 > rows) r1 = rows;
    float a0=0,a1=0,a2=0,a3=0, q0=0,q1=0,q2=0,q3=0;
    long r = r0;
    for (; r + 4 <= r1; r += 4) {
        float v0 = X[(r+0)*CO + c], v1 = X[(r+1)*CO + c];
        float v2 = X[(r+2)*CO + c], v3 = X[(r+3)*CO + c];
        a0 += v0; q0 = fmaf(v0,v0,q0);
        a1 += v1; q1 = fmaf(v1,v1,q1);
        a2 += v2; q2 = fmaf(v2,v2,q2);
        a3 += v3; q3 = fmaf(v3,v3,q3);
    }
    for (; r < r1; r++) { float v = X[r*CO + c]; a0 += v; q0 = fmaf(v,v,q0); }
    g_partf[((size_t)region*2 + 0)*CO + c] = (a0+a1) + (a2+a3);
    g_partf[((size_t)region*2 + 1)*CO + c] = (q0+q1) + (q2+q3);
}

__global__ void bn_stats_partial(const float* __restrict__ X, long rows)
{
    bn_partial_region(X, rows, gridDim.x, blockIdx.x, blockIdx.x);
}

__global__ void bn_stats_final(int nblocks, long rows, float* msc)
{
    int c = threadIdx.x;
    double s = 0.0, s2 = 0.0;
    for (int i = 0; i < nblocks; i++) {
        s  += (double)g_partf[((size_t)i*2 + 0)*CO + c];
        s2 += (double)g_partf[((size_t)i*2 + 1)*CO + c];
    }
    double mean = s / (double)rows;
    double var  = s2 / (double)rows - mean*mean;
    msc[c]      = (float)mean;
    msc[CO + c] = (float)(1.0 / sqrt(var + (double)EPSB));
}

__global__ void bn_stats_qkv()
{
    const float* X = (blockIdx.y==0) ? g_q : (blockIdx.y==1) ? g_k : g_v;
    bn_partial_region(X, MTOT, 64, blockIdx.x, blockIdx.y*64 + blockIdx.x);
}
__global__ void bn_final_qkv(float* msc)
{
    int y = blockIdx.x;
    int c = threadIdx.x;
    double s = 0.0, s2 = 0.0;
    for (int i = y*64; i < y*64 + 64; i++) {
        s  += (double)g_partf[((size_t)i*2 + 0)*CO + c];
        s2 += (double)g_partf[((size_t)i*2 + 1)*CO + c];
    }
    double mean = s / (double)MTOT;
    double var  = s2 / (double)MTOT - mean*mean;
    msc[(2+y)*512 + c]      = (float)mean;
    msc[(2+y)*512 + CO + c] = (float)(1.0 / sqrt(var + (double)EPSB));
}

// =====================================================================
// branch BN + relu + maxpool
// =====================================================================
__global__ void branch_apply(const float* msc,
                             const float* __restrict__ g_geo, const float* __restrict__ b_geo,
                             const float* __restrict__ g_fea, const float* __restrict__ b_fea)
{
    int m = blockIdx.x;
    int c = threadIdx.x;
    float mean = msc[c], istd = msc[CO + c];
    float ga = (c < 128) ? g_geo[c] : g_fea[c - 128];
    float be = (c < 128) ? b_geo[c] : b_fea[c - 128];
    float sc = istd * ga;
    float best = -FLT_MAX;
    const float* base = g_act + (size_t)m*KNB*CO + c;
#pragma unroll 3
    for (int k = 0; k < KNB; k++) {
        float zv = base[(size_t)k*CO];
        float y = (zv - mean) * sc + be;
        y = fmaxf(y, 0.0f);
        best = fmaxf(best, y);
    }
    g_featv[(size_t)m*CO + c] = best;
}

// =====================================================================
// BN apply variants
// =====================================================================
__global__ void bn_apply(const float* __restrict__ in, float* __restrict__ out,
                         const float* msc,
                         const float* __restrict__ gamma, const float* __restrict__ beta,
                         const float* __restrict__ res, int do_relu)
{
    size_t i = (size_t)blockIdx.x * blockDim.x + threadIdx.x;
    int c = (int)(i & (CO-1));
    float y = (in[i] - msc[c]) * msc[CO + c] * gamma[c] + beta[c];
    if (do_relu) y = fmaxf(y, 0.0f);
    if (res) y += res[i];
    out[i] = y;
}

__global__ void bn_apply_split(const float* __restrict__ in,
                               const float* msc,
                               const float* __restrict__ gamma, const float* __restrict__ beta,
                               int do_relu,
                               __nv_bfloat16* __restrict__ oh, __nv_bfloat16* __restrict__ ol)
{
    size_t i = (size_t)blockIdx.x * blockDim.x + threadIdx.x;
    int c = (int)(i & (CO-1));
    float y = (in[i] - msc[c]) * msc[CO + c] * gamma[c] + beta[c];
    if (do_relu) y = fmaxf(y, 0.0f);
    __nv_bfloat16 hb = __float2bfloat16(y);
    oh[i] = hb;
    ol[i] = __float2bfloat16(y - __bfloat162float(hb));
}

__global__ void bn_apply_qkv(const float* msc,
                             const float* __restrict__ gq, const float* __restrict__ bq,
                             const float* __restrict__ gk, const float* __restrict__ bk,
                             const float* __restrict__ gv, const float* __restrict__ bv)
{
    int y = blockIdx.y;
    size_t i = (size_t)blockIdx.x * 256 + threadIdx.x;
    int c = (int)(i & (CO-1));
    const float* in = (y==0) ? g_q : (y==1) ? g_k : g_v;
    const float* ga = (y==0) ? gq : (y==1) ? gk : gv;
    const float* be = (y==0) ? bq : (y==1) ? bk : bv;
    const float* ms = msc + (2+y)*512;
    float v = fmaxf((in[i] - ms[c]) * ms[CO + c] * ga[c] + be[c], 0.0f);
    if (y == 2) { g_v[i] = v; return; }
    __nv_bfloat16 hb = __float2bfloat16(v);
    __nv_bfloat16 lb = __float2bfloat16(v - __bfloat162float(hb));
    if (y == 0) { g_qh[i] = hb; g_ql[i] = lb; }
    else        { g_kh[i] = hb; g_kl[i] = lb; }
}

// =====================================================================
// fused weight splits
// =====================================================================
__global__ void split_weights(const float* __restrict__ Wf, const float* __restrict__ Wq,
                              const float* __restrict__ Wk, const float* __restrict__ Wv,
                              const float* __restrict__ Wfus, const float* __restrict__ Wm)
{
    int i = blockIdx.x*256 + threadIdx.x;
    const float* src; __nv_bfloat16 *dh, *dl; int off;
    if      (i < 16384)  { src = Wf;   dh = g_wfh;   dl = g_wfl;   off = i; }
    else if (i < 81920)  { src = Wq;   dh = g_wqh;   dl = g_wql;   off = i - 16384; }
    else if (i < 147456) { src = Wk;   dh = g_wkh;   dl = g_wkl;   off = i - 81920; }
    else if (i < 212992) { src = Wv;   dh = g_wvh;   dl = g_wvl;   off = i - 147456; }
    else if (i < 327680) { src = Wfus; dh = g_wfush; dl = g_wfusl; off = i - 212992; }
    else                 { src = Wm;   dh = g_wmh;   dl = g_wml;   off = i - 327680; }
    float v = src[off];
    __nv_bfloat16 hb = __float2bfloat16(v);
    dh[off] = hb;
    dl[off] = __float2bfloat16(v - __bfloat162float(hb));
}

// =====================================================================
// v -> per-head transposed bf16 split
// =====================================================================
__global__ void vt_convert()
{
    __shared__ float tile[32][33];
    int z  = blockIdx.z;
    int b  = z / HEADS, h = z - b*HEADS;
    int m0 = blockIdx.x * 32;
    int c0 = blockIdx.y * 32;
    int tx = threadIdx.x, ty = threadIdx.y;
#pragma unroll
    for (int i = 0; i < 32; i += 8)
        tile[ty+i][tx] = g_v[((size_t)(b*NN) + m0 + ty + i)*CO + h*32 + c0 + tx];
    __syncthreads();
#pragma unroll
    for (int i = 0; i < 32; i += 8) {
        int c = c0 + ty + i, m = m0 + tx;
        float v = tile[tx][ty+i];
        __nv_bfloat16 hb = __float2bfloat16(v);
        size_t o = (size_t)z*WCH*NN + (size_t)c*NN + m;
        g_vth[o] = hb;
        g_vtl[o] = __float2bfloat16(v - __bfloat162float(hb));
    }
}

// =====================================================================
// FLASH pass 1: per-row softmax stats (S never stored), register prefetch.
// grid (16 m-tiles, 28 z), 256 threads. smem 68KB -> multi-CTA/SM.
// =====================================================================
#define ST_SMEM (1024 + 65536 + 64 + 1088)

__global__ void __launch_bounds__(256, 1)
attn_stats()
{
#if HAS_TC
    extern __shared__ char sm[];
    uint32_t raw = smem_u32(sm);
    uint32_t base = (raw + 1023) & ~1023u;
    char* sb = sm + (base - raw);
    uint32_t ctrl = base + 65536;
    uint32_t mbar = ctrl + 8;
    float2* mrg = (float2*)(sb + 65536 + 64);   // [row][half]

    int t = threadIdx.x;
    int z = blockIdx.y;
    int b = z / HEADS, h = z - b*HEADS;
    int m0 = blockIdx.x * 128;

    if (t == 0) MBARRIER_INIT(mbar, 1);
    if (t < 32) { TCGEN05_ALLOC(ctrl, 128); TCGEN05_RELINQ(); }
    __syncthreads();
    uint32_t tmem;
    asm volatile("ld.shared.b32 %0, [%1];" : "=r"(tmem) : "r"(ctrl));

    const __nv_bfloat16* pQh = g_qh + ((size_t)(b*NN) + m0)*CO + h*32;
    const __nv_bfloat16* pQl = g_ql + ((size_t)(b*NN) + m0)*CO + h*32;
    const __nv_bfloat16* pKh = g_kh + ((size_t)b*NN)*CO + h*32;
    const __nv_bfloat16* pKl = g_kl + ((size_t)b*NN)*CO + h*32;

    int rb = t >> 4, kq = t & 15;
#pragma unroll
    for (int i = 0; i < 8; i++) {
        int r = rb + i*16;
        uint32_t so = swz((uint32_t)(r*128 + kq*8));
        *(uint2*)(sb + 0*16384 + so) = *(const uint2*)(pQh + (size_t)r*CO + kq*4);
        *(uint2*)(sb + 1*16384 + so) = *(const uint2*)(pQl + (size_t)r*CO + kq*4);
    }

    uint64_t dQh = make_desc(base + 0*16384);
    uint64_t dQl = make_desc(base + 1*16384);
    uint64_t dKh = make_desc(base + 2*16384);
    uint64_t dKl = make_desc(base + 3*16384);

    int w = t >> 5, lane = t & 31;
    int sub = w & 3, half = w >> 2;
    int rrow = sub*32 + lane;

    uint2 kh[8], kl[8];
    auto ldK = [&](int nc) {
        int n0 = nc*128;
#pragma unroll
        for (int i = 0; i < 8; i++) {
            int r = rb + i*16;
            kh[i] = *(const uint2*)(pKh + (size_t)(n0+r)*CO + kq*4);
            kl[i] = *(const uint2*)(pKl + (size_t)(n0+r)*CO + kq*4);
        }
    };
    auto stK = [&]() {
#pragma unroll
        for (int i = 0; i < 8; i++) {
            int r = rb + i*16;
            uint32_t so = swz((uint32_t)(r*128 + kq*8));
            *(uint2*)(sb + 2*16384 + so) = kh[i];
            *(uint2*)(sb + 3*16384 + so) = kl[i];
        }
    };

    float mx = -FLT_MAX, sum = 0.0f;
    ldK(0);
    for (int nc = 0; nc < 16; nc++) {
        stK();
        __syncthreads();
        if (t < 32) {
            if (elect_one_pred()) {
                FENCE_ASYNC_SHARED();
#pragma unroll
                for (int ks = 0; ks < 4; ks++) {
                    uint64_t o = ks*2;
                    mma_f16_ss(tmem, dQh+o, dKh+o, IDESC_N128, (ks > 0) ? 1u : 0u);
                    mma_f16_ss(tmem, dQh+o, dKl+o, IDESC_N128, 1u);
                    mma_f16_ss(tmem, dQl+o, dKh+o, IDESC_N128, 1u);
                }
                TCGEN05_COMMIT(mbar);
            }
        }
        if (nc < 15) ldK(nc + 1);      // overlap LDG with MMA
        MBARRIER_WAIT_PARITY(mbar, nc & 1);
        TCGEN05_FENCE_AFTER();
#pragma unroll
        for (int gi = 0; gi < 2; gi++) {
            int g = half*2 + gi;
            uint32_t r[32];
            TCGEN05_LD_X32(r, tmem + g*32);
            TCGEN05_WAIT_LD();
            float gm = -FLT_MAX;
#pragma unroll
            for (int j = 0; j < 32; j++) gm = fmaxf(gm, __uint_as_float(r[j]));
            float gs = 0.0f;
#pragma unroll
            for (int j = 0; j < 32; j++) gs += __expf(__uint_as_float(r[j]) - gm);
            if (gm <= mx) sum += gs * __expf(gm - mx);
            else { sum = sum * __expf(mx - gm) + gs; mx = gm; }
        }
        __syncthreads();   // all LDTMs done before next MMA overwrites S
    }
    mrg[rrow*2 + half] = make_float2(mx, sum);
    __syncthreads();
    if (half == 0) {
        float2 o = mrg[rrow*2 + 1];
        float M = fmaxf(mx, o.x);
        float S = sum * __expf(mx - M) + o.y * __expf(o.x - M);
        size_t row = (size_t)z*NN + m0 + rrow;
        g_rowstat[row*2]   = M;
        g_rowstat[row*2+1] = 1.0f / S;
    }
    __syncthreads();
    if (t < 32) TCGEN05_DEALLOC(tmem, 128);
#else
    int t = threadIdx.x;
    int z = blockIdx.y;
    int b = z / HEADS, h = z - b*HEADS;
    int m0 = blockIdx.x * 128;
    if (t >= 128) return;
    int m = m0 + t;
    const float* qp = g_q + ((size_t)(b*NN) + m)*CO + h*32;
    float mx = -FLT_MAX;
    for (int n = 0; n < NN; n++) {
        const float* kp = g_k + ((size_t)(b*NN) + n)*CO + h*32;
        float acc = 0.0f;
        for (int k = 0; k < 64; k++) acc = fmaf(qp[k], kp[k], acc);
        mx = fmaxf(mx, acc);
    }
    float sum = 0.0f;
    for (int n = 0; n < NN; n++) {
        const float* kp = g_k + ((size_t)(b*NN) + n)*CO + h*32;
        float acc = 0.0f;
        for (int k = 0; k < 64; k++) acc = fmaf(qp[k], kp[k], acc);
        sum += __expf(acc - mx);
    }
    size_t row = (size_t)z*NN + m;
    g_rowstat[row*2] = mx; g_rowstat[row*2+1] = 1.0f / sum;
#endif
}

// =====================================================================
// FLASH pass 2: recompute S tile, softmax-apply, P·V in TMEM, prefetch.
// grid (16 m-tiles, 28 z), 256 threads.
// TMEM: S cols 0..127, O cols 128..191 (alloc 256)
// =====================================================================
#define FL_SMEM (1024 + 163840 + 64 + 1088)

__global__ void __launch_bounds__(256, 1)
attn_flash()
{
#if HAS_TC
    extern __shared__ char sm[];
    uint32_t raw = smem_u32(sm);
    uint32_t base = (raw + 1023) & ~1023u;
    char* sb = sm + (base - raw);
    const uint32_t off_Qh = 0, off_Ql = 16384, off_Kh = 32768, off_Kl = 49152;
    const uint32_t off_Vh = 65536, off_Vl = 81920, off_Ph = 98304, off_Pl = 131072;
    uint32_t ctrl = base + 163840;
    uint32_t mbar_s = ctrl + 8;
    uint32_t mbar_o = ctrl + 16;
    float* sst = (float*)(sb + 163840 + 64);

    int t = threadIdx.x;
    int z = blockIdx.y;
    int b = z / HEADS, h = z - b*HEADS;
    int m0 = blockIdx.x * 128;

    if (t == 0) { MBARRIER_INIT(mbar_s, 1); MBARRIER_INIT(mbar_o, 1); }
    if (t < 32) { TCGEN05_ALLOC(ctrl, 256); TCGEN05_RELINQ(); }
    sst[t] = g_rowstat[(size_t)(z*NN + m0)*2 + t];
    __syncthreads();
    uint32_t tmem;
    asm volatile("ld.shared.b32 %0, [%1];" : "=r"(tmem) : "r"(ctrl));
    uint32_t tmemO = tmem + 128;

    const __nv_bfloat16* pQh = g_qh + ((size_t)(b*NN) + m0)*CO + h*32;
    const __nv_bfloat16* pQl = g_ql + ((size_t)(b*NN) + m0)*CO + h*32;
    const __nv_bfloat16* pKh = g_kh + ((size_t)b*NN)*CO + h*32;
    const __nv_bfloat16* pKl = g_kl + ((size_t)b*NN)*CO + h*32;
    const __nv_bfloat16* Vh = g_vth + (size_t)z*WCH*NN;
    const __nv_bfloat16* Vl = g_vtl + (size_t)z*WCH*NN;

    int rb = t >> 4, kq = t & 15;
#pragma unroll
    for (int i = 0; i < 8; i++) {
        int r = rb + i*16;
        uint32_t so = swz((uint32_t)(r*128 + kq*8));
        *(uint2*)(sb + off_Qh + so) = *(const uint2*)(pQh + (size_t)r*CO + kq*4);
        *(uint2*)(sb + off_Ql + so) = *(const uint2*)(pQl + (size_t)r*CO + kq*4);
    }

    uint64_t dQh = make_desc(base + off_Qh);
    uint64_t dQl = make_desc(base + off_Ql);
    uint64_t dKh = make_desc(base + off_Kh);
    uint64_t dKl = make_desc(base + off_Kl);

    int w = t >> 5, lane = t & 31;
    int sub = w & 3, half = w >> 2;
    int rrow = sub*32 + lane;
    float mxr = sst[rrow*2], invr = sst[rrow*2+1];

    uint2 kh[8], kl[8], vh[8], vl[8];
    auto ldK = [&](int nc) {
        int n0 = nc*128;
#pragma unroll
        for (int i = 0; i < 8; i++) {
            int r = rb + i*16;
            kh[i] = *(const uint2*)(pKh + (size_t)(n0+r)*CO + kq*4);
            kl[i] = *(const uint2*)(pKl + (size_t)(n0+r)*CO + kq*4);
        }
    };
    auto stK = [&]() {
#pragma unroll
        for (int i = 0; i < 8; i++) {
            int r = rb + i*16;
            uint32_t so = swz((uint32_t)(r*128 + kq*8));
            *(uint2*)(sb + off_Kh + so) = kh[i];
            *(uint2*)(sb + off_Kl + so) = kl[i];
        }
    };
    auto ldV = [&](int nc) {
        int n0 = nc*128;
#pragma unroll
        for (int i = 0; i < 4; i++) {
            int r = rb + i*16;
#pragma unroll
            for (int j = 0; j < 2; j++) {
                size_t gk = (size_t)r*NN + n0 + j*64 + kq*4;
                vh[i*2+j] = *(const uint2*)(Vh + gk);
                vl[i*2+j] = *(const uint2*)(Vl + gk);
            }
        }
    };
    auto stV = [&]() {
#pragma unroll
        for (int i = 0; i < 4; i++) {
            int r = rb + i*16;
            uint32_t so = swz((uint32_t)(r*128 + kq*8));
#pragma unroll
            for (int j = 0; j < 2; j++) {
                *(uint2*)(sb + off_Vh + j*8192 + so) = vh[i*2+j];
                *(uint2*)(sb + off_Vl + j*8192 + so) = vl[i*2+j];
            }
        }
    };

    ldK(0); ldV(0);
    for (int nc = 0; nc < 16; nc++) {
        if (nc > 0) MBARRIER_WAIT_PARITY(mbar_o, (nc-1) & 1);  // V,P smem free
        stK(); stV();
        __syncthreads();
        // S = Q K^T, fresh accumulator each chunk
        if (t < 32) {
            if (elect_one_pred()) {
                FENCE_ASYNC_SHARED();
#pragma unroll
                for (int ks = 0; ks < 4; ks++) {
                    uint64_t o = ks*2;
                    mma_f16_ss(tmem, dQh+o, dKh+o, IDESC_N128, (ks > 0) ? 1u : 0u);
                    mma_f16_ss(tmem, dQh+o, dKl+o, IDESC_N128, 1u);
                    mma_f16_ss(tmem, dQl+o, dKh+o, IDESC_N128, 1u);
                }
                TCGEN05_COMMIT(mbar_s);
            }
        }
        if (nc < 15) { ldK(nc + 1); ldV(nc + 1); }   // overlap LDG with MMA
        MBARRIER_WAIT_PARITY(mbar_s, nc & 1);
        TCGEN05_FENCE_AFTER();

        // read S tile, softmax apply, write P (bf16 split) to smem
#pragma unroll
        for (int gi = 0; gi < 2; gi++) {
            int g = half*2 + gi;
            uint32_t r[32];
            TCGEN05_LD_X32(r, tmem + g*32);
            TCGEN05_WAIT_LD();
#pragma unroll
            for (int j = 0; j < 8; j++) {
                float v0 = __expf(__uint_as_float(r[j*4+0]) - mxr) * invr;
                float v1 = __expf(__uint_as_float(r[j*4+1]) - mxr) * invr;
                float v2 = __expf(__uint_as_float(r[j*4+2]) - mxr) * invr;
                float v3 = __expf(__uint_as_float(r[j*4+3]) - mxr) * invr;
                __nv_bfloat16 h0 = __float2bfloat16(v0);
                __nv_bfloat16 h1 = __float2bfloat16(v1);
                __nv_bfloat16 h2 = __float2bfloat16(v2);
                __nv_bfloat16 h3 = __float2bfloat16(v3);
                uint32_t so = swz((uint32_t)(rrow*128 + (gi*32 + j*4)*2));
                *(uint2*)(sb + off_Ph + half*16384 + so) = make_uint2(bpackh(h0,h1), bpackh(h2,h3));
                *(uint2*)(sb + off_Pl + half*16384 + so) = make_uint2(
                    bpackh(__float2bfloat16(v0 - __bfloat162float(h0)),
                           __float2bfloat16(v1 - __bfloat162float(h1))),
                    bpackh(__float2bfloat16(v2 - __bfloat162float(h2)),
                           __float2bfloat16(v3 - __bfloat162float(h3))));
            }
        }
        __syncthreads();

        // O += P V^T
        if (t < 32) {
            if (elect_one_pred()) {
                FENCE_ASYNC_SHARED();
#pragma unroll
                for (int kch = 0; kch < 2; kch++) {
                    uint64_t dPh = make_desc(base + off_Ph + kch*16384);
                    uint64_t dPl = make_desc(base + off_Pl + kch*16384);
                    uint64_t dVh2 = make_desc(base + off_Vh + kch*8192);
                    uint64_t dVl2 = make_desc(base + off_Vl + kch*8192);
#pragma unroll
                    for (int ks = 0; ks < 4; ks++) {
                        uint64_t o = ks*2;
                        mma_f16_ss(tmemO, dPh+o, dVh2+o, IDESC_N64,
                                   (nc > 0 || kch > 0 || ks > 0) ? 1u : 0u);
                        mma_f16_ss(tmemO, dPh+o, dVl2+o, IDESC_N64, 1u);
                        mma_f16_ss(tmemO, dPl+o, dVh2+o, IDESC_N64, 1u);
                    }
                }
                TCGEN05_COMMIT(mbar_o);
            }
        }
    }
    MBARRIER_WAIT_PARITY(mbar_o, 1);   // (16-1)&1
    TCGEN05_FENCE_AFTER();

    size_t rbase = (size_t)(b*NN + m0 + rrow)*FUSC + h*64 + half*32;
    {
        uint32_t r[32];
        TCGEN05_LD_X32(r, tmemO + half*32);
        TCGEN05_WAIT_LD();
        TCGEN05_FENCE_BEFORE();
#pragma unroll
        for (int j = 0; j < 8; j++) {
            float v0 = __uint_as_float(r[j*4+0]);
            float v1 = __uint_as_float(r[j*4+1]);
            float v2 = __uint_as_float(r[j*4+2]);
            float v3 = __uint_as_float(r[j*4+3]);
            __nv_bfloat16 h0 = __float2bfloat16(v0);
            __nv_bfloat16 h1 = __float2bfloat16(v1);
            __nv_bfloat16 h2 = __float2bfloat16(v2);
            __nv_bfloat16 h3 = __float2bfloat16(v3);
            *(uint2*)(g_Oh + rbase + j*4) = make_uint2(bpackh(h0,h1), bpackh(h2,h3));
            *(uint2*)(g_Ol + rbase + j*4) = make_uint2(
                bpackh(__float2bfloat16(v0 - __bfloat162float(h0)),
                       __float2bfloat16(v1 - __bfloat162float(h1))),
                bpackh(__float2bfloat16(v2 - __bfloat162float(h2)),
                       __float2bfloat16(v3 - __bfloat162float(h3))));
        }
    }
    __syncthreads();
    if (t < 32) TCGEN05_DEALLOC(tmem, 256);
#else
    int t = threadIdx.x;
    int z = blockIdx.y;
    int b = z / HEADS, h = z - b*HEADS;
    int m0 = blockIdx.x * 128;
    if (t >= 128) return;
    int m = m0 + t;
    const float* qp = g_q + ((size_t)(b*NN) + m)*CO + h*32;
    float mxr = g_rowstat[(size_t)(z*NN + m)*2], invr = g_rowstat[(size_t)(z*NN + m)*2+1];
    for (int c = 0; c < 64; c++) {
        float acc = 0.0f;
        for (int n = 0; n < NN; n++) {
            const float* kp = g_k + ((size_t)(b*NN) + n)*CO + h*32;
            float s = 0.0f;
            for (int k = 0; k < 64; k++) s = fmaf(qp[k], kp[k], s);
            acc = fmaf(__expf(s - mxr)*invr, g_v[((size_t)(b*NN) + n)*CO + h*32 + c], acc);
        }
        size_t o = (size_t)(b*NN + m)*FUSC + h*64 + c;
        __nv_bfloat16 hb = __float2bfloat16(acc);
        g_Oh[o] = hb;
        g_Ol[o] = __float2bfloat16(acc - __bfloat162float(hb));
    }
#endif
}

// =====================================================================
// LayerNorm -> bf16 split
// =====================================================================
__global__ void layernorm_kernel(const float* __restrict__ X,
                                 const float* __restrict__ g, const float* __restrict__ b)
{
    int m = blockIdx.x, c = threadIdx.x;
    __shared__ float red[256];
    float v = X[(size_t)m*CO + c];
    red[c] = v; __syncthreads();
    for (int s = 128; s; s >>= 1) { if (c < s) red[c] += red[c+s]; __syncthreads(); }
    float mean = red[0] * (1.0f/CO); __syncthreads();
    float d = v - mean;
    red[c] = d*d; __syncthreads();
    for (int s = 128; s; s >>= 1) { if (c < s) red[c] += red[c+s]; __syncthreads(); }
    float var = red[0] * (1.0f/CO);
    float y = d * rsqrtf(var + EPSB) * g[c] + b[c];
    __nv_bfloat16 hb = __float2bfloat16(y);
    size_t i = (size_t)m*CO + c;
    g_yh[i] = hb;
    g_yl[i] = __float2bfloat16(y - __bfloat162float(hb));
}

// =====================================================================
// final output (transposed)
// =====================================================================
__global__ void final_out(const float* __restrict__ bias, float* __restrict__ out)
{
    __shared__ float tile[32][33];
    int b  = blockIdx.z;
    int n0 = blockIdx.x * 32;
    int c0 = blockIdx.y * 32;
    int tx = threadIdx.x, ty = threadIdx.y;
#pragma unroll
    for (int i = 0; i < 32; i += 8) {
        int n = n0 + ty + i, c = c0 + tx;
        size_t src = ((size_t)b*NN + n)*CO + c;
        tile[ty+i][tx] = g_f2[src] + g_fp[src] + bias[c];
    }
    __syncthreads();
#pragma unroll
    for (int i = 0; i < 32; i += 8) {
        int c = c0 + ty + i, n = n0 + tx;
        out[((size_t)b*CO + c)*NN + n] = tile[tx][ty+i];
    }
}

// =====================================================================
// host
// =====================================================================
extern "C" void kernel_launch(void* const* d_in, const int* in_sizes, int n_in,
                              void* d_out, int out_size)
{
    const float* xyz    = (const float*)d_in[0];
    const float* f      = (const float*)d_in[1];
    const float* W_geo  = (const float*)d_in[2];
    const float* gg     = (const float*)d_in[3];
    const float* bg     = (const float*)d_in[4];
    const float* W_feat = (const float*)d_in[5];
    const float* gf     = (const float*)d_in[6];
    const float* bf     = (const float*)d_in[7];
    const float* g_bn   = (const float*)d_in[8];
    const float* b_bn   = (const float*)d_in[9];
    const float* W_q    = (const float*)d_in[10];
    const float* gq     = (const float*)d_in[11];
    const float* bq     = (const float*)d_in[12];
    const float* W_k    = (const float*)d_in[13];
    const float* gk     = (const float*)d_in[14];
    const float* bk     = (const float*)d_in[15];
    const float* W_v    = (const float*)d_in[16];
    const float* gv     = (const float*)d_in[17];
    const float* bv     = (const float*)d_in[18];
    const float* W_fus  = (const float*)d_in[19];
    /* d_in[20] bias_fus: cancels inside BN */
    const float* gfu    = (const float*)d_in[21];
    const float* bfu    = (const float*)d_in[22];
    const float* g_ln   = (const float*)d_in[23];
    const float* b_ln   = (const float*)d_in[24];
    const float* W_mlp  = (const float*)d_in[25];
    const float* b_mlp  = (const float*)d_in[26];
    float* out = (float*)d_out;

    float *p_featv, *p_fp, *p_f2, *p_msc;
    __nv_bfloat16 *p_yh, *p_yl, *p_Oh, *p_Ol, *p_xh, *p_xl;
    __nv_bfloat16 *p_wfush, *p_wfusl, *p_wmh, *p_wml;
    cudaGetSymbolAddress((void**)&p_featv, g_featv);
    cudaGetSymbolAddress((void**)&p_fp,    g_fp);
    cudaGetSymbolAddress((void**)&p_f2,    g_f2);
    cudaGetSymbolAddress((void**)&p_msc,   g_msc);
    cudaGetSymbolAddress((void**)&p_xh,    g_xh);
    cudaGetSymbolAddress((void**)&p_xl,    g_xl);
    cudaGetSymbolAddress((void**)&p_yh,    g_yh);
    cudaGetSymbolAddress((void**)&p_yl,    g_yl);
    cudaGetSymbolAddress((void**)&p_Oh,    g_Oh);
    cudaGetSymbolAddress((void**)&p_Ol,    g_Ol);
    cudaGetSymbolAddress((void**)&p_wfush, g_wfush);
    cudaGetSymbolAddress((void**)&p_wfusl, g_wfusl);
    cudaGetSymbolAddress((void**)&p_wmh,   g_wmh);
    cudaGetSymbolAddress((void**)&p_wml,   g_wml);

    cudaFuncSetAttribute(attn_stats, cudaFuncAttributeMaxDynamicSharedMemorySize, ST_SMEM);
    cudaFuncSetAttribute(attn_flash, cudaFuncAttributeMaxDynamicSharedMemorySize, FL_SMEM);
    cudaFuncSetAttribute(tgemm,      cudaFuncAttributeMaxDynamicSharedMemorySize, TG_SMEM);
    cudaFuncSetAttribute(qkv_gemm,   cudaFuncAttributeMaxDynamicSharedMemorySize, TG_SMEM);
    cudaFuncSetAttribute(feat_gemm,  cudaFuncAttributeMaxDynamicSharedMemorySize, FEAT_SMEM);

    // ---- 0. weight splits
    split_weights<<<1536, 256>>>(W_feat, W_q, W_k, W_v, W_fus, W_mlp);

    // ---- 1. KNN + transpose + geo (with fused stats) + gather
    knn_kernel<<<MTOT, 256>>>(xyz);
    transpose_f<<<dim3(NN/32, CIN/32, BB), dim3(32,8)>>>(f);
    geo_pre<<<NGEOREG, 128>>>(xyz, W_geo);
    gather_feat<<<RTOT*32/256, 256>>>();

    // ---- 2. feat GEMM (with fused stats)
    feat_gemm<<<dim3(1, NFEATCTA), 256, FEAT_SMEM>>>();

    // ---- 3. act stats (combine partials) + branch apply
    bn_stats_act<<<1, 256>>>(p_msc + 0*512);
    branch_apply<<<MTOT, 256>>>(p_msc + 0*512, gg, bg, gf, bf);

    // ---- 4. BatchNorm1d -> x split
    bn_stats_partial<<<32, 256>>>(p_featv, MTOT);
    bn_stats_final<<<1, 256>>>(32, MTOT, p_msc + 1*512);
    bn_apply_split<<<MTOT, 256>>>(p_featv, p_msc + 1*512, g_bn, b_bn, 0, p_xh, p_xl);

    // ---- 5. q/k/v merged GEMM + stats + apply
    qkv_gemm<<<dim3(2, MTOT/128, 3), 256, TG_SMEM>>>();
    bn_stats_qkv<<<dim3(64, 3), 256>>>();
    bn_final_qkv<<<3, 256>>>(p_msc);
    bn_apply_qkv<<<dim3(MTOT*CO/256, 3), 256>>>(p_msc, gq, bq, gk, bk, gv, bv);
    vt_convert<<<dim3(NN/32, 2, BB*HEADS), dim3(32,8)>>>();

    // ---- 6. flash attention (two kernels: stats then PV)
    attn_stats<<<dim3(16, BB*HEADS), 256, ST_SMEM>>>();
    attn_flash<<<dim3(16, BB*HEADS), 256, FL_SMEM>>>();

    // ---- 7. fus + residual
    tgemm<<<dim3(2, MTOT/128), 256, TG_SMEM>>>(p_Oh, p_Ol, p_wfush, p_wfusl,
                                               p_fp, FUSC, FUSC, CO, 7);
    bn_stats_partial<<<32, 256>>>(p_fp, MTOT);
    bn_stats_final<<<1, 256>>>(32, MTOT, p_msc + 5*512);
    bn_apply<<<MTOT, 256>>>(p_fp, p_f2, p_msc + 5*512, gfu, bfu, p_featv, 1);

    // ---- 8. layernorm + mlp + out
    layernorm_kernel<<<MTOT, 256>>>(p_f2, g_ln, b_ln);
    tgemm<<<dim3(2, MTOT/128), 256, TG_SMEM>>>(p_yh, p_yl, p_wmh, p_wml, p_fp, CO, CO, CO, 4);
    final_out<<<dim3(NN/32, CO/32, BB), dim3(32,8)>>>(b_mlp, out);

    (void)in_sizes; (void)n_in; (void)out_size;
}

// round 13
// speedup vs baseline: 1.3606x; 1.3606x over previous
#include <cuda_runtime.h>
#include <cuda_bf16.h>
#include <cfloat>
#include <math.h>
#include <cstdint>

#if defined(__CUDA_ARCH__) && defined(__CUDA_ARCH_FEAT_SM103_ALL)
#define HAS_TC 1
#else
#define HAS_TC 0
#endif

// ---------------- problem constants ----------------
#define BB    4
#define NN    2048
#define KNB   21
#define CIN   64
#define CO    256
#define HEADS 7
#define WCH   64
#define FUSC  (HEADS*WCH)          /* 448 */
#define MTOT  (BB*NN)              /* 8192 */
#define RTOT  (MTOT*KNB)           /* 172032 */
#define EPSB  1e-5f
#define NGEOREG  2048              /* geo stat regions (4 points each) */

// ---------------- scratch ----------------
__device__ int    g_idx[RTOT];
__device__ float  g_ft[MTOT*CIN];
__device__ float  g_act[(size_t)RTOT*CO];
__device__ float  g_featv[MTOT*CO];
__device__ float  g_q[MTOT*CO];
__device__ float  g_k[MTOT*CO];
__device__ float  g_v[MTOT*CO];
__device__ float  g_rowstat[BB*HEADS*NN*2];
__device__ float  g_fp[MTOT*CO];
__device__ float  g_f2[MTOT*CO];
__device__ float  g_partf[256*2*CO];
__device__ float  g_msc[6*2*CO];
__device__ float  g_geo_part[(size_t)NGEOREG*256];   // [region]{sum[128]|sq[128]}
__device__ float  g_geo_c[64*256];
__device__ float  g_feat_c[128*256];
// bf16 hi/lo splits
__device__ __nv_bfloat16 g_ginh[(size_t)RTOT*128], g_ginl[(size_t)RTOT*128];
__device__ __nv_bfloat16 g_xh[MTOT*CO],  g_xl[MTOT*CO];
__device__ __nv_bfloat16 g_qh[MTOT*CO],  g_ql[MTOT*CO];
__device__ __nv_bfloat16 g_kh[MTOT*CO],  g_kl[MTOT*CO];
__device__ __nv_bfloat16 g_yh[MTOT*CO],  g_yl[MTOT*CO];
__device__ __nv_bfloat16 g_Oh[MTOT*FUSC], g_Ol[MTOT*FUSC];
__device__ __nv_bfloat16 g_vth[(size_t)BB*HEADS*WCH*NN], g_vtl[(size_t)BB*HEADS*WCH*NN];
__device__ __nv_bfloat16 g_wfh[128*128],  g_wfl[128*128];
__device__ __nv_bfloat16 g_wqh[CO*CO],    g_wql[CO*CO];
__device__ __nv_bfloat16 g_wkh[CO*CO],    g_wkl[CO*CO];
__device__ __nv_bfloat16 g_wvh[CO*CO],    g_wvl[CO*CO];
__device__ __nv_bfloat16 g_wfush[CO*FUSC],g_wfusl[CO*FUSC];
__device__ __nv_bfloat16 g_wmh[CO*CO],    g_wml[CO*CO];

// ---------------- helpers ----------------
__device__ __forceinline__ uint32_t smem_u32(const void* p) {
    uint32_t a;
    asm("{ .reg .u64 t; cvta.to.shared.u64 t, %1; cvt.u32.u64 %0, t; }" : "=r"(a) : "l"(p));
    return a;
}
__device__ __forceinline__ uint32_t swz(uint32_t o) { return o ^ ((o >> 3) & 0x70); }
__device__ __forceinline__ uint32_t bpackh(__nv_bfloat16 a, __nv_bfloat16 b) {
    __nv_bfloat162 t = __halves2bfloat162(a, b);
    return *reinterpret_cast<uint32_t*>(&t);
}

#if HAS_TC
__device__ __forceinline__ uint32_t elect_one_pred() {
    uint32_t pred;
    asm volatile("{\n\t.reg .pred p;\n\telect.sync _|p, 0xFFFFFFFF;\n\tselp.b32 %0, 1, 0, p;\n\t}" : "=r"(pred));
    return pred;
}

#define MBARRIER_INIT(addr, cnt) \
    asm volatile("mbarrier.init.shared.b64 [%0], %1;" :: "r"((uint32_t)(addr)), "r"((uint32_t)(cnt)) : "memory")

#define MBARRIER_WAIT_PARITY(mbar_smem_addr, phase_parity) do { \
    uint32_t _mbar = (uint32_t)(mbar_smem_addr); \
    uint32_t _parity = (uint32_t)(phase_parity); \
    uint32_t _done; \
    asm volatile("{\n\t.reg .pred p;\n\t" \
        "mbarrier.try_wait.parity.acquire.cta.shared::cta.b64 p, [%1], %2;\n\t" \
        "selp.b32 %0, 1, 0, p;\n\t}" : "=r"(_done) : "r"(_mbar), "r"(_parity) : "memory"); \
    if (!_done) { \
        asm volatile("{\n\t.reg .pred P1;\n\t" \
            "WAIT_LOOP_%=:\n\t" \
            "mbarrier.try_wait.parity.acquire.cta.shared::cta.b64 P1, [%0], %1, 0x989680;\n\t" \
            "@P1 bra.uni WAIT_DONE_%=;\n\t" \
            "bra.uni WAIT_LOOP_%=;\n\t" \
            "WAIT_DONE_%=:\n\t}" :: "r"(_mbar), "r"(_parity) : "memory"); \
    } \
} while(0)

#define TCGEN05_ALLOC(sm, n) \
    asm volatile("tcgen05.alloc.cta_group::1.sync.aligned.shared::cta.b32 [%0], %1;" \
                 :: "r"((uint32_t)(sm)), "r"((uint32_t)(n)) : "memory")
#define TCGEN05_RELINQ() \
    asm volatile("tcgen05.relinquish_alloc_permit.cta_group::1.sync.aligned;")
#define TCGEN05_DEALLOC(t, n) \
    asm volatile("tcgen05.dealloc.cta_group::1.sync.aligned.b32 %0, %1;" :: "r"(t), "r"(n))
#define TCGEN05_COMMIT(mbar) \
    asm volatile("tcgen05.commit.cta_group::1.mbarrier::arrive::one.shared::cluster.b64 [%0];" \
                 :: "r"((uint32_t)(mbar)) : "memory")
#define TCGEN05_FENCE_AFTER()  asm volatile("tcgen05.fence::after_thread_sync;" ::: "memory")
#define TCGEN05_FENCE_BEFORE() asm volatile("tcgen05.fence::before_thread_sync;" ::: "memory")
#define TCGEN05_WAIT_LD()      asm volatile("tcgen05.wait::ld.sync.aligned;" ::: "memory")
#define FENCE_ASYNC_SHARED()   asm volatile("fence.proxy.async.shared::cta;" ::: "memory")

#define TCGEN05_LD_X32(r, addr) \
    asm volatile("tcgen05.ld.sync.aligned.32x32b.x32.b32 " \
        "{%0, %1, %2, %3, %4, %5, %6, %7, %8, %9, %10, %11, %12, %13, %14, %15, " \
        " %16, %17, %18, %19, %20, %21, %22, %23, %24, %25, %26, %27, %28, %29, %30, %31}, [%32];" \
        : "=r"((r)[0]),  "=r"((r)[1]),  "=r"((r)[2]),  "=r"((r)[3]), \
          "=r"((r)[4]),  "=r"((r)[5]),  "=r"((r)[6]),  "=r"((r)[7]), \
          "=r"((r)[8]),  "=r"((r)[9]),  "=r"((r)[10]), "=r"((r)[11]), \
          "=r"((r)[12]), "=r"((r)[13]), "=r"((r)[14]), "=r"((r)[15]), \
          "=r"((r)[16]), "=r"((r)[17]), "=r"((r)[18]), "=r"((r)[19]), \
          "=r"((r)[20]), "=r"((r)[21]), "=r"((r)[22]), "=r"((r)[23]), \
          "=r"((r)[24]), "=r"((r)[25]), "=r"((r)[26]), "=r"((r)[27]), \
          "=r"((r)[28]), "=r"((r)[29]), "=r"((r)[30]), "=r"((r)[31]) \
        : "r"(addr))

static __device__ __forceinline__ uint64_t make_desc(uint32_t addr) {
    const uint64_t base =
        (uint64_t(2) << 61) | (uint64_t(1) << 46) | (uint64_t(64) << 32) | (uint64_t(1) << 16);
    return base | ((uint64_t)(addr >> 4) & 0x3FFF);
}

__device__ __forceinline__ void mma_f16_ss(uint32_t d, uint64_t a, uint64_t b,
                                           uint32_t idesc, uint32_t en) {
    asm volatile(
        "{\n\t.reg .pred p;\n\tsetp.ne.u32 p, %5, 0;\n\t"
        "tcgen05.mma.cta_group::1.kind::f16 [%0], %1, %2, %3, {%4, %4, %4, %4}, p;\n\t}"
        :: "r"(d), "l"(a), "l"(b), "r"(idesc), "r"(0u), "r"(en) : "memory");
}

#define IDESC_N128 ((1u<<4)|(1u<<7)|(1u<<10)|((128u/8)<<17)|((128u/16)<<24))
#define IDESC_N64  ((1u<<4)|(1u<<7)|(1u<<10)|(( 64u/8)<<17)|((128u/16)<<24))

// ---- tensor-GEMM core (R8 baseline: NO register prefetch) ----
__device__ __forceinline__ void tgemm_core(char* sb, uint32_t base,
    const __nv_bfloat16* __restrict__ Ah, const __nv_bfloat16* __restrict__ Al,
    const __nv_bfloat16* __restrict__ Bh, const __nv_bfloat16* __restrict__ Bl,
    float* __restrict__ C, int lda, int ldb, int ldc, int nkc, int m0, int n0)
{
    uint32_t ctrl = base + 65536;
    uint32_t mbar = ctrl + 8;
    int t = threadIdx.x;

    if (t == 0) MBARRIER_INIT(mbar, 1);
    if (t < 32) { TCGEN05_ALLOC(ctrl, 128); TCGEN05_RELINQ(); }
    __syncthreads();
    uint32_t tmem;
    asm volatile("ld.shared.b32 %0, [%1];" : "=r"(tmem) : "r"(ctrl));

    Ah += (size_t)m0 * lda; Al += (size_t)m0 * lda;
    Bh += (size_t)n0 * ldb; Bl += (size_t)n0 * ldb;

    uint64_t dAh = make_desc(base + 0*16384);
    uint64_t dAl = make_desc(base + 1*16384);
    uint64_t dBh = make_desc(base + 2*16384);
    uint64_t dBl = make_desc(base + 3*16384);

    int rb = t >> 4, kq = t & 15;

    for (int kc = 0; kc < nkc; kc++) {
        if (kc > 0) MBARRIER_WAIT_PARITY(mbar, (kc-1) & 1);
        int k0 = kc*64;
#pragma unroll
        for (int i = 0; i < 8; i++) {
            int r = rb + i*16;
            uint32_t so = swz((uint32_t)(r*128 + kq*8));
            *(uint2*)(sb + 0*16384 + so) = *(const uint2*)(Ah + (size_t)r*lda + k0 + kq*4);
            *(uint2*)(sb + 1*16384 + so) = *(const uint2*)(Al + (size_t)r*lda + k0 + kq*4);
            *(uint2*)(sb + 2*16384 + so) = *(const uint2*)(Bh + (size_t)r*ldb + k0 + kq*4);
            *(uint2*)(sb + 3*16384 + so) = *(const uint2*)(Bl + (size_t)r*ldb + k0 + kq*4);
        }
        __syncthreads();
        if (t < 32) {
            if (elect_one_pred()) {
                FENCE_ASYNC_SHARED();
#pragma unroll
                for (int ks = 0; ks < 4; ks++) {
                    uint64_t o = ks*2;
                    mma_f16_ss(tmem, dAh+o, dBh+o, IDESC_N128, (kc > 0 || ks > 0) ? 1u : 0u);
                    mma_f16_ss(tmem, dAh+o, dBl+o, IDESC_N128, 1u);
                    mma_f16_ss(tmem, dAl+o, dBh+o, IDESC_N128, 1u);
                }
                TCGEN05_COMMIT(mbar);
            }
        }
    }
    MBARRIER_WAIT_PARITY(mbar, (nkc-1) & 1);
    TCGEN05_FENCE_AFTER();

    int w = t >> 5, lane = t & 31;
    int sub = w & 3, half = w >> 2;
    float* Crow = C + (size_t)(m0 + sub*32 + lane)*ldc + n0;
#pragma unroll
    for (int gi = 0; gi < 2; gi++) {
        int g = half*2 + gi;
        uint32_t r[32];
        TCGEN05_LD_X32(r, tmem + g*32);
        TCGEN05_WAIT_LD();
        TCGEN05_FENCE_BEFORE();
#pragma unroll
        for (int j = 0; j < 8; j++)
            *(float4*)(Crow + g*32 + j*4) = make_float4(
                __uint_as_float(r[j*4+0]), __uint_as_float(r[j*4+1]),
                __uint_as_float(r[j*4+2]), __uint_as_float(r[j*4+3]));
    }
    __syncthreads();
    if (t < 32) TCGEN05_DEALLOC(tmem, 128);
}
#else
__device__ __forceinline__ void tgemm_core_simt(
    const __nv_bfloat16* Ah, const __nv_bfloat16* Al,
    const __nv_bfloat16* Bh, const __nv_bfloat16* Bl,
    float* C, int lda, int ldb, int ldc, int nkc, int m0, int n0)
{
    int t = threadIdx.x;
    int m = m0 + (t >> 1);
    int nb = (t & 1) * 64;
    for (int n = nb; n < nb + 64; n++) {
        float acc = 0.0f;
        for (int k = 0; k < nkc*64; k++) {
            float a = __bfloat162float(Ah[(size_t)m*lda+k]) + __bfloat162float(Al[(size_t)m*lda+k]);
            float b = __bfloat162float(Bh[(size_t)(n0+n)*ldb+k]) + __bfloat162float(Bl[(size_t)(n0+n)*ldb+k]);
            acc = fmaf(a, b, acc);
        }
        C[(size_t)m*ldc + n0 + n] = acc;
    }
}
#endif // HAS_TC

#define TG_SMEM (1024 + 4*16384 + 64)

// =====================================================================
// KNN
// =====================================================================
__global__ void knn_kernel(const float* __restrict__ xyz)
{
    __shared__ float d2s[NN];
    __shared__ float rv[256];
    __shared__ int   ri[256];
    int m = blockIdx.x;
    int b = m >> 11;
    int t = threadIdx.x;
    const float* base = xyz + (size_t)(b << 11) * 3;

    float qx = xyz[m*3+0], qy = xyz[m*3+1], qz = xyz[m*3+2];
    float sqq = qx*qx + qy*qy + qz*qz;

    for (int j = t; j < NN; j += 256) {
        float px = base[j*3+0], py = base[j*3+1], pz = base[j*3+2];
        float sqp = px*px + py*py + pz*pz;
        float dot = qx*px + qy*py + qz*pz;
        d2s[j] = sqq + sqp - 2.0f*dot;
    }
    __syncthreads();

    for (int it = 0; it < KNB; it++) {
        float bv = FLT_MAX; int bi = 0x3fffffff;
        for (int j = t; j < NN; j += 256) {
            float v = d2s[j];
            if (v < bv) { bv = v; bi = j; }
        }
        rv[t] = bv; ri[t] = bi;
        __syncthreads();
        for (int s = 128; s; s >>= 1) {
            if (t < s) {
                float ov = rv[t+s]; int oi = ri[t+s];
                if (ov < rv[t] || (ov == rv[t] && oi < ri[t])) { rv[t] = ov; ri[t] = oi; }
            }
            __syncthreads();
        }
        if (t == 0) { g_idx[(size_t)m*KNB + it] = ri[0]; d2s[ri[0]] = FLT_MAX; }
        __syncthreads();
    }
}

// =====================================================================
// transpose f
// =====================================================================
__global__ void transpose_f(const float* __restrict__ f)
{
    __shared__ float tile[32][33];
    int b  = blockIdx.z;
    int n0 = blockIdx.x * 32;
    int c0 = blockIdx.y * 32;
    int tx = threadIdx.x, ty = threadIdx.y;
#pragma unroll
    for (int i = 0; i < 32; i += 8)
        tile[ty+i][tx] = f[((size_t)b*CIN + c0 + ty + i)*NN + n0 + tx];
    __syncthreads();
#pragma unroll
    for (int i = 0; i < 32; i += 8)
        g_ft[((size_t)b*NN + n0 + ty + i)*CIN + c0 + tx] = tile[tx][ty+i];
}

// =====================================================================
// geo pre-activation + fused fp32 stat partials (verified: 19.3us)
// grid NGEOREG=2048 regions x 128 threads; 4 points per region
// =====================================================================
__global__ void geo_pre(const float* __restrict__ xyz, const float* __restrict__ Wg)
{
    __shared__ float nb3[KNB*3];
    int region = blockIdx.x;
    int c = threadIdx.x;
    float w0 = Wg[c*6+0], w1 = Wg[c*6+1], w2 = Wg[c*6+2];
    float w3 = Wg[c*6+3], w4 = Wg[c*6+4], w5 = Wg[c*6+5];
    float s = 0.0f, s2 = 0.0f;

    for (int p = 0; p < 4; p++) {
        int m = region*4 + p;
        int b = m >> 11;
        __syncthreads();
        if (c < KNB) {
            int nb = g_idx[(size_t)m*KNB + c];
            const float* pp = xyz + (size_t)((b << 11) + nb)*3;
            nb3[c*3+0] = pp[0]; nb3[c*3+1] = pp[1]; nb3[c*3+2] = pp[2];
        }
        __syncthreads();
        float cx = xyz[m*3+0], cy = xyz[m*3+1], cz = xyz[m*3+2];
        float base = w0*cx + w1*cy + w2*cz;
        float* dst = g_act + (size_t)m*KNB*CO + c;
#pragma unroll 3
        for (int k = 0; k < KNB; k++) {
            float dx = nb3[k*3+0]-cx, dy = nb3[k*3+1]-cy, dz = nb3[k*3+2]-cz;
            float z = base + w3*dx + w4*dy + w5*dz;
            dst[(size_t)k*CO] = z;
            s += z; s2 = fmaf(z, z, s2);
        }
    }
    g_geo_part[(size_t)region*256 + c]       = s;
    g_geo_part[(size_t)region*256 + 128 + c] = s2;
}

// geo partial combine: 64 blocks x 128 threads, 32 regions each (fixed order)
__global__ void geo_combine()
{
    int c = threadIdx.x;
    int blk = blockIdx.x;
    float s = 0.0f, s2 = 0.0f;
    for (int r = blk*32; r < blk*32 + 32; r++) {
        s  += g_geo_part[(size_t)r*256 + c];
        s2 += g_geo_part[(size_t)r*256 + 128 + c];
    }
    g_geo_c[blk*256 + c]       = s;
    g_geo_c[blk*256 + 128 + c] = s2;
}

// feat half stats: read only cols 128..255 of g_act. 128 blocks x 128 thr.
__global__ void feat_stats_partial()
{
    int c = threadIdx.x;             // channel-128
    const long rows = RTOT, per = RTOT/128;
    long r0 = (long)blockIdx.x * per, r1 = r0 + per;
    const float* X = g_act + 128 + c;
    float a0=0,a1=0,a2=0,a3=0, q0=0,q1=0,q2=0,q3=0;
    long r = r0;
    for (; r + 4 <= r1; r += 4) {
        float v0 = X[(r+0)*CO], v1 = X[(r+1)*CO];
        float v2 = X[(r+2)*CO], v3 = X[(r+3)*CO];
        a0 += v0; q0 = fmaf(v0,v0,q0);
        a1 += v1; q1 = fmaf(v1,v1,q1);
        a2 += v2; q2 = fmaf(v2,v2,q2);
        a3 += v3; q3 = fmaf(v3,v3,q3);
    }
    (void)rows;
    g_feat_c[blockIdx.x*256 + c]       = (a0+a1) + (a2+a3);
    g_feat_c[blockIdx.x*256 + 128 + c] = (q0+q1) + (q2+q3);
}

// final act stats combine (double, fixed order)
__global__ void bn_stats_act(float* msc)
{
    int c = threadIdx.x;
    double s = 0.0, s2 = 0.0;
    if (c < 128) {
        for (int r = 0; r < 64; r++) {
            s  += (double)g_geo_c[r*256 + c];
            s2 += (double)g_geo_c[r*256 + 128 + c];
        }
    } else {
        int cc = c - 128;
        for (int r = 0; r < 128; r++) {
            s  += (double)g_feat_c[r*256 + cc];
            s2 += (double)g_feat_c[r*256 + 128 + cc];
        }
    }
    double mean = s / (double)RTOT;
    double var  = s2 / (double)RTOT - mean*mean;
    msc[c]      = (float)mean;
    msc[CO + c] = (float)(1.0 / sqrt(var + (double)EPSB));
}

// =====================================================================
// gather feat_in -> bf16 split
// =====================================================================
__global__ void gather_feat()
{
    uint32_t tid = blockIdx.x*256u + threadIdx.x;
    uint32_t r = tid >> 5;
    uint32_t c4 = (tid & 31u) * 4u;
    uint32_t m = r / KNB;
    uint32_t b = m >> 11;
    float4 v;
    if (c4 < 64u) {
        uint32_t nb = (uint32_t)g_idx[r];
        v = *(const float4*)(g_ft + (size_t)((b << 11) + nb)*CIN + c4);
    } else {
        v = *(const float4*)(g_ft + (size_t)m*CIN + (c4 - 64u));
    }
    __nv_bfloat16 h0 = __float2bfloat16(v.x);
    __nv_bfloat16 h1 = __float2bfloat16(v.y);
    __nv_bfloat16 h2 = __float2bfloat16(v.z);
    __nv_bfloat16 h3 = __float2bfloat16(v.w);
    size_t o = (size_t)r*128 + c4;
    *(uint2*)(g_ginh + o) = make_uint2(bpackh(h0,h1), bpackh(h2,h3));
    *(uint2*)(g_ginl + o) = make_uint2(
        bpackh(__float2bfloat16(v.x - __bfloat162float(h0)),
               __float2bfloat16(v.y - __bfloat162float(h1))),
        bpackh(__float2bfloat16(v.z - __bfloat162float(h2)),
               __float2bfloat16(v.w - __bfloat162float(h3))));
}

// =====================================================================
// tensor GEMM wrappers
// =====================================================================
__global__ void __launch_bounds__(256, 1)
tgemm(const __nv_bfloat16* __restrict__ Ah, const __nv_bfloat16* __restrict__ Al,
      const __nv_bfloat16* __restrict__ Bh, const __nv_bfloat16* __restrict__ Bl,
      float* __restrict__ C, int lda, int ldb, int ldc, int nkc)
{
#if HAS_TC
    extern __shared__ char sm[];
    uint32_t raw = smem_u32(sm);
    uint32_t base = (raw + 1023) & ~1023u;
    tgemm_core(sm + (base - raw), base, Ah, Al, Bh, Bl, C, lda, ldb, ldc, nkc,
               blockIdx.y*128, blockIdx.x*128);
#else
    tgemm_core_simt(Ah, Al, Bh, Bl, C, lda, ldb, ldc, nkc, blockIdx.y*128, blockIdx.x*128);
#endif
}

__global__ void __launch_bounds__(256, 1)
qkv_gemm()
{
    int z = blockIdx.z;
    const __nv_bfloat16* Bh = (z==0) ? g_wqh : (z==1) ? g_wkh : g_wvh;
    const __nv_bfloat16* Bl = (z==0) ? g_wql : (z==1) ? g_wkl : g_wvl;
    float* C = (z==0) ? g_q : (z==1) ? g_k : g_v;
#if HAS_TC
    extern __shared__ char sm[];
    uint32_t raw = smem_u32(sm);
    uint32_t base = (raw + 1023) & ~1023u;
    tgemm_core(sm + (base - raw), base, g_xh, g_xl, Bh, Bl, C, CO, CO, CO, 4,
               blockIdx.y*128, blockIdx.x*128);
#else
    tgemm_core_simt(g_xh, g_xl, Bh, Bl, C, CO, CO, CO, 4, blockIdx.y*128, blockIdx.x*128);
#endif
}

// =====================================================================
// BN stats (fp32 partials, double combine) — small tensors
// =====================================================================
__device__ __forceinline__ void bn_partial_region(const float* X, long rows,
                                                  int nblk, int blk, int region)
{
    int c = threadIdx.x;
    long per = (rows + nblk - 1) / nblk;
    long r0 = (long)blk * per;
    long r1 = r0 + per; if (r1 > rows) r1 = rows;
    float a0=0,a1=0,a2=0,a3=0, q0=0,q1=0,q2=0,q3=0;
    long r = r0;
    for (; r + 4 <= r1; r += 4) {
        float v0 = X[(r+0)*CO + c], v1 = X[(r+1)*CO + c];
        float v2 = X[(r+2)*CO + c], v3 = X[(r+3)*CO + c];
        a0 += v0; q0 = fmaf(v0,v0,q0);
        a1 += v1; q1 = fmaf(v1,v1,q1);
        a2 += v2; q2 = fmaf(v2,v2,q2);
        a3 += v3; q3 = fmaf(v3,v3,q3);
    }
    for (; r < r1; r++) { float v = X[r*CO + c]; a0 += v; q0 = fmaf(v,v,q0); }
    g_partf[((size_t)region*2 + 0)*CO + c] = (a0+a1) + (a2+a3);
    g_partf[((size_t)region*2 + 1)*CO + c] = (q0+q1) + (q2+q3);
}

__global__ void bn_stats_partial(const float* __restrict__ X, long rows)
{
    bn_partial_region(X, rows, gridDim.x, blockIdx.x, blockIdx.x);
}

__global__ void bn_stats_final(int nblocks, long rows, float* msc)
{
    int c = threadIdx.x;
    double s = 0.0, s2 = 0.0;
    for (int i = 0; i < nblocks; i++) {
        s  += (double)g_partf[((size_t)i*2 + 0)*CO + c];
        s2 += (double)g_partf[((size_t)i*2 + 1)*CO + c];
    }
    double mean = s / (double)rows;
    double var  = s2 / (double)rows - mean*mean;
    msc[c]      = (float)mean;
    msc[CO + c] = (float)(1.0 / sqrt(var + (double)EPSB));
}

__global__ void bn_stats_qkv()
{
    const float* X = (blockIdx.y==0) ? g_q : (blockIdx.y==1) ? g_k : g_v;
    bn_partial_region(X, MTOT, 64, blockIdx.x, blockIdx.y*64 + blockIdx.x);
}
__global__ void bn_final_qkv(float* msc)
{
    int y = blockIdx.x;
    int c = threadIdx.x;
    double s = 0.0, s2 = 0.0;
    for (int i = y*64; i < y*64 + 64; i++) {
        s  += (double)g_partf[((size_t)i*2 + 0)*CO + c];
        s2 += (double)g_partf[((size_t)i*2 + 1)*CO + c];
    }
    double mean = s / (double)MTOT;
    double var  = s2 / (double)MTOT - mean*mean;
    msc[(2+y)*512 + c]      = (float)mean;
    msc[(2+y)*512 + CO + c] = (float)(1.0 / sqrt(var + (double)EPSB));
}

// =====================================================================
// branch BN + relu + maxpool
// =====================================================================
__global__ void branch_apply(const float* msc,
                             const float* __restrict__ g_geo, const float* __restrict__ b_geo,
                             const float* __restrict__ g_fea, const float* __restrict__ b_fea)
{
    int m = blockIdx.x;
    int c = threadIdx.x;
    float mean = msc[c], istd = msc[CO + c];
    float ga = (c < 128) ? g_geo[c] : g_fea[c - 128];
    float be = (c < 128) ? b_geo[c] : b_fea[c - 128];
    float sc = istd * ga;
    float best = -FLT_MAX;
    const float* base = g_act + (size_t)m*KNB*CO + c;
#pragma unroll 3
    for (int k = 0; k < KNB; k++) {
        float zv = base[(size_t)k*CO];
        float y = (zv - mean) * sc + be;
        y = fmaxf(y, 0.0f);
        best = fmaxf(best, y);
    }
    g_featv[(size_t)m*CO + c] = best;
}

// =====================================================================
// BN apply variants
// =====================================================================
__global__ void bn_apply(const float* __restrict__ in, float* __restrict__ out,
                         const float* msc,
                         const float* __restrict__ gamma, const float* __restrict__ beta,
                         const float* __restrict__ res, int do_relu)
{
    size_t i = (size_t)blockIdx.x * blockDim.x + threadIdx.x;
    int c = (int)(i & (CO-1));
    float y = (in[i] - msc[c]) * msc[CO + c] * gamma[c] + beta[c];
    if (do_relu) y = fmaxf(y, 0.0f);
    if (res) y += res[i];
    out[i] = y;
}

__global__ void bn_apply_split(const float* __restrict__ in,
                               const float* msc,
                               const float* __restrict__ gamma, const float* __restrict__ beta,
                               int do_relu,
                               __nv_bfloat16* __restrict__ oh, __nv_bfloat16* __restrict__ ol)
{
    size_t i = (size_t)blockIdx.x * blockDim.x + threadIdx.x;
    int c = (int)(i & (CO-1));
    float y = (in[i] - msc[c]) * msc[CO + c] * gamma[c] + beta[c];
    if (do_relu) y = fmaxf(y, 0.0f);
    __nv_bfloat16 hb = __float2bfloat16(y);
    oh[i] = hb;
    ol[i] = __float2bfloat16(y - __bfloat162float(hb));
}

__global__ void bn_apply_qkv(const float* msc,
                             const float* __restrict__ gq, const float* __restrict__ bq,
                             const float* __restrict__ gk, const float* __restrict__ bk,
                             const float* __restrict__ gv, const float* __restrict__ bv)
{
    int y = blockIdx.y;
    size_t i = (size_t)blockIdx.x * 256 + threadIdx.x;
    int c = (int)(i & (CO-1));
    const float* in = (y==0) ? g_q : (y==1) ? g_k : g_v;
    const float* ga = (y==0) ? gq : (y==1) ? gk : gv;
    const float* be = (y==0) ? bq : (y==1) ? bk : bv;
    const float* ms = msc + (2+y)*512;
    float v = fmaxf((in[i] - ms[c]) * ms[CO + c] * ga[c] + be[c], 0.0f);
    if (y == 2) { g_v[i] = v; return; }
    __nv_bfloat16 hb = __float2bfloat16(v);
    __nv_bfloat16 lb = __float2bfloat16(v - __bfloat162float(hb));
    if (y == 0) { g_qh[i] = hb; g_ql[i] = lb; }
    else        { g_kh[i] = hb; g_kl[i] = lb; }
}

// =====================================================================
// fused weight splits
// =====================================================================
__global__ void split_weights(const float* __restrict__ Wf, const float* __restrict__ Wq,
                              const float* __restrict__ Wk, const float* __restrict__ Wv,
                              const float* __restrict__ Wfus, const float* __restrict__ Wm)
{
    int i = blockIdx.x*256 + threadIdx.x;
    const float* src; __nv_bfloat16 *dh, *dl; int off;
    if      (i < 16384)  { src = Wf;   dh = g_wfh;   dl = g_wfl;   off = i; }
    else if (i < 81920)  { src = Wq;   dh = g_wqh;   dl = g_wql;   off = i - 16384; }
    else if (i < 147456) { src = Wk;   dh = g_wkh;   dl = g_wkl;   off = i - 81920; }
    else if (i < 212992) { src = Wv;   dh = g_wvh;   dl = g_wvl;   off = i - 147456; }
    else if (i < 327680) { src = Wfus; dh = g_wfush; dl = g_wfusl; off = i - 212992; }
    else                 { src = Wm;   dh = g_wmh;   dl = g_wml;   off = i - 327680; }
    float v = src[off];
    __nv_bfloat16 hb = __float2bfloat16(v);
    dh[off] = hb;
    dl[off] = __float2bfloat16(v - __bfloat162float(hb));
}

// =====================================================================
// v -> per-head transposed bf16 split
// =====================================================================
__global__ void vt_convert()
{
    __shared__ float tile[32][33];
    int z  = blockIdx.z;
    int b  = z / HEADS, h = z - b*HEADS;
    int m0 = blockIdx.x * 32;
    int c0 = blockIdx.y * 32;
    int tx = threadIdx.x, ty = threadIdx.y;
#pragma unroll
    for (int i = 0; i < 32; i += 8)
        tile[ty+i][tx] = g_v[((size_t)(b*NN) + m0 + ty + i)*CO + h*32 + c0 + tx];
    __syncthreads();
#pragma unroll
    for (int i = 0; i < 32; i += 8) {
        int c = c0 + ty + i, m = m0 + tx;
        float v = tile[tx][ty+i];
        __nv_bfloat16 hb = __float2bfloat16(v);
        size_t o = (size_t)z*WCH*NN + (size_t)c*NN + m;
        g_vth[o] = hb;
        g_vtl[o] = __float2bfloat16(v - __bfloat162float(hb));
    }
}

// =====================================================================
// FLASH pass 1 (R8 baseline, no prefetch): per-row softmax stats
// grid (16 m-tiles, 28 z), 256 threads.
// =====================================================================
#define ST_SMEM (1024 + 65536 + 64 + 1088)

__global__ void __launch_bounds__(256, 1)
attn_stats()
{
#if HAS_TC
    extern __shared__ char sm[];
    uint32_t raw = smem_u32(sm);
    uint32_t base = (raw + 1023) & ~1023u;
    char* sb = sm + (base - raw);
    uint32_t ctrl = base + 65536;
    uint32_t mbar = ctrl + 8;
    float* mrg = (float*)(sb + 65536 + 64);   // 128 x {mx,sum}

    int t = threadIdx.x;
    int z = blockIdx.y;
    int b = z / HEADS, h = z - b*HEADS;
    int m0 = blockIdx.x * 128;

    if (t == 0) MBARRIER_INIT(mbar, 1);
    if (t < 32) { TCGEN05_ALLOC(ctrl, 128); TCGEN05_RELINQ(); }
    __syncthreads();
    uint32_t tmem;
    asm volatile("ld.shared.b32 %0, [%1];" : "=r"(tmem) : "r"(ctrl));

    const __nv_bfloat16* pQh = g_qh + ((size_t)(b*NN) + m0)*CO + h*32;
    const __nv_bfloat16* pQl = g_ql + ((size_t)(b*NN) + m0)*CO + h*32;
    const __nv_bfloat16* pKh = g_kh + ((size_t)b*NN)*CO + h*32;
    const __nv_bfloat16* pKl = g_kl + ((size_t)b*NN)*CO + h*32;

    int rb = t >> 4, kq = t & 15;
#pragma unroll
    for (int i = 0; i < 8; i++) {
        int r = rb + i*16;
        uint32_t so = swz((uint32_t)(r*128 + kq*8));
        *(uint2*)(sb + 0*16384 + so) = *(const uint2*)(pQh + (size_t)r*CO + kq*4);
        *(uint2*)(sb + 1*16384 + so) = *(const uint2*)(pQl + (size_t)r*CO + kq*4);
    }

    uint64_t dQh = make_desc(base + 0*16384);
    uint64_t dQl = make_desc(base + 1*16384);
    uint64_t dKh = make_desc(base + 2*16384);
    uint64_t dKl = make_desc(base + 3*16384);

    int w = t >> 5, lane = t & 31;
    int sub = w & 3, half = w >> 2;
    int rrow = sub*32 + lane;

    float mx = -FLT_MAX, sum = 0.0f;

    for (int nc = 0; nc < 16; nc++) {
        int n0 = nc*128;
#pragma unroll
        for (int i = 0; i < 8; i++) {
            int r = rb + i*16;
            uint32_t so = swz((uint32_t)(r*128 + kq*8));
            *(uint2*)(sb + 2*16384 + so) = *(const uint2*)(pKh + (size_t)(n0+r)*CO + kq*4);
            *(uint2*)(sb + 3*16384 + so) = *(const uint2*)(pKl + (size_t)(n0+r)*CO + kq*4);
        }
        __syncthreads();
        if (t < 32) {
            if (elect_one_pred()) {
                FENCE_ASYNC_SHARED();
#pragma unroll
                for (int ks = 0; ks < 4; ks++) {
                    uint64_t o = ks*2;
                    mma_f16_ss(tmem, dQh+o, dKh+o, IDESC_N128, (ks > 0) ? 1u : 0u);
                    mma_f16_ss(tmem, dQh+o, dKl+o, IDESC_N128, 1u);
                    mma_f16_ss(tmem, dQl+o, dKh+o, IDESC_N128, 1u);
                }
                TCGEN05_COMMIT(mbar);
            }
        }
        MBARRIER_WAIT_PARITY(mbar, nc & 1);
        TCGEN05_FENCE_AFTER();
#pragma unroll
        for (int gi = 0; gi < 2; gi++) {
            int g = half*2 + gi;
            uint32_t r[32];
            TCGEN05_LD_X32(r, tmem + g*32);
            TCGEN05_WAIT_LD();
            float gm = -FLT_MAX;
#pragma unroll
            for (int j = 0; j < 32; j++) gm = fmaxf(gm, __uint_as_float(r[j]));
            float gs = 0.0f;
#pragma unroll
            for (int j = 0; j < 32; j++) gs += __expf(__uint_as_float(r[j]) - gm);
            if (gm <= mx) sum += gs * __expf(gm - mx);
            else { sum = sum * __expf(mx - gm) + gs; mx = gm; }
        }
        __syncthreads();   // all LDTMs done before next MMA overwrites S
    }

    if (half == 0) { mrg[rrow*2] = mx; mrg[rrow*2+1] = sum; }
    __syncthreads();
    if (half == 1) {
        float m2 = mrg[rrow*2], s2 = mrg[rrow*2+1];
        float M = fmaxf(mx, m2);
        float S = s2 * __expf(m2 - M) + sum * __expf(mx - M);
        size_t row = (size_t)z*NN + m0 + rrow;
        g_rowstat[row*2]   = M;
        g_rowstat[row*2+1] = 1.0f / S;
    }
    __syncthreads();
    if (t < 32) TCGEN05_DEALLOC(tmem, 128);
#else
    int t = threadIdx.x;
    int z = blockIdx.y;
    int b = z / HEADS, h = z - b*HEADS;
    int m0 = blockIdx.x * 128;
    if (t >= 128) return;
    int m = m0 + t;
    const float* qp = g_q + ((size_t)(b*NN) + m)*CO + h*32;
    float mx = -FLT_MAX;
    for (int n = 0; n < NN; n++) {
        const float* kp = g_k + ((size_t)(b*NN) + n)*CO + h*32;
        float acc = 0.0f;
        for (int k = 0; k < 64; k++) acc = fmaf(qp[k], kp[k], acc);
        mx = fmaxf(mx, acc);
    }
    float sum = 0.0f;
    for (int n = 0; n < NN; n++) {
        const float* kp = g_k + ((size_t)(b*NN) + n)*CO + h*32;
        float acc = 0.0f;
        for (int k = 0; k < 64; k++) acc = fmaf(qp[k], kp[k], acc);
        sum += __expf(acc - mx);
    }
    size_t row = (size_t)z*NN + m;
    g_rowstat[row*2] = mx; g_rowstat[row*2+1] = 1.0f / sum;
#endif
}

// =====================================================================
// FLASH pass 2 (R8 baseline, no prefetch): recompute S, softmax, P·V
// grid (16 m-tiles, 28 z), 256 threads.
// TMEM: S cols 0..127, O cols 128..191 (alloc 256)
// =====================================================================
#define FL_SMEM (1024 + 163840 + 64 + 1088)

__global__ void __launch_bounds__(256, 1)
attn_flash()
{
#if HAS_TC
    extern __shared__ char sm[];
    uint32_t raw = smem_u32(sm);
    uint32_t base = (raw + 1023) & ~1023u;
    char* sb = sm + (base - raw);
    const uint32_t off_Qh = 0, off_Ql = 16384, off_Kh = 32768, off_Kl = 49152;
    const uint32_t off_Vh = 65536, off_Vl = 81920, off_Ph = 98304, off_Pl = 131072;
    uint32_t ctrl = base + 163840;
    uint32_t mbar_s = ctrl + 8;
    uint32_t mbar_o = ctrl + 16;
    float* sst = (float*)(sb + 163840 + 64);

    int t = threadIdx.x;
    int z = blockIdx.y;
    int b = z / HEADS, h = z - b*HEADS;
    int m0 = blockIdx.x * 128;

    if (t == 0) { MBARRIER_INIT(mbar_s, 1); MBARRIER_INIT(mbar_o, 1); }
    if (t < 32) { TCGEN05_ALLOC(ctrl, 256); TCGEN05_RELINQ(); }
    sst[t] = g_rowstat[(size_t)(z*NN + m0)*2 + t];
    __syncthreads();
    uint32_t tmem;
    asm volatile("ld.shared.b32 %0, [%1];" : "=r"(tmem) : "r"(ctrl));
    uint32_t tmemO = tmem + 128;

    const __nv_bfloat16* pQh = g_qh + ((size_t)(b*NN) + m0)*CO + h*32;
    const __nv_bfloat16* pQl = g_ql + ((size_t)(b*NN) + m0)*CO + h*32;
    const __nv_bfloat16* pKh = g_kh + ((size_t)b*NN)*CO + h*32;
    const __nv_bfloat16* pKl = g_kl + ((size_t)b*NN)*CO + h*32;
    const __nv_bfloat16* Vh = g_vth + (size_t)z*WCH*NN;
    const __nv_bfloat16* Vl = g_vtl + (size_t)z*WCH*NN;

    int rb = t >> 4, kq = t & 15;
#pragma unroll
    for (int i = 0; i < 8; i++) {
        int r = rb + i*16;
        uint32_t so = swz((uint32_t)(r*128 + kq*8));
        *(uint2*)(sb + off_Qh + so) = *(const uint2*)(pQh + (size_t)r*CO + kq*4);
        *(uint2*)(sb + off_Ql + so) = *(const uint2*)(pQl + (size_t)r*CO + kq*4);
    }

    uint64_t dQh = make_desc(base + off_Qh);
    uint64_t dQl = make_desc(base + off_Ql);
    uint64_t dKh = make_desc(base + off_Kh);
    uint64_t dKl = make_desc(base + off_Kl);

    int w = t >> 5, lane = t & 31;
    int sub = w & 3, half = w >> 2;
    int rrow = sub*32 + lane;
    float mxr = sst[rrow*2], invr = sst[rrow*2+1];

    for (int nc = 0; nc < 16; nc++) {
        int n0 = nc*128;
        if (nc > 0) MBARRIER_WAIT_PARITY(mbar_o, (nc-1) & 1);

#pragma unroll
        for (int i = 0; i < 8; i++) {
            int r = rb + i*16;
            uint32_t so = swz((uint32_t)(r*128 + kq*8));
            *(uint2*)(sb + off_Kh + so) = *(const uint2*)(pKh + (size_t)(n0+r)*CO + kq*4);
            *(uint2*)(sb + off_Kl + so) = *(const uint2*)(pKl + (size_t)(n0+r)*CO + kq*4);
        }
#pragma unroll
        for (int i = 0; i < 4; i++) {
            int r = rb + i*16;
            uint32_t so = swz((uint32_t)(r*128 + kq*8));
#pragma unroll
            for (int j = 0; j < 2; j++) {
                size_t gk = (size_t)r*NN + n0 + j*64 + kq*4;
                *(uint2*)(sb + off_Vh + j*8192 + so) = *(const uint2*)(Vh + gk);
                *(uint2*)(sb + off_Vl + j*8192 + so) = *(const uint2*)(Vl + gk);
            }
        }
        __syncthreads();

        // S = Q K^T (fresh accumulator each chunk)
        if (t < 32) {
            if (elect_one_pred()) {
                FENCE_ASYNC_SHARED();
#pragma unroll
                for (int ks = 0; ks < 4; ks++) {
                    uint64_t o = ks*2;
                    mma_f16_ss(tmem, dQh+o, dKh+o, IDESC_N128, (ks > 0) ? 1u : 0u);
                    mma_f16_ss(tmem, dQh+o, dKl+o, IDESC_N128, 1u);
                    mma_f16_ss(tmem, dQl+o, dKh+o, IDESC_N128, 1u);
                }
                TCGEN05_COMMIT(mbar_s);
            }
        }
        MBARRIER_WAIT_PARITY(mbar_s, nc & 1);
        TCGEN05_FENCE_AFTER();

#pragma unroll
        for (int gi = 0; gi < 2; gi++) {
            int g = half*2 + gi;
            uint32_t r[32];
            TCGEN05_LD_X32(r, tmem + g*32);
            TCGEN05_WAIT_LD();
#pragma unroll
            for (int j = 0; j < 8; j++) {
                float v0 = __expf(__uint_as_float(r[j*4+0]) - mxr) * invr;
                float v1 = __expf(__uint_as_float(r[j*4+1]) - mxr) * invr;
                float v2 = __expf(__uint_as_float(r[j*4+2]) - mxr) * invr;
                float v3 = __expf(__uint_as_float(r[j*4+3]) - mxr) * invr;
                __nv_bfloat16 h0 = __float2bfloat16(v0);
                __nv_bfloat16 h1 = __float2bfloat16(v1);
                __nv_bfloat16 h2 = __float2bfloat16(v2);
                __nv_bfloat16 h3 = __float2bfloat16(v3);
                uint32_t so = swz((uint32_t)(rrow*128 + (gi*32 + j*4)*2));
                *(uint2*)(sb + off_Ph + half*16384 + so) = make_uint2(bpackh(h0,h1), bpackh(h2,h3));
                *(uint2*)(sb + off_Pl + half*16384 + so) = make_uint2(
                    bpackh(__float2bfloat16(v0 - __bfloat162float(h0)),
                           __float2bfloat16(v1 - __bfloat162float(h1))),
                    bpackh(__float2bfloat16(v2 - __bfloat162float(h2)),
                           __float2bfloat16(v3 - __bfloat162float(h3))));
            }
        }
        __syncthreads();

        // O += P V^T
        if (t < 32) {
            if (elect_one_pred()) {
                FENCE_ASYNC_SHARED();
#pragma unroll
                for (int kch = 0; kch < 2; kch++) {
                    uint64_t dPh = make_desc(base + off_Ph + kch*16384);
                    uint64_t dPl = make_desc(base + off_Pl + kch*16384);
                    uint64_t dVh2 = make_desc(base + off_Vh + kch*8192);
                    uint64_t dVl2 = make_desc(base + off_Vl + kch*8192);
#pragma unroll
                    for (int ks = 0; ks < 4; ks++) {
                        uint64_t o = ks*2;
                        mma_f16_ss(tmemO, dPh+o, dVh2+o, IDESC_N64,
                                   (nc > 0 || kch > 0 || ks > 0) ? 1u : 0u);
                        mma_f16_ss(tmemO, dPh+o, dVl2+o, IDESC_N64, 1u);
                        mma_f16_ss(tmemO, dPl+o, dVh2+o, IDESC_N64, 1u);
                    }
                }
                TCGEN05_COMMIT(mbar_o);
            }
        }
    }
    MBARRIER_WAIT_PARITY(mbar_o, 1);
    TCGEN05_FENCE_AFTER();

    size_t rbase = (size_t)(b*NN + m0 + rrow)*FUSC + h*64 + half*32;
    {
        uint32_t r[32];
        TCGEN05_LD_X32(r, tmemO + half*32);
        TCGEN05_WAIT_LD();
        TCGEN05_FENCE_BEFORE();
#pragma unroll
        for (int j = 0; j < 8; j++) {
            float v0 = __uint_as_float(r[j*4+0]);
            float v1 = __uint_as_float(r[j*4+1]);
            float v2 = __uint_as_float(r[j*4+2]);
            float v3 = __uint_as_float(r[j*4+3]);
            __nv_bfloat16 h0 = __float2bfloat16(v0);
            __nv_bfloat16 h1 = __float2bfloat16(v1);
            __nv_bfloat16 h2 = __float2bfloat16(v2);
            __nv_bfloat16 h3 = __float2bfloat16(v3);
            *(uint2*)(g_Oh + rbase + j*4) = make_uint2(bpackh(h0,h1), bpackh(h2,h3));
            *(uint2*)(g_Ol + rbase + j*4) = make_uint2(
                bpackh(__float2bfloat16(v0 - __bfloat162float(h0)),
                       __float2bfloat16(v1 - __bfloat162float(h1))),
                bpackh(__float2bfloat16(v2 - __bfloat162float(h2)),
                       __float2bfloat16(v3 - __bfloat162float(h3))));
        }
    }
    __syncthreads();
    if (t < 32) TCGEN05_DEALLOC(tmem, 256);
#else
    int t = threadIdx.x;
    int z = blockIdx.y;
    int b = z / HEADS, h = z - b*HEADS;
    int m0 = blockIdx.x * 128;
    if (t >= 128) return;
    int m = m0 + t;
    const float* qp = g_q + ((size_t)(b*NN) + m)*CO + h*32;
    float mxr = g_rowstat[(size_t)(z*NN + m)*2], invr = g_rowstat[(size_t)(z*NN + m)*2+1];
    for (int c = 0; c < 64; c++) {
        float acc = 0.0f;
        for (int n = 0; n < NN; n++) {
            const float* kp = g_k + ((size_t)(b*NN) + n)*CO + h*32;
            float s = 0.0f;
            for (int k = 0; k < 64; k++) s = fmaf(qp[k], kp[k], s);
            acc = fmaf(__expf(s - mxr)*invr, g_v[((size_t)(b*NN) + n)*CO + h*32 + c], acc);
        }
        size_t o = (size_t)(b*NN + m)*FUSC + h*64 + c;
        __nv_bfloat16 hb = __float2bfloat16(acc);
        g_Oh[o] = hb;
        g_Ol[o] = __float2bfloat16(acc - __bfloat162float(hb));
    }
#endif
}

// =====================================================================
// LayerNorm -> bf16 split
// =====================================================================
__global__ void layernorm_kernel(const float* __restrict__ X,
                                 const float* __restrict__ g, const float* __restrict__ b)
{
    int m = blockIdx.x, c = threadIdx.x;
    __shared__ float red[256];
    float v = X[(size_t)m*CO + c];
    red[c] = v; __syncthreads();
    for (int s = 128; s; s >>= 1) { if (c < s) red[c] += red[c+s]; __syncthreads(); }
    float mean = red[0] * (1.0f/CO); __syncthreads();
    float d = v - mean;
    red[c] = d*d; __syncthreads();
    for (int s = 128; s; s >>= 1) { if (c < s) red[c] += red[c+s]; __syncthreads(); }
    float var = red[0] * (1.0f/CO);
    float y = d * rsqrtf(var + EPSB) * g[c] + b[c];
    __nv_bfloat16 hb = __float2bfloat16(y);
    size_t i = (size_t)m*CO + c;
    g_yh[i] = hb;
    g_yl[i] = __float2bfloat16(y - __bfloat162float(hb));
}

// =====================================================================
// final output (transposed)
// =====================================================================
__global__ void final_out(const float* __restrict__ bias, float* __restrict__ out)
{
    __shared__ float tile[32][33];
    int b  = blockIdx.z;
    int n0 = blockIdx.x * 32;
    int c0 = blockIdx.y * 32;
    int tx = threadIdx.x, ty = threadIdx.y;
#pragma unroll
    for (int i = 0; i < 32; i += 8) {
        int n = n0 + ty + i, c = c0 + tx;
        size_t src = ((size_t)b*NN + n)*CO + c;
        tile[ty+i][tx] = g_f2[src] + g_fp[src] + bias[c];
    }
    __syncthreads();
#pragma unroll
    for (int i = 0; i < 32; i += 8) {
        int c = c0 + ty + i, n = n0 + tx;
        out[((size_t)b*CO + c)*NN + n] = tile[tx][ty+i];
    }
}

// =====================================================================
// host
// =====================================================================
extern "C" void kernel_launch(void* const* d_in, const int* in_sizes, int n_in,
                              void* d_out, int out_size)
{
    const float* xyz    = (const float*)d_in[0];
    const float* f      = (const float*)d_in[1];
    const float* W_geo  = (const float*)d_in[2];
    const float* gg     = (const float*)d_in[3];
    const float* bg     = (const float*)d_in[4];
    const float* W_feat = (const float*)d_in[5];
    const float* gf     = (const float*)d_in[6];
    const float* bf     = (const float*)d_in[7];
    const float* g_bn   = (const float*)d_in[8];
    const float* b_bn   = (const float*)d_in[9];
    const float* W_q    = (const float*)d_in[10];
    const float* gq     = (const float*)d_in[11];
    const float* bq     = (const float*)d_in[12];
    const float* W_k    = (const float*)d_in[13];
    const float* gk     = (const float*)d_in[14];
    const float* bk     = (const float*)d_in[15];
    const float* W_v    = (const float*)d_in[16];
    const float* gv     = (const float*)d_in[17];
    const float* bv     = (const float*)d_in[18];
    const float* W_fus  = (const float*)d_in[19];
    /* d_in[20] bias_fus: cancels inside BN */
    const float* gfu    = (const float*)d_in[21];
    const float* bfu    = (const float*)d_in[22];
    const float* g_ln   = (const float*)d_in[23];
    const float* b_ln   = (const float*)d_in[24];
    const float* W_mlp  = (const float*)d_in[25];
    const float* b_mlp  = (const float*)d_in[26];
    float* out = (float*)d_out;

    float *p_featv, *p_fp, *p_f2, *p_msc, *p_act;
    __nv_bfloat16 *p_yh, *p_yl, *p_Oh, *p_Ol, *p_xh, *p_xl;
    __nv_bfloat16 *p_ginh, *p_ginl, *p_wfh, *p_wfl;
    __nv_bfloat16 *p_wfush, *p_wfusl, *p_wmh, *p_wml;
    cudaGetSymbolAddress((void**)&p_act,   g_act);
    cudaGetSymbolAddress((void**)&p_featv, g_featv);
    cudaGetSymbolAddress((void**)&p_fp,    g_fp);
    cudaGetSymbolAddress((void**)&p_f2,    g_f2);
    cudaGetSymbolAddress((void**)&p_msc,   g_msc);
    cudaGetSymbolAddress((void**)&p_xh,    g_xh);
    cudaGetSymbolAddress((void**)&p_xl,    g_xl);
    cudaGetSymbolAddress((void**)&p_yh,    g_yh);
    cudaGetSymbolAddress((void**)&p_yl,    g_yl);
    cudaGetSymbolAddress((void**)&p_Oh,    g_Oh);
    cudaGetSymbolAddress((void**)&p_Ol,    g_Ol);
    cudaGetSymbolAddress((void**)&p_ginh,  g_ginh);
    cudaGetSymbolAddress((void**)&p_ginl,  g_ginl);
    cudaGetSymbolAddress((void**)&p_wfh,   g_wfh);
    cudaGetSymbolAddress((void**)&p_wfl,   g_wfl);
    cudaGetSymbolAddress((void**)&p_wfush, g_wfush);
    cudaGetSymbolAddress((void**)&p_wfusl, g_wfusl);
    cudaGetSymbolAddress((void**)&p_wmh,   g_wmh);
    cudaGetSymbolAddress((void**)&p_wml,   g_wml);

    cudaFuncSetAttribute(attn_stats, cudaFuncAttributeMaxDynamicSharedMemorySize, ST_SMEM);
    cudaFuncSetAttribute(attn_flash, cudaFuncAttributeMaxDynamicSharedMemorySize, FL_SMEM);
    cudaFuncSetAttribute(tgemm,      cudaFuncAttributeMaxDynamicSharedMemorySize, TG_SMEM);
    cudaFuncSetAttribute(qkv_gemm,   cudaFuncAttributeMaxDynamicSharedMemorySize, TG_SMEM);

    // ---- 0. weight splits
    split_weights<<<1536, 256>>>(W_feat, W_q, W_k, W_v, W_fus, W_mlp);

    // ---- 1. KNN + transpose + geo (fused stats) + gather
    knn_kernel<<<MTOT, 256>>>(xyz);
    transpose_f<<<dim3(NN/32, CIN/32, BB), dim3(32,8)>>>(f);
    geo_pre<<<NGEOREG, 128>>>(xyz, W_geo);
    gather_feat<<<RTOT*32/256, 256>>>();

    // ---- 2. feat GEMM
    tgemm<<<dim3(1, RTOT/128), 256, TG_SMEM>>>(p_ginh, p_ginl, p_wfh, p_wfl,
                                               p_act + 128, 128, 128, CO, 2);

    // ---- 3. act stats (geo from fused partials; feat half-read) + apply
    geo_combine<<<64, 128>>>();
    feat_stats_partial<<<128, 128>>>();
    bn_stats_act<<<1, 256>>>(p_msc + 0*512);
    branch_apply<<<MTOT, 256>>>(p_msc + 0*512, gg, bg, gf, bf);

    // ---- 4. BatchNorm1d -> x split
    bn_stats_partial<<<32, 256>>>(p_featv, MTOT);
    bn_stats_final<<<1, 256>>>(32, MTOT, p_msc + 1*512);
    bn_apply_split<<<MTOT, 256>>>(p_featv, p_msc + 1*512, g_bn, b_bn, 0, p_xh, p_xl);

    // ---- 5. q/k/v merged GEMM + stats + apply
    qkv_gemm<<<dim3(2, MTOT/128, 3), 256, TG_SMEM>>>();
    bn_stats_qkv<<<dim3(64, 3), 256>>>();
    bn_final_qkv<<<3, 256>>>(p_msc);
    bn_apply_qkv<<<dim3(MTOT*CO/256, 3), 256>>>(p_msc, gq, bq, gk, bk, gv, bv);
    vt_convert<<<dim3(NN/32, 2, BB*HEADS), dim3(32,8)>>>();

    // ---- 6. flash attention (two kernels, no prefetch — measured best)
    attn_stats<<<dim3(16, BB*HEADS), 256, ST_SMEM>>>();
    attn_flash<<<dim3(16, BB*HEADS), 256, FL_SMEM>>>();

    // ---- 7. fus + residual
    tgemm<<<dim3(2, MTOT/128), 256, TG_SMEM>>>(p_Oh, p_Ol, p_wfush, p_wfusl,
                                               p_fp, FUSC, FUSC, CO, 7);
    bn_stats_partial<<<32, 256>>>(p_fp, MTOT);
    bn_stats_final<<<1, 256>>>(32, MTOT, p_msc + 5*512);
    bn_apply<<<MTOT, 256>>>(p_fp, p_f2, p_msc + 5*512, gfu, bfu, p_featv, 1);

    // ---- 8. layernorm + mlp + out
    layernorm_kernel<<<MTOT, 256>>>(p_f2, g_ln, b_ln);
    tgemm<<<dim3(2, MTOT/128), 256, TG_SMEM>>>(p_yh, p_yl, p_wmh, p_wml, p_fp, CO, CO, CO, 4);
    final_out<<<dim3(NN/32, CO/32, BB), dim3(32,8)>>>(b_mlp, out);

    (void)in_sizes; (void)n_in; (void)out_size;
}

// round 14
// speedup vs baseline: 1.5788x; 1.1604x over previous
#include <cuda_runtime.h>
#include <cuda_bf16.h>
#include <cfloat>
#include <math.h>
#include <cstdint>

#if defined(__CUDA_ARCH__) && defined(__CUDA_ARCH_FEAT_SM103_ALL)
#define HAS_TC 1
#else
#define HAS_TC 0
#endif

// ---------------- problem constants ----------------
#define BB    4
#define NN    2048
#define KNB   21
#define CIN   64
#define CO    256
#define HEADS 7
#define WCH   64
#define FUSC  (HEADS*WCH)          /* 448 */
#define MTOT  (BB*NN)              /* 8192 */
#define RTOT  (MTOT*KNB)           /* 172032 */
#define EPSB  1e-5f
#define NGEOREG  2048              /* geo stat regions (4 points each) */
#define NFEATCTA (RTOT/128)        /* 1344 */

// ---------------- scratch ----------------
__device__ int    g_idx[RTOT];
__device__ float  g_ft[MTOT*CIN];
__device__ float  g_actf[(size_t)RTOT*128];          // feat pre-BN only
__device__ float  g_zmx[MTOT*128];                   // geo pre-BN max over k
__device__ float  g_zmn[MTOT*128];                   // geo pre-BN min over k
__device__ float  g_featv[MTOT*CO];
__device__ float  g_q[MTOT*CO];
__device__ float  g_k[MTOT*CO];
__device__ float  g_v[MTOT*CO];
__device__ float  g_rowstat[BB*HEADS*NN*2];
__device__ float  g_fp[MTOT*CO];
__device__ float  g_f2[MTOT*CO];
__device__ float  g_partf[256*2*CO];
__device__ float  g_msc[6*2*CO];
__device__ float  g_geo_part[(size_t)NGEOREG*256];   // [region]{sum[128]|sq[128]}
__device__ float  g_feat_part[(size_t)NFEATCTA*256];
__device__ float  g_geo_c[64*256];
__device__ float  g_feat_c[64*256];
// bf16 hi/lo splits
__device__ __nv_bfloat16 g_ginh[(size_t)RTOT*128], g_ginl[(size_t)RTOT*128];
__device__ __nv_bfloat16 g_xh[MTOT*CO],  g_xl[MTOT*CO];
__device__ __nv_bfloat16 g_qh[MTOT*CO],  g_ql[MTOT*CO];
__device__ __nv_bfloat16 g_kh[MTOT*CO],  g_kl[MTOT*CO];
__device__ __nv_bfloat16 g_yh[MTOT*CO],  g_yl[MTOT*CO];
__device__ __nv_bfloat16 g_Oh[MTOT*FUSC], g_Ol[MTOT*FUSC];
__device__ __nv_bfloat16 g_vth[(size_t)BB*HEADS*WCH*NN], g_vtl[(size_t)BB*HEADS*WCH*NN];
__device__ __nv_bfloat16 g_wfh[128*128],  g_wfl[128*128];
__device__ __nv_bfloat16 g_wqh[CO*CO],    g_wql[CO*CO];
__device__ __nv_bfloat16 g_wkh[CO*CO],    g_wkl[CO*CO];
__device__ __nv_bfloat16 g_wvh[CO*CO],    g_wvl[CO*CO];
__device__ __nv_bfloat16 g_wfush[CO*FUSC],g_wfusl[CO*FUSC];
__device__ __nv_bfloat16 g_wmh[CO*CO],    g_wml[CO*CO];

// ---------------- helpers ----------------
__device__ __forceinline__ uint32_t smem_u32(const void* p) {
    uint32_t a;
    asm("{ .reg .u64 t; cvta.to.shared.u64 t, %1; cvt.u32.u64 %0, t; }" : "=r"(a) : "l"(p));
    return a;
}
__device__ __forceinline__ uint32_t swz(uint32_t o) { return o ^ ((o >> 3) & 0x70); }
__device__ __forceinline__ uint32_t bpackh(__nv_bfloat16 a, __nv_bfloat16 b) {
    __nv_bfloat162 t = __halves2bfloat162(a, b);
    return *reinterpret_cast<uint32_t*>(&t);
}

#if HAS_TC
__device__ __forceinline__ uint32_t elect_one_pred() {
    uint32_t pred;
    asm volatile("{\n\t.reg .pred p;\n\telect.sync _|p, 0xFFFFFFFF;\n\tselp.b32 %0, 1, 0, p;\n\t}" : "=r"(pred));
    return pred;
}

#define MBARRIER_INIT(addr, cnt) \
    asm volatile("mbarrier.init.shared.b64 [%0], %1;" :: "r"((uint32_t)(addr)), "r"((uint32_t)(cnt)) : "memory")

#define MBARRIER_WAIT_PARITY(mbar_smem_addr, phase_parity) do { \
    uint32_t _mbar = (uint32_t)(mbar_smem_addr); \
    uint32_t _parity = (uint32_t)(phase_parity); \
    uint32_t _done; \
    asm volatile("{\n\t.reg .pred p;\n\t" \
        "mbarrier.try_wait.parity.acquire.cta.shared::cta.b64 p, [%1], %2;\n\t" \
        "selp.b32 %0, 1, 0, p;\n\t}" : "=r"(_done) : "r"(_mbar), "r"(_parity) : "memory"); \
    if (!_done) { \
        asm volatile("{\n\t.reg .pred P1;\n\t" \
            "WAIT_LOOP_%=:\n\t" \
            "mbarrier.try_wait.parity.acquire.cta.shared::cta.b64 P1, [%0], %1, 0x989680;\n\t" \
            "@P1 bra.uni WAIT_DONE_%=;\n\t" \
            "bra.uni WAIT_LOOP_%=;\n\t" \
            "WAIT_DONE_%=:\n\t}" :: "r"(_mbar), "r"(_parity) : "memory"); \
    } \
} while(0)

#define TCGEN05_ALLOC(sm, n) \
    asm volatile("tcgen05.alloc.cta_group::1.sync.aligned.shared::cta.b32 [%0], %1;" \
                 :: "r"((uint32_t)(sm)), "r"((uint32_t)(n)) : "memory")
#define TCGEN05_RELINQ() \
    asm volatile("tcgen05.relinquish_alloc_permit.cta_group::1.sync.aligned;")
#define TCGEN05_DEALLOC(t, n) \
    asm volatile("tcgen05.dealloc.cta_group::1.sync.aligned.b32 %0, %1;" :: "r"(t), "r"(n))
#define TCGEN05_COMMIT(mbar) \
    asm volatile("tcgen05.commit.cta_group::1.mbarrier::arrive::one.shared::cluster.b64 [%0];" \
                 :: "r"((uint32_t)(mbar)) : "memory")
#define TCGEN05_FENCE_AFTER()  asm volatile("tcgen05.fence::after_thread_sync;" ::: "memory")
#define TCGEN05_FENCE_BEFORE() asm volatile("tcgen05.fence::before_thread_sync;" ::: "memory")
#define TCGEN05_WAIT_LD()      asm volatile("tcgen05.wait::ld.sync.aligned;" ::: "memory")
#define FENCE_ASYNC_SHARED()   asm volatile("fence.proxy.async.shared::cta;" ::: "memory")

#define TCGEN05_LD_X32(r, addr) \
    asm volatile("tcgen05.ld.sync.aligned.32x32b.x32.b32 " \
        "{%0, %1, %2, %3, %4, %5, %6, %7, %8, %9, %10, %11, %12, %13, %14, %15, " \
        " %16, %17, %18, %19, %20, %21, %22, %23, %24, %25, %26, %27, %28, %29, %30, %31}, [%32];" \
        : "=r"((r)[0]),  "=r"((r)[1]),  "=r"((r)[2]),  "=r"((r)[3]), \
          "=r"((r)[4]),  "=r"((r)[5]),  "=r"((r)[6]),  "=r"((r)[7]), \
          "=r"((r)[8]),  "=r"((r)[9]),  "=r"((r)[10]), "=r"((r)[11]), \
          "=r"((r)[12]), "=r"((r)[13]), "=r"((r)[14]), "=r"((r)[15]), \
          "=r"((r)[16]), "=r"((r)[17]), "=r"((r)[18]), "=r"((r)[19]), \
          "=r"((r)[20]), "=r"((r)[21]), "=r"((r)[22]), "=r"((r)[23]), \
          "=r"((r)[24]), "=r"((r)[25]), "=r"((r)[26]), "=r"((r)[27]), \
          "=r"((r)[28]), "=r"((r)[29]), "=r"((r)[30]), "=r"((r)[31]) \
        : "r"(addr))

static __device__ __forceinline__ uint64_t make_desc(uint32_t addr) {
    const uint64_t base =
        (uint64_t(2) << 61) | (uint64_t(1) << 46) | (uint64_t(64) << 32) | (uint64_t(1) << 16);
    return base | ((uint64_t)(addr >> 4) & 0x3FFF);
}

__device__ __forceinline__ void mma_f16_ss(uint32_t d, uint64_t a, uint64_t b,
                                           uint32_t idesc, uint32_t en) {
    asm volatile(
        "{\n\t.reg .pred p;\n\tsetp.ne.u32 p, %5, 0;\n\t"
        "tcgen05.mma.cta_group::1.kind::f16 [%0], %1, %2, %3, {%4, %4, %4, %4}, p;\n\t}"
        :: "r"(d), "l"(a), "l"(b), "r"(idesc), "r"(0u), "r"(en) : "memory");
}

#define IDESC_N128 ((1u<<4)|(1u<<7)|(1u<<10)|((128u/8)<<17)|((128u/16)<<24))
#define IDESC_N64  ((1u<<4)|(1u<<7)|(1u<<10)|(( 64u/8)<<17)|((128u/16)<<24))

// ---- tensor-GEMM core (no register prefetch — measured best) ----
__device__ __forceinline__ void tgemm_core(char* sb, uint32_t base,
    const __nv_bfloat16* __restrict__ Ah, const __nv_bfloat16* __restrict__ Al,
    const __nv_bfloat16* __restrict__ Bh, const __nv_bfloat16* __restrict__ Bl,
    float* __restrict__ C, int lda, int ldb, int ldc, int nkc, int m0, int n0)
{
    uint32_t ctrl = base + 65536;
    uint32_t mbar = ctrl + 8;
    int t = threadIdx.x;

    if (t == 0) MBARRIER_INIT(mbar, 1);
    if (t < 32) { TCGEN05_ALLOC(ctrl, 128); TCGEN05_RELINQ(); }
    __syncthreads();
    uint32_t tmem;
    asm volatile("ld.shared.b32 %0, [%1];" : "=r"(tmem) : "r"(ctrl));

    Ah += (size_t)m0 * lda; Al += (size_t)m0 * lda;
    Bh += (size_t)n0 * ldb; Bl += (size_t)n0 * ldb;

    uint64_t dAh = make_desc(base + 0*16384);
    uint64_t dAl = make_desc(base + 1*16384);
    uint64_t dBh = make_desc(base + 2*16384);
    uint64_t dBl = make_desc(base + 3*16384);

    int rb = t >> 4, kq = t & 15;

    for (int kc = 0; kc < nkc; kc++) {
        if (kc > 0) MBARRIER_WAIT_PARITY(mbar, (kc-1) & 1);
        int k0 = kc*64;
#pragma unroll
        for (int i = 0; i < 8; i++) {
            int r = rb + i*16;
            uint32_t so = swz((uint32_t)(r*128 + kq*8));
            *(uint2*)(sb + 0*16384 + so) = *(const uint2*)(Ah + (size_t)r*lda + k0 + kq*4);
            *(uint2*)(sb + 1*16384 + so) = *(const uint2*)(Al + (size_t)r*lda + k0 + kq*4);
            *(uint2*)(sb + 2*16384 + so) = *(const uint2*)(Bh + (size_t)r*ldb + k0 + kq*4);
            *(uint2*)(sb + 3*16384 + so) = *(const uint2*)(Bl + (size_t)r*ldb + k0 + kq*4);
        }
        __syncthreads();
        if (t < 32) {
            if (elect_one_pred()) {
                FENCE_ASYNC_SHARED();
#pragma unroll
                for (int ks = 0; ks < 4; ks++) {
                    uint64_t o = ks*2;
                    mma_f16_ss(tmem, dAh+o, dBh+o, IDESC_N128, (kc > 0 || ks > 0) ? 1u : 0u);
                    mma_f16_ss(tmem, dAh+o, dBl+o, IDESC_N128, 1u);
                    mma_f16_ss(tmem, dAl+o, dBh+o, IDESC_N128, 1u);
                }
                TCGEN05_COMMIT(mbar);
            }
        }
    }
    MBARRIER_WAIT_PARITY(mbar, (nkc-1) & 1);
    TCGEN05_FENCE_AFTER();

    int w = t >> 5, lane = t & 31;
    int sub = w & 3, half = w >> 2;
    float* Crow = C + (size_t)(m0 + sub*32 + lane)*ldc + n0;
#pragma unroll
    for (int gi = 0; gi < 2; gi++) {
        int g = half*2 + gi;
        uint32_t r[32];
        TCGEN05_LD_X32(r, tmem + g*32);
        TCGEN05_WAIT_LD();
        TCGEN05_FENCE_BEFORE();
#pragma unroll
        for (int j = 0; j < 8; j++)
            *(float4*)(Crow + g*32 + j*4) = make_float4(
                __uint_as_float(r[j*4+0]), __uint_as_float(r[j*4+1]),
                __uint_as_float(r[j*4+2]), __uint_as_float(r[j*4+3]));
    }
    __syncthreads();
    if (t < 32) TCGEN05_DEALLOC(tmem, 128);
}
#else
__device__ __forceinline__ void tgemm_core_simt(
    const __nv_bfloat16* Ah, const __nv_bfloat16* Al,
    const __nv_bfloat16* Bh, const __nv_bfloat16* Bl,
    float* C, int lda, int ldb, int ldc, int nkc, int m0, int n0)
{
    int t = threadIdx.x;
    int m = m0 + (t >> 1);
    int nb = (t & 1) * 64;
    for (int n = nb; n < nb + 64; n++) {
        float acc = 0.0f;
        for (int k = 0; k < nkc*64; k++) {
            float a = __bfloat162float(Ah[(size_t)m*lda+k]) + __bfloat162float(Al[(size_t)m*lda+k]);
            float b = __bfloat162float(Bh[(size_t)(n0+n)*ldb+k]) + __bfloat162float(Bl[(size_t)(n0+n)*ldb+k]);
            acc = fmaf(a, b, acc);
        }
        C[(size_t)m*ldc + n0 + n] = acc;
    }
}
#endif // HAS_TC

#define TG_SMEM (1024 + 4*16384 + 64)

// =====================================================================
// KNN
// =====================================================================
__global__ void knn_kernel(const float* __restrict__ xyz)
{
    __shared__ float d2s[NN];
    __shared__ float rv[256];
    __shared__ int   ri[256];
    int m = blockIdx.x;
    int b = m >> 11;
    int t = threadIdx.x;
    const float* base = xyz + (size_t)(b << 11) * 3;

    float qx = xyz[m*3+0], qy = xyz[m*3+1], qz = xyz[m*3+2];
    float sqq = qx*qx + qy*qy + qz*qz;

    for (int j = t; j < NN; j += 256) {
        float px = base[j*3+0], py = base[j*3+1], pz = base[j*3+2];
        float sqp = px*px + py*py + pz*pz;
        float dot = qx*px + qy*py + qz*pz;
        d2s[j] = sqq + sqp - 2.0f*dot;
    }
    __syncthreads();

    for (int it = 0; it < KNB; it++) {
        float bv = FLT_MAX; int bi = 0x3fffffff;
        for (int j = t; j < NN; j += 256) {
            float v = d2s[j];
            if (v < bv) { bv = v; bi = j; }
        }
        rv[t] = bv; ri[t] = bi;
        __syncthreads();
        for (int s = 128; s; s >>= 1) {
            if (t < s) {
                float ov = rv[t+s]; int oi = ri[t+s];
                if (ov < rv[t] || (ov == rv[t] && oi < ri[t])) { rv[t] = ov; ri[t] = oi; }
            }
            __syncthreads();
        }
        if (t == 0) { g_idx[(size_t)m*KNB + it] = ri[0]; d2s[ri[0]] = FLT_MAX; }
        __syncthreads();
    }
}

// =====================================================================
// transpose f
// =====================================================================
__global__ void transpose_f(const float* __restrict__ f)
{
    __shared__ float tile[32][33];
    int b  = blockIdx.z;
    int n0 = blockIdx.x * 32;
    int c0 = blockIdx.y * 32;
    int tx = threadIdx.x, ty = threadIdx.y;
#pragma unroll
    for (int i = 0; i < 32; i += 8)
        tile[ty+i][tx] = f[((size_t)b*CIN + c0 + ty + i)*NN + n0 + tx];
    __syncthreads();
#pragma unroll
    for (int i = 0; i < 32; i += 8)
        g_ft[((size_t)b*NN + n0 + ty + i)*CIN + c0 + tx] = tile[tx][ty+i];
}

// =====================================================================
// geo pre-activation: store only max/min over k + fused stat partials
// grid NGEOREG=2048 regions x 128 threads; 4 points per region
// =====================================================================
__global__ void geo_pre(const float* __restrict__ xyz, const float* __restrict__ Wg)
{
    __shared__ float nb3[KNB*3];
    int region = blockIdx.x;
    int c = threadIdx.x;
    float w0 = Wg[c*6+0], w1 = Wg[c*6+1], w2 = Wg[c*6+2];
    float w3 = Wg[c*6+3], w4 = Wg[c*6+4], w5 = Wg[c*6+5];
    float s = 0.0f, s2 = 0.0f;

    for (int p = 0; p < 4; p++) {
        int m = region*4 + p;
        int b = m >> 11;
        __syncthreads();
        if (c < KNB) {
            int nb = g_idx[(size_t)m*KNB + c];
            const float* pp = xyz + (size_t)((b << 11) + nb)*3;
            nb3[c*3+0] = pp[0]; nb3[c*3+1] = pp[1]; nb3[c*3+2] = pp[2];
        }
        __syncthreads();
        float cx = xyz[m*3+0], cy = xyz[m*3+1], cz = xyz[m*3+2];
        float base = w0*cx + w1*cy + w2*cz;
        float mx = -FLT_MAX, mn = FLT_MAX;
#pragma unroll 3
        for (int k = 0; k < KNB; k++) {
            float dx = nb3[k*3+0]-cx, dy = nb3[k*3+1]-cy, dz = nb3[k*3+2]-cz;
            float z = base + w3*dx + w4*dy + w5*dz;
            s += z; s2 = fmaf(z, z, s2);
            mx = fmaxf(mx, z); mn = fminf(mn, z);
        }
        g_zmx[(size_t)m*128 + c] = mx;
        g_zmn[(size_t)m*128 + c] = mn;
    }
    g_geo_part[(size_t)region*256 + c]       = s;
    g_geo_part[(size_t)region*256 + 128 + c] = s2;
}

// geo partial combine: 64 blocks x 128 threads, 32 regions each
__global__ void geo_combine()
{
    int c = threadIdx.x;
    int blk = blockIdx.x;
    float s = 0.0f, s2 = 0.0f;
    for (int r = blk*32; r < blk*32 + 32; r++) {
        s  += g_geo_part[(size_t)r*256 + c];
        s2 += g_geo_part[(size_t)r*256 + 128 + c];
    }
    g_geo_c[blk*256 + c]       = s;
    g_geo_c[blk*256 + 128 + c] = s2;
}

// feat partial combine: 64 blocks x 128 threads, 21 tiles each (64*21=1344)
__global__ void feat_combine()
{
    int c = threadIdx.x;
    int blk = blockIdx.x;
    float s = 0.0f, s2 = 0.0f;
    for (int r = blk*21; r < blk*21 + 21; r++) {
        s  += g_feat_part[(size_t)r*256 + c];
        s2 += g_feat_part[(size_t)r*256 + 128 + c];
    }
    g_feat_c[blk*256 + c]       = s;
    g_feat_c[blk*256 + 128 + c] = s2;
}

// final act stats combine (double, fixed order)
__global__ void bn_stats_act(float* msc)
{
    int c = threadIdx.x;
    double s = 0.0, s2 = 0.0;
    if (c < 128) {
        for (int r = 0; r < 64; r++) {
            s  += (double)g_geo_c[r*256 + c];
            s2 += (double)g_geo_c[r*256 + 128 + c];
        }
    } else {
        int cc = c - 128;
        for (int r = 0; r < 64; r++) {
            s  += (double)g_feat_c[r*256 + cc];
            s2 += (double)g_feat_c[r*256 + 128 + cc];
        }
    }
    double mean = s / (double)RTOT;
    double var  = s2 / (double)RTOT - mean*mean;
    msc[c]      = (float)mean;
    msc[CO + c] = (float)(1.0 / sqrt(var + (double)EPSB));
}

// =====================================================================
// gather feat_in -> bf16 split
// =====================================================================
__global__ void gather_feat()
{
    uint32_t tid = blockIdx.x*256u + threadIdx.x;
    uint32_t r = tid >> 5;
    uint32_t c4 = (tid & 31u) * 4u;
    uint32_t m = r / KNB;
    uint32_t b = m >> 11;
    float4 v;
    if (c4 < 64u) {
        uint32_t nb = (uint32_t)g_idx[r];
        v = *(const float4*)(g_ft + (size_t)((b << 11) + nb)*CIN + c4);
    } else {
        v = *(const float4*)(g_ft + (size_t)m*CIN + (c4 - 64u));
    }
    __nv_bfloat16 h0 = __float2bfloat16(v.x);
    __nv_bfloat16 h1 = __float2bfloat16(v.y);
    __nv_bfloat16 h2 = __float2bfloat16(v.z);
    __nv_bfloat16 h3 = __float2bfloat16(v.w);
    size_t o = (size_t)r*128 + c4;
    *(uint2*)(g_ginh + o) = make_uint2(bpackh(h0,h1), bpackh(h2,h3));
    *(uint2*)(g_ginl + o) = make_uint2(
        bpackh(__float2bfloat16(v.x - __bfloat162float(h0)),
               __float2bfloat16(v.y - __bfloat162float(h1))),
        bpackh(__float2bfloat16(v.z - __bfloat162float(h2)),
               __float2bfloat16(v.w - __bfloat162float(h3))));
}

// =====================================================================
// feat GEMM (no prefetch) + fused stat partials. grid (1, NFEATCTA)
// out: g_actf [RTOT,128] dense
// =====================================================================
#define FEAT_SMEM (1024 + 69632 + 64)

__global__ void __launch_bounds__(256, 1)
feat_gemm()
{
#if HAS_TC
    extern __shared__ char sm[];
    uint32_t raw = smem_u32(sm);
    uint32_t base = (raw + 1023) & ~1023u;
    char* sb = sm + (base - raw);
    uint32_t ctrl = base + 69632;
    uint32_t mbar = ctrl + 8;
    int t = threadIdx.x;
    int m0 = blockIdx.y * 128;

    if (t == 0) MBARRIER_INIT(mbar, 1);
    if (t < 32) { TCGEN05_ALLOC(ctrl, 128); TCGEN05_RELINQ(); }
    __syncthreads();
    uint32_t tmem;
    asm volatile("ld.shared.b32 %0, [%1];" : "=r"(tmem) : "r"(ctrl));

    const __nv_bfloat16* Ah = g_ginh + (size_t)m0*128;
    const __nv_bfloat16* Al = g_ginl + (size_t)m0*128;

    uint64_t dAh = make_desc(base + 0*16384);
    uint64_t dAl = make_desc(base + 1*16384);
    uint64_t dBh = make_desc(base + 2*16384);
    uint64_t dBl = make_desc(base + 3*16384);

    int rb = t >> 4, kq = t & 15;
    for (int kc = 0; kc < 2; kc++) {
        if (kc > 0) MBARRIER_WAIT_PARITY(mbar, 0);
        int k0 = kc*64;
#pragma unroll
        for (int i = 0; i < 8; i++) {
            int r = rb + i*16;
            uint32_t so = swz((uint32_t)(r*128 + kq*8));
            *(uint2*)(sb + 0*16384 + so) = *(const uint2*)(Ah + (size_t)r*128 + k0 + kq*4);
            *(uint2*)(sb + 1*16384 + so) = *(const uint2*)(Al + (size_t)r*128 + k0 + kq*4);
            *(uint2*)(sb + 2*16384 + so) = *(const uint2*)(g_wfh + (size_t)r*128 + k0 + kq*4);
            *(uint2*)(sb + 3*16384 + so) = *(const uint2*)(g_wfl + (size_t)r*128 + k0 + kq*4);
        }
        __syncthreads();
        if (t < 32) {
            if (elect_one_pred()) {
                FENCE_ASYNC_SHARED();
#pragma unroll
                for (int ks = 0; ks < 4; ks++) {
                    uint64_t o = ks*2;
                    mma_f16_ss(tmem, dAh+o, dBh+o, IDESC_N128, (kc > 0 || ks > 0) ? 1u : 0u);
                    mma_f16_ss(tmem, dAh+o, dBl+o, IDESC_N128, 1u);
                    mma_f16_ss(tmem, dAl+o, dBh+o, IDESC_N128, 1u);
                }
                TCGEN05_COMMIT(mbar);
            }
        }
    }
    MBARRIER_WAIT_PARITY(mbar, 1);
    TCGEN05_FENCE_AFTER();

    int w = t >> 5, lane = t & 31;
    int sub = w & 3, half = w >> 2;
    int row = sub*32 + lane;
    float* Crow = g_actf + (size_t)(m0 + row)*128;
    float* stile = (float*)sb;   // [128][132], inputs dead now
#pragma unroll
    for (int gi = 0; gi < 2; gi++) {
        int g = half*2 + gi;
        uint32_t r[32];
        TCGEN05_LD_X32(r, tmem + g*32);
        TCGEN05_WAIT_LD();
        TCGEN05_FENCE_BEFORE();
#pragma unroll
        for (int j = 0; j < 8; j++) {
            float4 v = make_float4(
                __uint_as_float(r[j*4+0]), __uint_as_float(r[j*4+1]),
                __uint_as_float(r[j*4+2]), __uint_as_float(r[j*4+3]));
            *(float4*)(Crow + g*32 + j*4) = v;
            *(float4*)(stile + row*132 + g*32 + j*4) = v;
        }
    }
    __syncthreads();
    if (t < 128) {
        float a0=0,a1=0, q0=0,q1=0;
        for (int rr = 0; rr < 128; rr += 2) {
            float v0 = stile[rr*132 + t], v1 = stile[(rr+1)*132 + t];
            a0 += v0; q0 = fmaf(v0,v0,q0);
            a1 += v1; q1 = fmaf(v1,v1,q1);
        }
        g_feat_part[(size_t)blockIdx.y*256 + t]       = a0 + a1;
        g_feat_part[(size_t)blockIdx.y*256 + 128 + t] = q0 + q1;
    }
    __syncthreads();
    if (t < 32) TCGEN05_DEALLOC(tmem, 128);
#else
    int t = threadIdx.x;
    int m0 = blockIdx.y*128;
    int m = m0 + (t >> 1);
    int nb = (t & 1) * 64;
    for (int n = nb; n < nb + 64; n++) {
        float acc = 0.0f;
        for (int k = 0; k < 128; k++) {
            float a = __bfloat162float(g_ginh[(size_t)m*128+k]) + __bfloat162float(g_ginl[(size_t)m*128+k]);
            float b = __bfloat162float(g_wfh[(size_t)n*128+k]) + __bfloat162float(g_wfl[(size_t)n*128+k]);
            acc = fmaf(a, b, acc);
        }
        g_actf[(size_t)m*128 + n] = acc;
    }
    __syncthreads();
    if (t < 128) {
        float s = 0, q = 0;
        for (int rr = 0; rr < 128; rr++) {
            float v = g_actf[(size_t)(m0+rr)*128 + t];
            s += v; q = fmaf(v,v,q);
        }
        g_feat_part[(size_t)blockIdx.y*256 + t] = s;
        g_feat_part[(size_t)blockIdx.y*256 + 128 + t] = q;
    }
#endif
}

// =====================================================================
// tensor GEMM wrappers
// =====================================================================
__global__ void __launch_bounds__(256, 1)
tgemm(const __nv_bfloat16* __restrict__ Ah, const __nv_bfloat16* __restrict__ Al,
      const __nv_bfloat16* __restrict__ Bh, const __nv_bfloat16* __restrict__ Bl,
      float* __restrict__ C, int lda, int ldb, int ldc, int nkc)
{
#if HAS_TC
    extern __shared__ char sm[];
    uint32_t raw = smem_u32(sm);
    uint32_t base = (raw + 1023) & ~1023u;
    tgemm_core(sm + (base - raw), base, Ah, Al, Bh, Bl, C, lda, ldb, ldc, nkc,
               blockIdx.y*128, blockIdx.x*128);
#else
    tgemm_core_simt(Ah, Al, Bh, Bl, C, lda, ldb, ldc, nkc, blockIdx.y*128, blockIdx.x*128);
#endif
}

__global__ void __launch_bounds__(256, 1)
qkv_gemm()
{
    int z = blockIdx.z;
    const __nv_bfloat16* Bh = (z==0) ? g_wqh : (z==1) ? g_wkh : g_wvh;
    const __nv_bfloat16* Bl = (z==0) ? g_wql : (z==1) ? g_wkl : g_wvl;
    float* C = (z==0) ? g_q : (z==1) ? g_k : g_v;
#if HAS_TC
    extern __shared__ char sm[];
    uint32_t raw = smem_u32(sm);
    uint32_t base = (raw + 1023) & ~1023u;
    tgemm_core(sm + (base - raw), base, g_xh, g_xl, Bh, Bl, C, CO, CO, CO, 4,
               blockIdx.y*128, blockIdx.x*128);
#else
    tgemm_core_simt(g_xh, g_xl, Bh, Bl, C, CO, CO, CO, 4, blockIdx.y*128, blockIdx.x*128);
#endif
}

// =====================================================================
// BN stats (fp32 partials, double combine) — small tensors
// =====================================================================
__device__ __forceinline__ void bn_partial_region(const float* X, long rows,
                                                  int nblk, int blk, int region)
{
    int c = threadIdx.x;
    long per = (rows + nblk - 1) / nblk;
    long r0 = (long)blk * per;
    long r1 = r0 + per; if (r1 > rows) r1 = rows;
    float a0=0,a1=0,a2=0,a3=0, q0=0,q1=0,q2=0,q3=0;
    long r = r0;
    for (; r + 4 <= r1; r += 4) {
        float v0 = X[(r+0)*CO + c], v1 = X[(r+1)*CO + c];
        float v2 = X[(r+2)*CO + c], v3 = X[(r+3)*CO + c];
        a0 += v0; q0 = fmaf(v0,v0,q0);
        a1 += v1; q1 = fmaf(v1,v1,q1);
        a2 += v2; q2 = fmaf(v2,v2,q2);
        a3 += v3; q3 = fmaf(v3,v3,q3);
    }
    for (; r < r1; r++) { float v = X[r*CO + c]; a0 += v; q0 = fmaf(v,v,q0); }
    g_partf[((size_t)region*2 + 0)*CO + c] = (a0+a1) + (a2+a3);
    g_partf[((size_t)region*2 + 1)*CO + c] = (q0+q1) + (q2+q3);
}

__global__ void bn_stats_partial(const float* __restrict__ X, long rows)
{
    bn_partial_region(X, rows, gridDim.x, blockIdx.x, blockIdx.x);
}

__global__ void bn_stats_final(int nblocks, long rows, float* msc)
{
    int c = threadIdx.x;
    double s = 0.0, s2 = 0.0;
    for (int i = 0; i < nblocks; i++) {
        s  += (double)g_partf[((size_t)i*2 + 0)*CO + c];
        s2 += (double)g_partf[((size_t)i*2 + 1)*CO + c];
    }
    double mean = s / (double)rows;
    double var  = s2 / (double)rows - mean*mean;
    msc[c]      = (float)mean;
    msc[CO + c] = (float)(1.0 / sqrt(var + (double)EPSB));
}

__global__ void bn_stats_qkv()
{
    const float* X = (blockIdx.y==0) ? g_q : (blockIdx.y==1) ? g_k : g_v;
    bn_partial_region(X, MTOT, 64, blockIdx.x, blockIdx.y*64 + blockIdx.x);
}
__global__ void bn_final_qkv(float* msc)
{
    int y = blockIdx.x;
    int c = threadIdx.x;
    double s = 0.0, s2 = 0.0;
    for (int i = y*64; i < y*64 + 64; i++) {
        s  += (double)g_partf[((size_t)i*2 + 0)*CO + c];
        s2 += (double)g_partf[((size_t)i*2 + 1)*CO + c];
    }
    double mean = s / (double)MTOT;
    double var  = s2 / (double)MTOT - mean*mean;
    msc[(2+y)*512 + c]      = (float)mean;
    msc[(2+y)*512 + CO + c] = (float)(1.0 / sqrt(var + (double)EPSB));
}

// =====================================================================
// branch BN + relu + maxpool
// geo half: exact via monotonicity (zmax if scale>=0 else zmin)
// feat half: loop over 21 stored pre-activations
// =====================================================================
__global__ void branch_apply(const float* msc,
                             const float* __restrict__ g_geo, const float* __restrict__ b_geo,
                             const float* __restrict__ g_fea, const float* __restrict__ b_fea)
{
    int m = blockIdx.x;
    int c = threadIdx.x;
    float mean = msc[c], istd = msc[CO + c];
    float ga = (c < 128) ? g_geo[c] : g_fea[c - 128];
    float be = (c < 128) ? b_geo[c] : b_fea[c - 128];
    float sc = istd * ga;
    float best;
    if (c < 128) {
        float zv = (sc >= 0.0f) ? g_zmx[(size_t)m*128 + c] : g_zmn[(size_t)m*128 + c];
        best = fmaxf((zv - mean) * sc + be, 0.0f);
    } else {
        best = -FLT_MAX;
        const float* basep = g_actf + (size_t)m*KNB*128 + (c - 128);
#pragma unroll 3
        for (int k = 0; k < KNB; k++) {
            float y = fmaxf((basep[(size_t)k*128] - mean) * sc + be, 0.0f);
            best = fmaxf(best, y);
        }
    }
    g_featv[(size_t)m*CO + c] = best;
}

// =====================================================================
// BN apply variants
// =====================================================================
__global__ void bn_apply(const float* __restrict__ in, float* __restrict__ out,
                         const float* msc,
                         const float* __restrict__ gamma, const float* __restrict__ beta,
                         const float* __restrict__ res, int do_relu)
{
    size_t i = (size_t)blockIdx.x * blockDim.x + threadIdx.x;
    int c = (int)(i & (CO-1));
    float y = (in[i] - msc[c]) * msc[CO + c] * gamma[c] + beta[c];
    if (do_relu) y = fmaxf(y, 0.0f);
    if (res) y += res[i];
    out[i] = y;
}

__global__ void bn_apply_split(const float* __restrict__ in,
                               const float* msc,
                               const float* __restrict__ gamma, const float* __restrict__ beta,
                               int do_relu,
                               __nv_bfloat16* __restrict__ oh, __nv_bfloat16* __restrict__ ol)
{
    size_t i = (size_t)blockIdx.x * blockDim.x + threadIdx.x;
    int c = (int)(i & (CO-1));
    float y = (in[i] - msc[c]) * msc[CO + c] * gamma[c] + beta[c];
    if (do_relu) y = fmaxf(y, 0.0f);
    __nv_bfloat16 hb = __float2bfloat16(y);
    oh[i] = hb;
    ol[i] = __float2bfloat16(y - __bfloat162float(hb));
}

__global__ void bn_apply_qkv(const float* msc,
                             const float* __restrict__ gq, const float* __restrict__ bq,
                             const float* __restrict__ gk, const float* __restrict__ bk,
                             const float* __restrict__ gv, const float* __restrict__ bv)
{
    int y = blockIdx.y;
    size_t i = (size_t)blockIdx.x * 256 + threadIdx.x;
    int c = (int)(i & (CO-1));
    const float* in = (y==0) ? g_q : (y==1) ? g_k : g_v;
    const float* ga = (y==0) ? gq : (y==1) ? gk : gv;
    const float* be = (y==0) ? bq : (y==1) ? bk : bv;
    const float* ms = msc + (2+y)*512;
    float v = fmaxf((in[i] - ms[c]) * ms[CO + c] * ga[c] + be[c], 0.0f);
    if (y == 2) { g_v[i] = v; return; }
    __nv_bfloat16 hb = __float2bfloat16(v);
    __nv_bfloat16 lb = __float2bfloat16(v - __bfloat162float(hb));
    if (y == 0) { g_qh[i] = hb; g_ql[i] = lb; }
    else        { g_kh[i] = hb; g_kl[i] = lb; }
}

// =====================================================================
// fused weight splits
// =====================================================================
__global__ void split_weights(const float* __restrict__ Wf, const float* __restrict__ Wq,
                              const float* __restrict__ Wk, const float* __restrict__ Wv,
                              const float* __restrict__ Wfus, const float* __restrict__ Wm)
{
    int i = blockIdx.x*256 + threadIdx.x;
    const float* src; __nv_bfloat16 *dh, *dl; int off;
    if      (i < 16384)  { src = Wf;   dh = g_wfh;   dl = g_wfl;   off = i; }
    else if (i < 81920)  { src = Wq;   dh = g_wqh;   dl = g_wql;   off = i - 16384; }
    else if (i < 147456) { src = Wk;   dh = g_wkh;   dl = g_wkl;   off = i - 81920; }
    else if (i < 212992) { src = Wv;   dh = g_wvh;   dl = g_wvl;   off = i - 147456; }
    else if (i < 327680) { src = Wfus; dh = g_wfush; dl = g_wfusl; off = i - 212992; }
    else                 { src = Wm;   dh = g_wmh;   dl = g_wml;   off = i - 327680; }
    float v = src[off];
    __nv_bfloat16 hb = __float2bfloat16(v);
    dh[off] = hb;
    dl[off] = __float2bfloat16(v - __bfloat162float(hb));
}

// =====================================================================
// v -> per-head transposed bf16 split
// =====================================================================
__global__ void vt_convert()
{
    __shared__ float tile[32][33];
    int z  = blockIdx.z;
    int b  = z / HEADS, h = z - b*HEADS;
    int m0 = blockIdx.x * 32;
    int c0 = blockIdx.y * 32;
    int tx = threadIdx.x, ty = threadIdx.y;
#pragma unroll
    for (int i = 0; i < 32; i += 8)
        tile[ty+i][tx] = g_v[((size_t)(b*NN) + m0 + ty + i)*CO + h*32 + c0 + tx];
    __syncthreads();
#pragma unroll
    for (int i = 0; i < 32; i += 8) {
        int c = c0 + ty + i, m = m0 + tx;
        float v = tile[tx][ty+i];
        __nv_bfloat16 hb = __float2bfloat16(v);
        size_t o = (size_t)z*WCH*NN + (size_t)c*NN + m;
        g_vth[o] = hb;
        g_vtl[o] = __float2bfloat16(v - __bfloat162float(hb));
    }
}

// =====================================================================
// FLASH pass 1: per-row softmax stats
// grid (16 m-tiles, 28 z), 256 threads.
// =====================================================================
#define ST_SMEM (1024 + 65536 + 64 + 1088)

__global__ void __launch_bounds__(256, 1)
attn_stats()
{
#if HAS_TC
    extern __shared__ char sm[];
    uint32_t raw = smem_u32(sm);
    uint32_t base = (raw + 1023) & ~1023u;
    char* sb = sm + (base - raw);
    uint32_t ctrl = base + 65536;
    uint32_t mbar = ctrl + 8;
    float* mrg = (float*)(sb + 65536 + 64);   // 128 x {mx,sum}

    int t = threadIdx.x;
    int z = blockIdx.y;
    int b = z / HEADS, h = z - b*HEADS;
    int m0 = blockIdx.x * 128;

    if (t == 0) MBARRIER_INIT(mbar, 1);
    if (t < 32) { TCGEN05_ALLOC(ctrl, 128); TCGEN05_RELINQ(); }
    __syncthreads();
    uint32_t tmem;
    asm volatile("ld.shared.b32 %0, [%1];" : "=r"(tmem) : "r"(ctrl));

    const __nv_bfloat16* pQh = g_qh + ((size_t)(b*NN) + m0)*CO + h*32;
    const __nv_bfloat16* pQl = g_ql + ((size_t)(b*NN) + m0)*CO + h*32;
    const __nv_bfloat16* pKh = g_kh + ((size_t)b*NN)*CO + h*32;
    const __nv_bfloat16* pKl = g_kl + ((size_t)b*NN)*CO + h*32;

    int rb = t >> 4, kq = t & 15;
#pragma unroll
    for (int i = 0; i < 8; i++) {
        int r = rb + i*16;
        uint32_t so = swz((uint32_t)(r*128 + kq*8));
        *(uint2*)(sb + 0*16384 + so) = *(const uint2*)(pQh + (size_t)r*CO + kq*4);
        *(uint2*)(sb + 1*16384 + so) = *(const uint2*)(pQl + (size_t)r*CO + kq*4);
    }

    uint64_t dQh = make_desc(base + 0*16384);
    uint64_t dQl = make_desc(base + 1*16384);
    uint64_t dKh = make_desc(base + 2*16384);
    uint64_t dKl = make_desc(base + 3*16384);

    int w = t >> 5, lane = t & 31;
    int sub = w & 3, half = w >> 2;
    int rrow = sub*32 + lane;

    float mx = -FLT_MAX, sum = 0.0f;

    for (int nc = 0; nc < 16; nc++) {
        int n0 = nc*128;
#pragma unroll
        for (int i = 0; i < 8; i++) {
            int r = rb + i*16;
            uint32_t so = swz((uint32_t)(r*128 + kq*8));
            *(uint2*)(sb + 2*16384 + so) = *(const uint2*)(pKh + (size_t)(n0+r)*CO + kq*4);
            *(uint2*)(sb + 3*16384 + so) = *(const uint2*)(pKl + (size_t)(n0+r)*CO + kq*4);
        }
        __syncthreads();
        if (t < 32) {
            if (elect_one_pred()) {
                FENCE_ASYNC_SHARED();
#pragma unroll
                for (int ks = 0; ks < 4; ks++) {
                    uint64_t o = ks*2;
                    mma_f16_ss(tmem, dQh+o, dKh+o, IDESC_N128, (ks > 0) ? 1u : 0u);
                    mma_f16_ss(tmem, dQh+o, dKl+o, IDESC_N128, 1u);
                    mma_f16_ss(tmem, dQl+o, dKh+o, IDESC_N128, 1u);
                }
                TCGEN05_COMMIT(mbar);
            }
        }
        MBARRIER_WAIT_PARITY(mbar, nc & 1);
        TCGEN05_FENCE_AFTER();
#pragma unroll
        for (int gi = 0; gi < 2; gi++) {
            int g = half*2 + gi;
            uint32_t r[32];
            TCGEN05_LD_X32(r, tmem + g*32);
            TCGEN05_WAIT_LD();
            float gm = -FLT_MAX;
#pragma unroll
            for (int j = 0; j < 32; j++) gm = fmaxf(gm, __uint_as_float(r[j]));
            float gs = 0.0f;
#pragma unroll
            for (int j = 0; j < 32; j++) gs += __expf(__uint_as_float(r[j]) - gm);
            if (gm <= mx) sum += gs * __expf(gm - mx);
            else { sum = sum * __expf(mx - gm) + gs; mx = gm; }
        }
        __syncthreads();   // all LDTMs done before next MMA overwrites S
    }

    if (half == 0) { mrg[rrow*2] = mx; mrg[rrow*2+1] = sum; }
    __syncthreads();
    if (half == 1) {
        float m2 = mrg[rrow*2], s2 = mrg[rrow*2+1];
        float M = fmaxf(mx, m2);
        float S = s2 * __expf(m2 - M) + sum * __expf(mx - M);
        size_t row = (size_t)z*NN + m0 + rrow;
        g_rowstat[row*2]   = M;
        g_rowstat[row*2+1] = 1.0f / S;
    }
    __syncthreads();
    if (t < 32) TCGEN05_DEALLOC(tmem, 128);
#else
    int t = threadIdx.x;
    int z = blockIdx.y;
    int b = z / HEADS, h = z - b*HEADS;
    int m0 = blockIdx.x * 128;
    if (t >= 128) return;
    int m = m0 + t;
    const float* qp = g_q + ((size_t)(b*NN) + m)*CO + h*32;
    float mx = -FLT_MAX;
    for (int n = 0; n < NN; n++) {
        const float* kp = g_k + ((size_t)(b*NN) + n)*CO + h*32;
        float acc = 0.0f;
        for (int k = 0; k < 64; k++) acc = fmaf(qp[k], kp[k], acc);
        mx = fmaxf(mx, acc);
    }
    float sum = 0.0f;
    for (int n = 0; n < NN; n++) {
        const float* kp = g_k + ((size_t)(b*NN) + n)*CO + h*32;
        float acc = 0.0f;
        for (int k = 0; k < 64; k++) acc = fmaf(qp[k], kp[k], acc);
        sum += __expf(acc - mx);
    }
    size_t row = (size_t)z*NN + m;
    g_rowstat[row*2] = mx; g_rowstat[row*2+1] = 1.0f / sum;
#endif
}

// =====================================================================
// FLASH pass 2: recompute S, softmax, P·V in TMEM
// grid (16 m-tiles, 28 z), 256 threads.
// TMEM: S cols 0..127, O cols 128..191 (alloc 256)
// =====================================================================
#define FL_SMEM (1024 + 163840 + 64 + 1088)

__global__ void __launch_bounds__(256, 1)
attn_flash()
{
#if HAS_TC
    extern __shared__ char sm[];
    uint32_t raw = smem_u32(sm);
    uint32_t base = (raw + 1023) & ~1023u;
    char* sb = sm + (base - raw);
    const uint32_t off_Qh = 0, off_Ql = 16384, off_Kh = 32768, off_Kl = 49152;
    const uint32_t off_Vh = 65536, off_Vl = 81920, off_Ph = 98304, off_Pl = 131072;
    uint32_t ctrl = base + 163840;
    uint32_t mbar_s = ctrl + 8;
    uint32_t mbar_o = ctrl + 16;
    float* sst = (float*)(sb + 163840 + 64);

    int t = threadIdx.x;
    int z = blockIdx.y;
    int b = z / HEADS, h = z - b*HEADS;
    int m0 = blockIdx.x * 128;

    if (t == 0) { MBARRIER_INIT(mbar_s, 1); MBARRIER_INIT(mbar_o, 1); }
    if (t < 32) { TCGEN05_ALLOC(ctrl, 256); TCGEN05_RELINQ(); }
    sst[t] = g_rowstat[(size_t)(z*NN + m0)*2 + t];
    __syncthreads();
    uint32_t tmem;
    asm volatile("ld.shared.b32 %0, [%1];" : "=r"(tmem) : "r"(ctrl));
    uint32_t tmemO = tmem + 128;

    const __nv_bfloat16* pQh = g_qh + ((size_t)(b*NN) + m0)*CO + h*32;
    const __nv_bfloat16* pQl = g_ql + ((size_t)(b*NN) + m0)*CO + h*32;
    const __nv_bfloat16* pKh = g_kh + ((size_t)b*NN)*CO + h*32;
    const __nv_bfloat16* pKl = g_kl + ((size_t)b*NN)*CO + h*32;
    const __nv_bfloat16* Vh = g_vth + (size_t)z*WCH*NN;
    const __nv_bfloat16* Vl = g_vtl + (size_t)z*WCH*NN;

    int rb = t >> 4, kq = t & 15;
#pragma unroll
    for (int i = 0; i < 8; i++) {
        int r = rb + i*16;
        uint32_t so = swz((uint32_t)(r*128 + kq*8));
        *(uint2*)(sb + off_Qh + so) = *(const uint2*)(pQh + (size_t)r*CO + kq*4);
        *(uint2*)(sb + off_Ql + so) = *(const uint2*)(pQl + (size_t)r*CO + kq*4);
    }

    uint64_t dQh = make_desc(base + off_Qh);
    uint64_t dQl = make_desc(base + off_Ql);
    uint64_t dKh = make_desc(base + off_Kh);
    uint64_t dKl = make_desc(base + off_Kl);

    int w = t >> 5, lane = t & 31;
    int sub = w & 3, half = w >> 2;
    int rrow = sub*32 + lane;
    float mxr = sst[rrow*2], invr = sst[rrow*2+1];

    for (int nc = 0; nc < 16; nc++) {
        int n0 = nc*128;
        if (nc > 0) MBARRIER_WAIT_PARITY(mbar_o, (nc-1) & 1);

#pragma unroll
        for (int i = 0; i < 8; i++) {
            int r = rb + i*16;
            uint32_t so = swz((uint32_t)(r*128 + kq*8));
            *(uint2*)(sb + off_Kh + so) = *(const uint2*)(pKh + (size_t)(n0+r)*CO + kq*4);
            *(uint2*)(sb + off_Kl + so) = *(const uint2*)(pKl + (size_t)(n0+r)*CO + kq*4);
        }
#pragma unroll
        for (int i = 0; i < 4; i++) {
            int r = rb + i*16;
            uint32_t so = swz((uint32_t)(r*128 + kq*8));
#pragma unroll
            for (int j = 0; j < 2; j++) {
                size_t gk = (size_t)r*NN + n0 + j*64 + kq*4;
                *(uint2*)(sb + off_Vh + j*8192 + so) = *(const uint2*)(Vh + gk);
                *(uint2*)(sb + off_Vl + j*8192 + so) = *(const uint2*)(Vl + gk);
            }
        }
        __syncthreads();

        // S = Q K^T (fresh accumulator each chunk)
        if (t < 32) {
            if (elect_one_pred()) {
                FENCE_ASYNC_SHARED();
#pragma unroll
                for (int ks = 0; ks < 4; ks++) {
                    uint64_t o = ks*2;
                    mma_f16_ss(tmem, dQh+o, dKh+o, IDESC_N128, (ks > 0) ? 1u : 0u);
                    mma_f16_ss(tmem, dQh+o, dKl+o, IDESC_N128, 1u);
                    mma_f16_ss(tmem, dQl+o, dKh+o, IDESC_N128, 1u);
                }
                TCGEN05_COMMIT(mbar_s);
            }
        }
        MBARRIER_WAIT_PARITY(mbar_s, nc & 1);
        TCGEN05_FENCE_AFTER();

#pragma unroll
        for (int gi = 0; gi < 2; gi++) {
            int g = half*2 + gi;
            uint32_t r[32];
            TCGEN05_LD_X32(r, tmem + g*32);
            TCGEN05_WAIT_LD();
#pragma unroll
            for (int j = 0; j < 8; j++) {
                float v0 = __expf(__uint_as_float(r[j*4+0]) - mxr) * invr;
                float v1 = __expf(__uint_as_float(r[j*4+1]) - mxr) * invr;
                float v2 = __expf(__uint_as_float(r[j*4+2]) - mxr) * invr;
                float v3 = __expf(__uint_as_float(r[j*4+3]) - mxr) * invr;
                __nv_bfloat16 h0 = __float2bfloat16(v0);
                __nv_bfloat16 h1 = __float2bfloat16(v1);
                __nv_bfloat16 h2 = __float2bfloat16(v2);
                __nv_bfloat16 h3 = __float2bfloat16(v3);
                uint32_t so = swz((uint32_t)(rrow*128 + (gi*32 + j*4)*2));
                *(uint2*)(sb + off_Ph + half*16384 + so) = make_uint2(bpackh(h0,h1), bpackh(h2,h3));
                *(uint2*)(sb + off_Pl + half*16384 + so) = make_uint2(
                    bpackh(__float2bfloat16(v0 - __bfloat162float(h0)),
                           __float2bfloat16(v1 - __bfloat162float(h1))),
                    bpackh(__float2bfloat16(v2 - __bfloat162float(h2)),
                           __float2bfloat16(v3 - __bfloat162float(h3))));
            }
        }
        __syncthreads();

        // O += P V^T
        if (t < 32) {
            if (elect_one_pred()) {
                FENCE_ASYNC_SHARED();
#pragma unroll
                for (int kch = 0; kch < 2; kch++) {
                    uint64_t dPh = make_desc(base + off_Ph + kch*16384);
                    uint64_t dPl = make_desc(base + off_Pl + kch*16384);
                    uint64_t dVh2 = make_desc(base + off_Vh + kch*8192);
                    uint64_t dVl2 = make_desc(base + off_Vl + kch*8192);
#pragma unroll
                    for (int ks = 0; ks < 4; ks++) {
                        uint64_t o = ks*2;
                        mma_f16_ss(tmemO, dPh+o, dVh2+o, IDESC_N64,
                                   (nc > 0 || kch > 0 || ks > 0) ? 1u : 0u);
                        mma_f16_ss(tmemO, dPh+o, dVl2+o, IDESC_N64, 1u);
                        mma_f16_ss(tmemO, dPl+o, dVh2+o, IDESC_N64, 1u);
                    }
                }
                TCGEN05_COMMIT(mbar_o);
            }
        }
    }
    MBARRIER_WAIT_PARITY(mbar_o, 1);
    TCGEN05_FENCE_AFTER();

    size_t rbase = (size_t)(b*NN + m0 + rrow)*FUSC + h*64 + half*32;
    {
        uint32_t r[32];
        TCGEN05_LD_X32(r, tmemO + half*32);
        TCGEN05_WAIT_LD();
        TCGEN05_FENCE_BEFORE();
#pragma unroll
        for (int j = 0; j < 8; j++) {
            float v0 = __uint_as_float(r[j*4+0]);
            float v1 = __uint_as_float(r[j*4+1]);
            float v2 = __uint_as_float(r[j*4+2]);
            float v3 = __uint_as_float(r[j*4+3]);
            __nv_bfloat16 h0 = __float2bfloat16(v0);
            __nv_bfloat16 h1 = __float2bfloat16(v1);
            __nv_bfloat16 h2 = __float2bfloat16(v2);
            __nv_bfloat16 h3 = __float2bfloat16(v3);
            *(uint2*)(g_Oh + rbase + j*4) = make_uint2(bpackh(h0,h1), bpackh(h2,h3));
            *(uint2*)(g_Ol + rbase + j*4) = make_uint2(
                bpackh(__float2bfloat16(v0 - __bfloat162float(h0)),
                       __float2bfloat16(v1 - __bfloat162float(h1))),
                bpackh(__float2bfloat16(v2 - __bfloat162float(h2)),
                       __float2bfloat16(v3 - __bfloat162float(h3))));
        }
    }
    __syncthreads();
    if (t < 32) TCGEN05_DEALLOC(tmem, 256);
#else
    int t = threadIdx.x;
    int z = blockIdx.y;
    int b = z / HEADS, h = z - b*HEADS;
    int m0 = blockIdx.x * 128;
    if (t >= 128) return;
    int m = m0 + t;
    const float* qp = g_q + ((size_t)(b*NN) + m)*CO + h*32;
    float mxr = g_rowstat[(size_t)(z*NN + m)*2], invr = g_rowstat[(size_t)(z*NN + m)*2+1];
    for (int c = 0; c < 64; c++) {
        float acc = 0.0f;
        for (int n = 0; n < NN; n++) {
            const float* kp = g_k + ((size_t)(b*NN) + n)*CO + h*32;
            float s = 0.0f;
            for (int k = 0; k < 64; k++) s = fmaf(qp[k], kp[k], s);
            acc = fmaf(__expf(s - mxr)*invr, g_v[((size_t)(b*NN) + n)*CO + h*32 + c], acc);
        }
        size_t o = (size_t)(b*NN + m)*FUSC + h*64 + c;
        __nv_bfloat16 hb = __float2bfloat16(acc);
        g_Oh[o] = hb;
        g_Ol[o] = __float2bfloat16(acc - __bfloat162float(hb));
    }
#endif
}

// =====================================================================
// LayerNorm -> bf16 split
// =====================================================================
__global__ void layernorm_kernel(const float* __restrict__ X,
                                 const float* __restrict__ g, const float* __restrict__ b)
{
    int m = blockIdx.x, c = threadIdx.x;
    __shared__ float red[256];
    float v = X[(size_t)m*CO + c];
    red[c] = v; __syncthreads();
    for (int s = 128; s; s >>= 1) { if (c < s) red[c] += red[c+s]; __syncthreads(); }
    float mean = red[0] * (1.0f/CO); __syncthreads();
    float d = v - mean;
    red[c] = d*d; __syncthreads();
    for (int s = 128; s; s >>= 1) { if (c < s) red[c] += red[c+s]; __syncthreads(); }
    float var = red[0] * (1.0f/CO);
    float y = d * rsqrtf(var + EPSB) * g[c] + b[c];
    __nv_bfloat16 hb = __float2bfloat16(y);
    size_t i = (size_t)m*CO + c;
    g_yh[i] = hb;
    g_yl[i] = __float2bfloat16(y - __bfloat162float(hb));
}

// =====================================================================
// final output (transposed)
// =====================================================================
__global__ void final_out(const float* __restrict__ bias, float* __restrict__ out)
{
    __shared__ float tile[32][33];
    int b  = blockIdx.z;
    int n0 = blockIdx.x * 32;
    int c0 = blockIdx.y * 32;
    int tx = threadIdx.x, ty = threadIdx.y;
#pragma unroll
    for (int i = 0; i < 32; i += 8) {
        int n = n0 + ty + i, c = c0 + tx;
        size_t src = ((size_t)b*NN + n)*CO + c;
        tile[ty+i][tx] = g_f2[src] + g_fp[src] + bias[c];
    }
    __syncthreads();
#pragma unroll
    for (int i = 0; i < 32; i += 8) {
        int c = c0 + ty + i, n = n0 + tx;
        out[((size_t)b*CO + c)*NN + n] = tile[tx][ty+i];
    }
}

// =====================================================================
// host
// =====================================================================
extern "C" void kernel_launch(void* const* d_in, const int* in_sizes, int n_in,
                              void* d_out, int out_size)
{
    const float* xyz    = (const float*)d_in[0];
    const float* f      = (const float*)d_in[1];
    const float* W_geo  = (const float*)d_in[2];
    const float* gg     = (const float*)d_in[3];
    const float* bg     = (const float*)d_in[4];
    const float* W_feat = (const float*)d_in[5];
    const float* gf     = (const float*)d_in[6];
    const float* bf     = (const float*)d_in[7];
    const float* g_bn   = (const float*)d_in[8];
    const float* b_bn   = (const float*)d_in[9];
    const float* W_q    = (const float*)d_in[10];
    const float* gq     = (const float*)d_in[11];
    const float* bq     = (const float*)d_in[12];
    const float* W_k    = (const float*)d_in[13];
    const float* gk     = (const float*)d_in[14];
    const float* bk     = (const float*)d_in[15];
    const float* W_v    = (const float*)d_in[16];
    const float* gv     = (const float*)d_in[17];
    const float* bv     = (const float*)d_in[18];
    const float* W_fus  = (const float*)d_in[19];
    /* d_in[20] bias_fus: cancels inside BN */
    const float* gfu    = (const float*)d_in[21];
    const float* bfu    = (const float*)d_in[22];
    const float* g_ln   = (const float*)d_in[23];
    const float* b_ln   = (const float*)d_in[24];
    const float* W_mlp  = (const float*)d_in[25];
    const float* b_mlp  = (const float*)d_in[26];
    float* out = (float*)d_out;

    float *p_featv, *p_fp, *p_f2, *p_msc;
    __nv_bfloat16 *p_yh, *p_yl, *p_Oh, *p_Ol, *p_xh, *p_xl;
    __nv_bfloat16 *p_wfush, *p_wfusl, *p_wmh, *p_wml;
    cudaGetSymbolAddress((void**)&p_featv, g_featv);
    cudaGetSymbolAddress((void**)&p_fp,    g_fp);
    cudaGetSymbolAddress((void**)&p_f2,    g_f2);
    cudaGetSymbolAddress((void**)&p_msc,   g_msc);
    cudaGetSymbolAddress((void**)&p_xh,    g_xh);
    cudaGetSymbolAddress((void**)&p_xl,    g_xl);
    cudaGetSymbolAddress((void**)&p_yh,    g_yh);
    cudaGetSymbolAddress((void**)&p_yl,    g_yl);
    cudaGetSymbolAddress((void**)&p_Oh,    g_Oh);
    cudaGetSymbolAddress((void**)&p_Ol,    g_Ol);
    cudaGetSymbolAddress((void**)&p_wfush, g_wfush);
    cudaGetSymbolAddress((void**)&p_wfusl, g_wfusl);
    cudaGetSymbolAddress((void**)&p_wmh,   g_wmh);
    cudaGetSymbolAddress((void**)&p_wml,   g_wml);

    cudaFuncSetAttribute(attn_stats, cudaFuncAttributeMaxDynamicSharedMemorySize, ST_SMEM);
    cudaFuncSetAttribute(attn_flash, cudaFuncAttributeMaxDynamicSharedMemorySize, FL_SMEM);
    cudaFuncSetAttribute(tgemm,      cudaFuncAttributeMaxDynamicSharedMemorySize, TG_SMEM);
    cudaFuncSetAttribute(qkv_gemm,   cudaFuncAttributeMaxDynamicSharedMemorySize, TG_SMEM);
    cudaFuncSetAttribute(feat_gemm,  cudaFuncAttributeMaxDynamicSharedMemorySize, FEAT_SMEM);

    // ---- 0. weight splits
    split_weights<<<1536, 256>>>(W_feat, W_q, W_k, W_v, W_fus, W_mlp);

    // ---- 1. KNN + transpose + geo (max/min + fused stats) + gather
    knn_kernel<<<MTOT, 256>>>(xyz);
    transpose_f<<<dim3(NN/32, CIN/32, BB), dim3(32,8)>>>(f);
    geo_pre<<<NGEOREG, 128>>>(xyz, W_geo);
    gather_feat<<<RTOT*32/256, 256>>>();

    // ---- 2. feat GEMM (fused stats)
    feat_gemm<<<dim3(1, NFEATCTA), 256, FEAT_SMEM>>>();

    // ---- 3. act stats (hierarchical combines) + branch apply
    geo_combine<<<64, 128>>>();
    feat_combine<<<64, 128>>>();
    bn_stats_act<<<1, 256>>>(p_msc + 0*512);
    branch_apply<<<MTOT, 256>>>(p_msc + 0*512, gg, bg, gf, bf);

    // ---- 4. BatchNorm1d -> x split
    bn_stats_partial<<<32, 256>>>(p_featv, MTOT);
    bn_stats_final<<<1, 256>>>(32, MTOT, p_msc + 1*512);
    bn_apply_split<<<MTOT, 256>>>(p_featv, p_msc + 1*512, g_bn, b_bn, 0, p_xh, p_xl);

    // ---- 5. q/k/v merged GEMM + stats + apply
    qkv_gemm<<<dim3(2, MTOT/128, 3), 256, TG_SMEM>>>();
    bn_stats_qkv<<<dim3(64, 3), 256>>>();
    bn_final_qkv<<<3, 256>>>(p_msc);
    bn_apply_qkv<<<dim3(MTOT*CO/256, 3), 256>>>(p_msc, gq, bq, gk, bk, gv, bv);
    vt_convert<<<dim3(NN/32, 2, BB*HEADS), dim3(32,8)>>>();

    // ---- 6. flash attention (two kernels, no prefetch — measured best)
    attn_stats<<<dim3(16, BB*HEADS), 256, ST_SMEM>>>();
    attn_flash<<<dim3(16, BB*HEADS), 256, FL_SMEM>>>();

    // ---- 7. fus + residual
    tgemm<<<dim3(2, MTOT/128), 256, TG_SMEM>>>(p_Oh, p_Ol, p_wfush, p_wfusl,
                                               p_fp, FUSC, FUSC, CO, 7);
    bn_stats_partial<<<32, 256>>>(p_fp, MTOT);
    bn_stats_final<<<1, 256>>>(32, MTOT, p_msc + 5*512);
    bn_apply<<<MTOT, 256>>>(p_fp, p_f2, p_msc + 5*512, gfu, bfu, p_featv, 1);

    // ---- 8. layernorm + mlp + out
    layernorm_kernel<<<MTOT, 256>>>(p_f2, g_ln, b_ln);
    tgemm<<<dim3(2, MTOT/128), 256, TG_SMEM>>>(p_yh, p_yl, p_wmh, p_wml, p_fp, CO, CO, CO, 4);
    final_out<<<dim3(NN/32, CO/32, BB), dim3(32,8)>>>(b_mlp, out);

    (void)in_sizes; (void)n_in; (void)out_size;
}

// round 15
// speedup vs baseline: 1.6270x; 1.0305x over previous
#include <cuda_runtime.h>
#include <cuda_bf16.h>
#include <cfloat>
#include <math.h>
#include <cstdint>

#if defined(__CUDA_ARCH__) && defined(__CUDA_ARCH_FEAT_SM103_ALL)
#define HAS_TC 1
#else
#define HAS_TC 0
#endif

// ---------------- problem constants ----------------
#define BB    4
#define NN    2048
#define KNB   21
#define CIN   64
#define CO    256
#define HEADS 7
#define WCH   64
#define FUSC  (HEADS*WCH)          /* 448 */
#define MTOT  (BB*NN)              /* 8192 */
#define RTOT  (MTOT*KNB)           /* 172032 */
#define EPSB  1e-5f
#define NGEOREG  2048
#define NFEATCTA (RTOT/128)        /* 1344 */

// ---------------- scratch ----------------
__device__ int    g_idx[RTOT];
__device__ float  g_ft[MTOT*CIN];
__device__ float  g_actf[(size_t)RTOT*128];          // feat pre-BN only
__device__ float  g_zmx[MTOT*128];                   // geo pre-BN max over k
__device__ float  g_zmn[MTOT*128];                   // geo pre-BN min over k
__device__ float  g_featv[MTOT*CO];
__device__ float  g_q[MTOT*CO];
__device__ float  g_k[MTOT*CO];
__device__ float  g_v[MTOT*CO];
__device__ float  g_rowstat[BB*HEADS*NN*2];
__device__ float  g_fp[MTOT*CO];
__device__ float  g_f2[MTOT*CO];
__device__ float  g_partf[256*2*CO];
__device__ float  g_msc[6*2*CO];
__device__ float  g_geo_part[(size_t)NGEOREG*256];   // [region]{sum[128]|sq[128]}
__device__ float  g_feat_part[(size_t)NFEATCTA*256];
__device__ float  g_geo_c[64*256];
__device__ float  g_feat_c[64*256];
// bf16 hi/lo splits
__device__ __nv_bfloat16 g_xh[MTOT*CO],  g_xl[MTOT*CO];
__device__ __nv_bfloat16 g_qh[MTOT*CO],  g_ql[MTOT*CO];
__device__ __nv_bfloat16 g_kh[MTOT*CO],  g_kl[MTOT*CO];
__device__ __nv_bfloat16 g_yh[MTOT*CO],  g_yl[MTOT*CO];
__device__ __nv_bfloat16 g_Oh[MTOT*FUSC], g_Ol[MTOT*FUSC];
__device__ __nv_bfloat16 g_vth[(size_t)BB*HEADS*WCH*NN], g_vtl[(size_t)BB*HEADS*WCH*NN];
__device__ __nv_bfloat16 g_wfh[128*128],  g_wfl[128*128];
__device__ __nv_bfloat16 g_wqh[CO*CO],    g_wql[CO*CO];
__device__ __nv_bfloat16 g_wkh[CO*CO],    g_wkl[CO*CO];
__device__ __nv_bfloat16 g_wvh[CO*CO],    g_wvl[CO*CO];
__device__ __nv_bfloat16 g_wfush[CO*FUSC],g_wfusl[CO*FUSC];
__device__ __nv_bfloat16 g_wmh[CO*CO],    g_wml[CO*CO];

// ---------------- helpers ----------------
__device__ __forceinline__ uint32_t smem_u32(const void* p) {
    uint32_t a;
    asm("{ .reg .u64 t; cvta.to.shared.u64 t, %1; cvt.u32.u64 %0, t; }" : "=r"(a) : "l"(p));
    return a;
}
__device__ __forceinline__ uint32_t swz(uint32_t o) { return o ^ ((o >> 3) & 0x70); }
__device__ __forceinline__ uint32_t bpackh(__nv_bfloat16 a, __nv_bfloat16 b) {
    __nv_bfloat162 t = __halves2bfloat162(a, b);
    return *reinterpret_cast<uint32_t*>(&t);
}

#if HAS_TC
__device__ __forceinline__ uint32_t elect_one_pred() {
    uint32_t pred;
    asm volatile("{\n\t.reg .pred p;\n\telect.sync _|p, 0xFFFFFFFF;\n\tselp.b32 %0, 1, 0, p;\n\t}" : "=r"(pred));
    return pred;
}

#define MBARRIER_INIT(addr, cnt) \
    asm volatile("mbarrier.init.shared.b64 [%0], %1;" :: "r"((uint32_t)(addr)), "r"((uint32_t)(cnt)) : "memory")

#define MBARRIER_WAIT_PARITY(mbar_smem_addr, phase_parity) do { \
    uint32_t _mbar = (uint32_t)(mbar_smem_addr); \
    uint32_t _parity = (uint32_t)(phase_parity); \
    uint32_t _done; \
    asm volatile("{\n\t.reg .pred p;\n\t" \
        "mbarrier.try_wait.parity.acquire.cta.shared::cta.b64 p, [%1], %2;\n\t" \
        "selp.b32 %0, 1, 0, p;\n\t}" : "=r"(_done) : "r"(_mbar), "r"(_parity) : "memory"); \
    if (!_done) { \
        asm volatile("{\n\t.reg .pred P1;\n\t" \
            "WAIT_LOOP_%=:\n\t" \
            "mbarrier.try_wait.parity.acquire.cta.shared::cta.b64 P1, [%0], %1, 0x989680;\n\t" \
            "@P1 bra.uni WAIT_DONE_%=;\n\t" \
            "bra.uni WAIT_LOOP_%=;\n\t" \
            "WAIT_DONE_%=:\n\t}" :: "r"(_mbar), "r"(_parity) : "memory"); \
    } \
} while(0)

#define TCGEN05_ALLOC(sm, n) \
    asm volatile("tcgen05.alloc.cta_group::1.sync.aligned.shared::cta.b32 [%0], %1;" \
                 :: "r"((uint32_t)(sm)), "r"((uint32_t)(n)) : "memory")
#define TCGEN05_RELINQ() \
    asm volatile("tcgen05.relinquish_alloc_permit.cta_group::1.sync.aligned;")
#define TCGEN05_DEALLOC(t, n) \
    asm volatile("tcgen05.dealloc.cta_group::1.sync.aligned.b32 %0, %1;" :: "r"(t), "r"(n))
#define TCGEN05_COMMIT(mbar) \
    asm volatile("tcgen05.commit.cta_group::1.mbarrier::arrive::one.shared::cluster.b64 [%0];" \
                 :: "r"((uint32_t)(mbar)) : "memory")
#define TCGEN05_FENCE_AFTER()  asm volatile("tcgen05.fence::after_thread_sync;" ::: "memory")
#define TCGEN05_FENCE_BEFORE() asm volatile("tcgen05.fence::before_thread_sync;" ::: "memory")
#define TCGEN05_WAIT_LD()      asm volatile("tcgen05.wait::ld.sync.aligned;" ::: "memory")
#define FENCE_ASYNC_SHARED()   asm volatile("fence.proxy.async.shared::cta;" ::: "memory")

#define TCGEN05_LD_X32(r, addr) \
    asm volatile("tcgen05.ld.sync.aligned.32x32b.x32.b32 " \
        "{%0, %1, %2, %3, %4, %5, %6, %7, %8, %9, %10, %11, %12, %13, %14, %15, " \
        " %16, %17, %18, %19, %20, %21, %22, %23, %24, %25, %26, %27, %28, %29, %30, %31}, [%32];" \
        : "=r"((r)[0]),  "=r"((r)[1]),  "=r"((r)[2]),  "=r"((r)[3]), \
          "=r"((r)[4]),  "=r"((r)[5]),  "=r"((r)[6]),  "=r"((r)[7]), \
          "=r"((r)[8]),  "=r"((r)[9]),  "=r"((r)[10]), "=r"((r)[11]), \
          "=r"((r)[12]), "=r"((r)[13]), "=r"((r)[14]), "=r"((r)[15]), \
          "=r"((r)[16]), "=r"((r)[17]), "=r"((r)[18]), "=r"((r)[19]), \
          "=r"((r)[20]), "=r"((r)[21]), "=r"((r)[22]), "=r"((r)[23]), \
          "=r"((r)[24]), "=r"((r)[25]), "=r"((r)[26]), "=r"((r)[27]), \
          "=r"((r)[28]), "=r"((r)[29]), "=r"((r)[30]), "=r"((r)[31]) \
        : "r"(addr))

static __device__ __forceinline__ uint64_t make_desc(uint32_t addr) {
    const uint64_t base =
        (uint64_t(2) << 61) | (uint64_t(1) << 46) | (uint64_t(64) << 32) | (uint64_t(1) << 16);
    return base | ((uint64_t)(addr >> 4) & 0x3FFF);
}

__device__ __forceinline__ void mma_f16_ss(uint32_t d, uint64_t a, uint64_t b,
                                           uint32_t idesc, uint32_t en) {
    asm volatile(
        "{\n\t.reg .pred p;\n\tsetp.ne.u32 p, %5, 0;\n\t"
        "tcgen05.mma.cta_group::1.kind::f16 [%0], %1, %2, %3, {%4, %4, %4, %4}, p;\n\t}"
        :: "r"(d), "l"(a), "l"(b), "r"(idesc), "r"(0u), "r"(en) : "memory");
}

#define IDESC_N128 ((1u<<4)|(1u<<7)|(1u<<10)|((128u/8)<<17)|((128u/16)<<24))
#define IDESC_N64  ((1u<<4)|(1u<<7)|(1u<<10)|(( 64u/8)<<17)|((128u/16)<<24))

// ---- tensor-GEMM core (no register prefetch — measured best) ----
__device__ __forceinline__ void tgemm_core(char* sb, uint32_t base,
    const __nv_bfloat16* __restrict__ Ah, const __nv_bfloat16* __restrict__ Al,
    const __nv_bfloat16* __restrict__ Bh, const __nv_bfloat16* __restrict__ Bl,
    float* __restrict__ C, int lda, int ldb, int ldc, int nkc, int m0, int n0)
{
    uint32_t ctrl = base + 65536;
    uint32_t mbar = ctrl + 8;
    int t = threadIdx.x;

    if (t == 0) MBARRIER_INIT(mbar, 1);
    if (t < 32) { TCGEN05_ALLOC(ctrl, 128); TCGEN05_RELINQ(); }
    __syncthreads();
    uint32_t tmem;
    asm volatile("ld.shared.b32 %0, [%1];" : "=r"(tmem) : "r"(ctrl));

    Ah += (size_t)m0 * lda; Al += (size_t)m0 * lda;
    Bh += (size_t)n0 * ldb; Bl += (size_t)n0 * ldb;

    uint64_t dAh = make_desc(base + 0*16384);
    uint64_t dAl = make_desc(base + 1*16384);
    uint64_t dBh = make_desc(base + 2*16384);
    uint64_t dBl = make_desc(base + 3*16384);

    int rb = t >> 4, kq = t & 15;

    for (int kc = 0; kc < nkc; kc++) {
        if (kc > 0) MBARRIER_WAIT_PARITY(mbar, (kc-1) & 1);
        int k0 = kc*64;
#pragma unroll
        for (int i = 0; i < 8; i++) {
            int r = rb + i*16;
            uint32_t so = swz((uint32_t)(r*128 + kq*8));
            *(uint2*)(sb + 0*16384 + so) = *(const uint2*)(Ah + (size_t)r*lda + k0 + kq*4);
            *(uint2*)(sb + 1*16384 + so) = *(const uint2*)(Al + (size_t)r*lda + k0 + kq*4);
            *(uint2*)(sb + 2*16384 + so) = *(const uint2*)(Bh + (size_t)r*ldb + k0 + kq*4);
            *(uint2*)(sb + 3*16384 + so) = *(const uint2*)(Bl + (size_t)r*ldb + k0 + kq*4);
        }
        __syncthreads();
        if (t < 32) {
            if (elect_one_pred()) {
                FENCE_ASYNC_SHARED();
#pragma unroll
                for (int ks = 0; ks < 4; ks++) {
                    uint64_t o = ks*2;
                    mma_f16_ss(tmem, dAh+o, dBh+o, IDESC_N128, (kc > 0 || ks > 0) ? 1u : 0u);
                    mma_f16_ss(tmem, dAh+o, dBl+o, IDESC_N128, 1u);
                    mma_f16_ss(tmem, dAl+o, dBh+o, IDESC_N128, 1u);
                }
                TCGEN05_COMMIT(mbar);
            }
        }
    }
    MBARRIER_WAIT_PARITY(mbar, (nkc-1) & 1);
    TCGEN05_FENCE_AFTER();

    int w = t >> 5, lane = t & 31;
    int sub = w & 3, half = w >> 2;
    float* Crow = C + (size_t)(m0 + sub*32 + lane)*ldc + n0;
#pragma unroll
    for (int gi = 0; gi < 2; gi++) {
        int g = half*2 + gi;
        uint32_t r[32];
        TCGEN05_LD_X32(r, tmem + g*32);
        TCGEN05_WAIT_LD();
        TCGEN05_FENCE_BEFORE();
#pragma unroll
        for (int j = 0; j < 8; j++)
            *(float4*)(Crow + g*32 + j*4) = make_float4(
                __uint_as_float(r[j*4+0]), __uint_as_float(r[j*4+1]),
                __uint_as_float(r[j*4+2]), __uint_as_float(r[j*4+3]));
    }
    __syncthreads();
    if (t < 32) TCGEN05_DEALLOC(tmem, 128);
}
#else
__device__ __forceinline__ void tgemm_core_simt(
    const __nv_bfloat16* Ah, const __nv_bfloat16* Al,
    const __nv_bfloat16* Bh, const __nv_bfloat16* Bl,
    float* C, int lda, int ldb, int ldc, int nkc, int m0, int n0)
{
    int t = threadIdx.x;
    int m = m0 + (t >> 1);
    int nb = (t & 1) * 64;
    for (int n = nb; n < nb + 64; n++) {
        float acc = 0.0f;
        for (int k = 0; k < nkc*64; k++) {
            float a = __bfloat162float(Ah[(size_t)m*lda+k]) + __bfloat162float(Al[(size_t)m*lda+k]);
            float b = __bfloat162float(Bh[(size_t)(n0+n)*ldb+k]) + __bfloat162float(Bl[(size_t)(n0+n)*ldb+k]);
            acc = fmaf(a, b, acc);
        }
        C[(size_t)m*ldc + n0 + n] = acc;
    }
}
#endif // HAS_TC

#define TG_SMEM (1024 + 4*16384 + 64)

// =====================================================================
// KNN
// =====================================================================
__global__ void knn_kernel(const float* __restrict__ xyz)
{
    __shared__ float d2s[NN];
    __shared__ float rv[256];
    __shared__ int   ri[256];
    int m = blockIdx.x;
    int b = m >> 11;
    int t = threadIdx.x;
    const float* base = xyz + (size_t)(b << 11) * 3;

    float qx = xyz[m*3+0], qy = xyz[m*3+1], qz = xyz[m*3+2];
    float sqq = qx*qx + qy*qy + qz*qz;

    for (int j = t; j < NN; j += 256) {
        float px = base[j*3+0], py = base[j*3+1], pz = base[j*3+2];
        float sqp = px*px + py*py + pz*pz;
        float dot = qx*px + qy*py + qz*pz;
        d2s[j] = sqq + sqp - 2.0f*dot;
    }
    __syncthreads();

    for (int it = 0; it < KNB; it++) {
        float bv = FLT_MAX; int bi = 0x3fffffff;
        for (int j = t; j < NN; j += 256) {
            float v = d2s[j];
            if (v < bv) { bv = v; bi = j; }
        }
        rv[t] = bv; ri[t] = bi;
        __syncthreads();
        for (int s = 128; s; s >>= 1) {
            if (t < s) {
                float ov = rv[t+s]; int oi = ri[t+s];
                if (ov < rv[t] || (ov == rv[t] && oi < ri[t])) { rv[t] = ov; ri[t] = oi; }
            }
            __syncthreads();
        }
        if (t == 0) { g_idx[(size_t)m*KNB + it] = ri[0]; d2s[ri[0]] = FLT_MAX; }
        __syncthreads();
    }
}

// =====================================================================
// transpose f
// =====================================================================
__global__ void transpose_f(const float* __restrict__ f)
{
    __shared__ float tile[32][33];
    int b  = blockIdx.z;
    int n0 = blockIdx.x * 32;
    int c0 = blockIdx.y * 32;
    int tx = threadIdx.x, ty = threadIdx.y;
#pragma unroll
    for (int i = 0; i < 32; i += 8)
        tile[ty+i][tx] = f[((size_t)b*CIN + c0 + ty + i)*NN + n0 + tx];
    __syncthreads();
#pragma unroll
    for (int i = 0; i < 32; i += 8)
        g_ft[((size_t)b*NN + n0 + ty + i)*CIN + c0 + tx] = tile[tx][ty+i];
}

// =====================================================================
// geo pre-activation: store only max/min over k + fused stat partials
// =====================================================================
__global__ void geo_pre(const float* __restrict__ xyz, const float* __restrict__ Wg)
{
    __shared__ float nb3[KNB*3];
    int region = blockIdx.x;
    int c = threadIdx.x;
    float w0 = Wg[c*6+0], w1 = Wg[c*6+1], w2 = Wg[c*6+2];
    float w3 = Wg[c*6+3], w4 = Wg[c*6+4], w5 = Wg[c*6+5];
    float s = 0.0f, s2 = 0.0f;

    for (int p = 0; p < 4; p++) {
        int m = region*4 + p;
        int b = m >> 11;
        __syncthreads();
        if (c < KNB) {
            int nb = g_idx[(size_t)m*KNB + c];
            const float* pp = xyz + (size_t)((b << 11) + nb)*3;
            nb3[c*3+0] = pp[0]; nb3[c*3+1] = pp[1]; nb3[c*3+2] = pp[2];
        }
        __syncthreads();
        float cx = xyz[m*3+0], cy = xyz[m*3+1], cz = xyz[m*3+2];
        float base = w0*cx + w1*cy + w2*cz;
        float mx = -FLT_MAX, mn = FLT_MAX;
#pragma unroll 3
        for (int k = 0; k < KNB; k++) {
            float dx = nb3[k*3+0]-cx, dy = nb3[k*3+1]-cy, dz = nb3[k*3+2]-cz;
            float z = base + w3*dx + w4*dy + w5*dz;
            s += z; s2 = fmaf(z, z, s2);
            mx = fmaxf(mx, z); mn = fminf(mn, z);
        }
        g_zmx[(size_t)m*128 + c] = mx;
        g_zmn[(size_t)m*128 + c] = mn;
    }
    g_geo_part[(size_t)region*256 + c]       = s;
    g_geo_part[(size_t)region*256 + 128 + c] = s2;
}

// merged partial combine: blocks 0..63 geo (32 regions each),
// blocks 64..127 feat (21 tiles each)
__global__ void act_combine()
{
    int c = threadIdx.x;
    int blk = blockIdx.x;
    float s = 0.0f, s2 = 0.0f;
    if (blk < 64) {
        for (int r = blk*32; r < blk*32 + 32; r++) {
            s  += g_geo_part[(size_t)r*256 + c];
            s2 += g_geo_part[(size_t)r*256 + 128 + c];
        }
        g_geo_c[blk*256 + c]       = s;
        g_geo_c[blk*256 + 128 + c] = s2;
    } else {
        int fb = blk - 64;
        for (int r = fb*21; r < fb*21 + 21; r++) {
            s  += g_feat_part[(size_t)r*256 + c];
            s2 += g_feat_part[(size_t)r*256 + 128 + c];
        }
        g_feat_c[fb*256 + c]       = s;
        g_feat_c[fb*256 + 128 + c] = s2;
    }
}

// final act stats combine (double, fixed order)
__global__ void bn_stats_act(float* msc)
{
    int c = threadIdx.x;
    double s = 0.0, s2 = 0.0;
    if (c < 128) {
        for (int r = 0; r < 64; r++) {
            s  += (double)g_geo_c[r*256 + c];
            s2 += (double)g_geo_c[r*256 + 128 + c];
        }
    } else {
        int cc = c - 128;
        for (int r = 0; r < 64; r++) {
            s  += (double)g_feat_c[r*256 + cc];
            s2 += (double)g_feat_c[r*256 + 128 + cc];
        }
    }
    double mean = s / (double)RTOT;
    double var  = s2 / (double)RTOT - mean*mean;
    msc[c]      = (float)mean;
    msc[CO + c] = (float)(1.0 / sqrt(var + (double)EPSB));
}

// =====================================================================
// feat GEMM with INLINE gather+split (g_ft is L2-resident, 2MB)
// + fused stat partials. grid (1, NFEATCTA), 256 threads.
// A row R=m0+r: chunk0 = ft[neighbor(R)], chunk1 = ft[center(R)]
// =====================================================================
#define FEAT_SMEM (1024 + 69632 + 64)

__global__ void __launch_bounds__(256, 1)
feat_gemm()
{
#if HAS_TC
    extern __shared__ char sm[];
    uint32_t raw = smem_u32(sm);
    uint32_t base = (raw + 1023) & ~1023u;
    char* sb = sm + (base - raw);
    uint32_t ctrl = base + 69632;
    uint32_t mbar = ctrl + 8;
    int t = threadIdx.x;
    int m0 = blockIdx.y * 128;

    if (t == 0) MBARRIER_INIT(mbar, 1);
    if (t < 32) { TCGEN05_ALLOC(ctrl, 128); TCGEN05_RELINQ(); }
    __syncthreads();
    uint32_t tmem;
    asm volatile("ld.shared.b32 %0, [%1];" : "=r"(tmem) : "r"(ctrl));

    uint64_t dAh = make_desc(base + 0*16384);
    uint64_t dAl = make_desc(base + 1*16384);
    uint64_t dBh = make_desc(base + 2*16384);
    uint64_t dBl = make_desc(base + 3*16384);

    int rb = t >> 4, kq = t & 15;
    for (int kc = 0; kc < 2; kc++) {
        if (kc > 0) MBARRIER_WAIT_PARITY(mbar, 0);
        int k0 = kc*64;
#pragma unroll
        for (int i = 0; i < 8; i++) {
            int r = rb + i*16;
            uint32_t R = (uint32_t)(m0 + r);
            uint32_t m = R / KNB;
            uint32_t b = m >> 11;
            const float* src;
            if (kc == 0) {
                uint32_t nb = (uint32_t)g_idx[R];
                src = g_ft + (size_t)((b << 11) + nb)*CIN + kq*4;
            } else {
                src = g_ft + (size_t)m*CIN + kq*4;
            }
            float4 v = *(const float4*)src;
            __nv_bfloat16 h0 = __float2bfloat16(v.x);
            __nv_bfloat16 h1 = __float2bfloat16(v.y);
            __nv_bfloat16 h2 = __float2bfloat16(v.z);
            __nv_bfloat16 h3 = __float2bfloat16(v.w);
            uint32_t so = swz((uint32_t)(r*128 + kq*8));
            *(uint2*)(sb + 0*16384 + so) = make_uint2(bpackh(h0,h1), bpackh(h2,h3));
            *(uint2*)(sb + 1*16384 + so) = make_uint2(
                bpackh(__float2bfloat16(v.x - __bfloat162float(h0)),
                       __float2bfloat16(v.y - __bfloat162float(h1))),
                bpackh(__float2bfloat16(v.z - __bfloat162float(h2)),
                       __float2bfloat16(v.w - __bfloat162float(h3))));
            *(uint2*)(sb + 2*16384 + so) = *(const uint2*)(g_wfh + (size_t)r*128 + k0 + kq*4);
            *(uint2*)(sb + 3*16384 + so) = *(const uint2*)(g_wfl + (size_t)r*128 + k0 + kq*4);
        }
        __syncthreads();
        if (t < 32) {
            if (elect_one_pred()) {
                FENCE_ASYNC_SHARED();
#pragma unroll
                for (int ks = 0; ks < 4; ks++) {
                    uint64_t o = ks*2;
                    mma_f16_ss(tmem, dAh+o, dBh+o, IDESC_N128, (kc > 0 || ks > 0) ? 1u : 0u);
                    mma_f16_ss(tmem, dAh+o, dBl+o, IDESC_N128, 1u);
                    mma_f16_ss(tmem, dAl+o, dBh+o, IDESC_N128, 1u);
                }
                TCGEN05_COMMIT(mbar);
            }
        }
    }
    MBARRIER_WAIT_PARITY(mbar, 1);
    TCGEN05_FENCE_AFTER();

    int w = t >> 5, lane = t & 31;
    int sub = w & 3, half = w >> 2;
    int row = sub*32 + lane;
    float* Crow = g_actf + (size_t)(m0 + row)*128;
    float* stile = (float*)sb;   // [128][132], inputs dead now
#pragma unroll
    for (int gi = 0; gi < 2; gi++) {
        int g = half*2 + gi;
        uint32_t r[32];
        TCGEN05_LD_X32(r, tmem + g*32);
        TCGEN05_WAIT_LD();
        TCGEN05_FENCE_BEFORE();
#pragma unroll
        for (int j = 0; j < 8; j++) {
            float4 v = make_float4(
                __uint_as_float(r[j*4+0]), __uint_as_float(r[j*4+1]),
                __uint_as_float(r[j*4+2]), __uint_as_float(r[j*4+3]));
            *(float4*)(Crow + g*32 + j*4) = v;
            *(float4*)(stile + row*132 + g*32 + j*4) = v;
        }
    }
    __syncthreads();
    if (t < 128) {
        float a0=0,a1=0, q0=0,q1=0;
        for (int rr = 0; rr < 128; rr += 2) {
            float v0 = stile[rr*132 + t], v1 = stile[(rr+1)*132 + t];
            a0 += v0; q0 = fmaf(v0,v0,q0);
            a1 += v1; q1 = fmaf(v1,v1,q1);
        }
        g_feat_part[(size_t)blockIdx.y*256 + t]       = a0 + a1;
        g_feat_part[(size_t)blockIdx.y*256 + 128 + t] = q0 + q1;
    }
    __syncthreads();
    if (t < 32) TCGEN05_DEALLOC(tmem, 128);
#else
    int t = threadIdx.x;
    int m0 = blockIdx.y*128;
    int r = t >> 1;
    int R = m0 + r;
    int m = R / KNB;
    int b = m >> 11;
    int nbr = g_idx[R];
    int nb0 = (t & 1) * 64;
    for (int n = nb0; n < nb0 + 64; n++) {
        float acc = 0.0f;
        for (int k = 0; k < 128; k++) {
            float a = (k < 64) ? g_ft[(size_t)((b<<11)+nbr)*CIN + k]
                               : g_ft[(size_t)m*CIN + (k-64)];
            float bw = __bfloat162float(g_wfh[(size_t)n*128+k]) + __bfloat162float(g_wfl[(size_t)n*128+k]);
            acc = fmaf(a, bw, acc);
        }
        g_actf[(size_t)R*128 + n] = acc;
    }
    __syncthreads();
    if (t < 128) {
        float s = 0, q = 0;
        for (int rr = 0; rr < 128; rr++) {
            float v = g_actf[(size_t)(m0+rr)*128 + t];
            s += v; q = fmaf(v,v,q);
        }
        g_feat_part[(size_t)blockIdx.y*256 + t] = s;
        g_feat_part[(size_t)blockIdx.y*256 + 128 + t] = q;
    }
#endif
}

// =====================================================================
// tensor GEMM wrappers
// =====================================================================
__global__ void __launch_bounds__(256, 1)
tgemm(const __nv_bfloat16* __restrict__ Ah, const __nv_bfloat16* __restrict__ Al,
      const __nv_bfloat16* __restrict__ Bh, const __nv_bfloat16* __restrict__ Bl,
      float* __restrict__ C, int lda, int ldb, int ldc, int nkc)
{
#if HAS_TC
    extern __shared__ char sm[];
    uint32_t raw = smem_u32(sm);
    uint32_t base = (raw + 1023) & ~1023u;
    tgemm_core(sm + (base - raw), base, Ah, Al, Bh, Bl, C, lda, ldb, ldc, nkc,
               blockIdx.y*128, blockIdx.x*128);
#else
    tgemm_core_simt(Ah, Al, Bh, Bl, C, lda, ldb, ldc, nkc, blockIdx.y*128, blockIdx.x*128);
#endif
}

__global__ void __launch_bounds__(256, 1)
qkv_gemm()
{
    int z = blockIdx.z;
    const __nv_bfloat16* Bh = (z==0) ? g_wqh : (z==1) ? g_wkh : g_wvh;
    const __nv_bfloat16* Bl = (z==0) ? g_wql : (z==1) ? g_wkl : g_wvl;
    float* C = (z==0) ? g_q : (z==1) ? g_k : g_v;
#if HAS_TC
    extern __shared__ char sm[];
    uint32_t raw = smem_u32(sm);
    uint32_t base = (raw + 1023) & ~1023u;
    tgemm_core(sm + (base - raw), base, g_xh, g_xl, Bh, Bl, C, CO, CO, CO, 4,
               blockIdx.y*128, blockIdx.x*128);
#else
    tgemm_core_simt(g_xh, g_xl, Bh, Bl, C, CO, CO, CO, 4, blockIdx.y*128, blockIdx.x*128);
#endif
}

// =====================================================================
// BN stats (fp32 partials, double combine) — small tensors
// =====================================================================
__device__ __forceinline__ void bn_partial_region(const float* X, long rows,
                                                  int nblk, int blk, int region)
{
    int c = threadIdx.x;
    long per = (rows + nblk - 1) / nblk;
    long r0 = (long)blk * per;
    long r1 = r0 + per; if (r1 > rows) r1 = rows;
    float a0=0,a1=0,a2=0,a3=0, q0=0,q1=0,q2=0,q3=0;
    long r = r0;
    for (; r + 4 <= r1; r += 4) {
        float v0 = X[(r+0)*CO + c], v1 = X[(r+1)*CO + c];
        float v2 = X[(r+2)*CO + c], v3 = X[(r+3)*CO + c];
        a0 += v0; q0 = fmaf(v0,v0,q0);
        a1 += v1; q1 = fmaf(v1,v1,q1);
        a2 += v2; q2 = fmaf(v2,v2,q2);
        a3 += v3; q3 = fmaf(v3,v3,q3);
    }
    for (; r < r1; r++) { float v = X[r*CO + c]; a0 += v; q0 = fmaf(v,v,q0); }
    g_partf[((size_t)region*2 + 0)*CO + c] = (a0+a1) + (a2+a3);
    g_partf[((size_t)region*2 + 1)*CO + c] = (q0+q1) + (q2+q3);
}

__global__ void bn_stats_partial(const float* __restrict__ X, long rows)
{
    bn_partial_region(X, rows, gridDim.x, blockIdx.x, blockIdx.x);
}

__global__ void bn_stats_final(int nblocks, long rows, float* msc)
{
    int c = threadIdx.x;
    double s = 0.0, s2 = 0.0;
    for (int i = 0; i < nblocks; i++) {
        s  += (double)g_partf[((size_t)i*2 + 0)*CO + c];
        s2 += (double)g_partf[((size_t)i*2 + 1)*CO + c];
    }
    double mean = s / (double)rows;
    double var  = s2 / (double)rows - mean*mean;
    msc[c]      = (float)mean;
    msc[CO + c] = (float)(1.0 / sqrt(var + (double)EPSB));
}

__global__ void bn_stats_qkv()
{
    const float* X = (blockIdx.y==0) ? g_q : (blockIdx.y==1) ? g_k : g_v;
    bn_partial_region(X, MTOT, 64, blockIdx.x, blockIdx.y*64 + blockIdx.x);
}
__global__ void bn_final_qkv(float* msc)
{
    int y = blockIdx.x;
    int c = threadIdx.x;
    double s = 0.0, s2 = 0.0;
    for (int i = y*64; i < y*64 + 64; i++) {
        s  += (double)g_partf[((size_t)i*2 + 0)*CO + c];
        s2 += (double)g_partf[((size_t)i*2 + 1)*CO + c];
    }
    double mean = s / (double)MTOT;
    double var  = s2 / (double)MTOT - mean*mean;
    msc[(2+y)*512 + c]      = (float)mean;
    msc[(2+y)*512 + CO + c] = (float)(1.0 / sqrt(var + (double)EPSB));
}

// =====================================================================
// branch BN + relu + maxpool
// =====================================================================
__global__ void branch_apply(const float* msc,
                             const float* __restrict__ g_geo, const float* __restrict__ b_geo,
                             const float* __restrict__ g_fea, const float* __restrict__ b_fea)
{
    int m = blockIdx.x;
    int c = threadIdx.x;
    float mean = msc[c], istd = msc[CO + c];
    float ga = (c < 128) ? g_geo[c] : g_fea[c - 128];
    float be = (c < 128) ? b_geo[c] : b_fea[c - 128];
    float sc = istd * ga;
    float best;
    if (c < 128) {
        float zv = (sc >= 0.0f) ? g_zmx[(size_t)m*128 + c] : g_zmn[(size_t)m*128 + c];
        best = fmaxf((zv - mean) * sc + be, 0.0f);
    } else {
        best = -FLT_MAX;
        const float* basep = g_actf + (size_t)m*KNB*128 + (c - 128);
#pragma unroll 3
        for (int k = 0; k < KNB; k++) {
            float y = fmaxf((basep[(size_t)k*128] - mean) * sc + be, 0.0f);
            best = fmaxf(best, y);
        }
    }
    g_featv[(size_t)m*CO + c] = best;
}

// =====================================================================
// BN apply variants
// =====================================================================
__global__ void bn_apply(const float* __restrict__ in, float* __restrict__ out,
                         const float* msc,
                         const float* __restrict__ gamma, const float* __restrict__ beta,
                         const float* __restrict__ res, int do_relu)
{
    size_t i = (size_t)blockIdx.x * blockDim.x + threadIdx.x;
    int c = (int)(i & (CO-1));
    float y = (in[i] - msc[c]) * msc[CO + c] * gamma[c] + beta[c];
    if (do_relu) y = fmaxf(y, 0.0f);
    if (res) y += res[i];
    out[i] = y;
}

__global__ void bn_apply_split(const float* __restrict__ in,
                               const float* msc,
                               const float* __restrict__ gamma, const float* __restrict__ beta,
                               int do_relu,
                               __nv_bfloat16* __restrict__ oh, __nv_bfloat16* __restrict__ ol)
{
    size_t i = (size_t)blockIdx.x * blockDim.x + threadIdx.x;
    int c = (int)(i & (CO-1));
    float y = (in[i] - msc[c]) * msc[CO + c] * gamma[c] + beta[c];
    if (do_relu) y = fmaxf(y, 0.0f);
    __nv_bfloat16 hb = __float2bfloat16(y);
    oh[i] = hb;
    ol[i] = __float2bfloat16(y - __bfloat162float(hb));
}

__global__ void bn_apply_qkv(const float* msc,
                             const float* __restrict__ gq, const float* __restrict__ bq,
                             const float* __restrict__ gk, const float* __restrict__ bk,
                             const float* __restrict__ gv, const float* __restrict__ bv)
{
    int y = blockIdx.y;
    size_t i = (size_t)blockIdx.x * 256 + threadIdx.x;
    int c = (int)(i & (CO-1));
    const float* in = (y==0) ? g_q : (y==1) ? g_k : g_v;
    const float* ga = (y==0) ? gq : (y==1) ? gk : gv;
    const float* be = (y==0) ? bq : (y==1) ? bk : bv;
    const float* ms = msc + (2+y)*512;
    float v = fmaxf((in[i] - ms[c]) * ms[CO + c] * ga[c] + be[c], 0.0f);
    if (y == 2) { g_v[i] = v; return; }
    __nv_bfloat16 hb = __float2bfloat16(v);
    __nv_bfloat16 lb = __float2bfloat16(v - __bfloat162float(hb));
    if (y == 0) { g_qh[i] = hb; g_ql[i] = lb; }
    else        { g_kh[i] = hb; g_kl[i] = lb; }
}

// =====================================================================
// fused weight splits
// =====================================================================
__global__ void split_weights(const float* __restrict__ Wf, const float* __restrict__ Wq,
                              const float* __restrict__ Wk, const float* __restrict__ Wv,
                              const float* __restrict__ Wfus, const float* __restrict__ Wm)
{
    int i = blockIdx.x*256 + threadIdx.x;
    const float* src; __nv_bfloat16 *dh, *dl; int off;
    if      (i < 16384)  { src = Wf;   dh = g_wfh;   dl = g_wfl;   off = i; }
    else if (i < 81920)  { src = Wq;   dh = g_wqh;   dl = g_wql;   off = i - 16384; }
    else if (i < 147456) { src = Wk;   dh = g_wkh;   dl = g_wkl;   off = i - 81920; }
    else if (i < 212992) { src = Wv;   dh = g_wvh;   dl = g_wvl;   off = i - 147456; }
    else if (i < 327680) { src = Wfus; dh = g_wfush; dl = g_wfusl; off = i - 212992; }
    else                 { src = Wm;   dh = g_wmh;   dl = g_wml;   off = i - 327680; }
    float v = src[off];
    __nv_bfloat16 hb = __float2bfloat16(v);
    dh[off] = hb;
    dl[off] = __float2bfloat16(v - __bfloat162float(hb));
}

// =====================================================================
// v -> per-head transposed bf16 split
// =====================================================================
__global__ void vt_convert()
{
    __shared__ float tile[32][33];
    int z  = blockIdx.z;
    int b  = z / HEADS, h = z - b*HEADS;
    int m0 = blockIdx.x * 32;
    int c0 = blockIdx.y * 32;
    int tx = threadIdx.x, ty = threadIdx.y;
#pragma unroll
    for (int i = 0; i < 32; i += 8)
        tile[ty+i][tx] = g_v[((size_t)(b*NN) + m0 + ty + i)*CO + h*32 + c0 + tx];
    __syncthreads();
#pragma unroll
    for (int i = 0; i < 32; i += 8) {
        int c = c0 + ty + i, m = m0 + tx;
        float v = tile[tx][ty+i];
        __nv_bfloat16 hb = __float2bfloat16(v);
        size_t o = (size_t)z*WCH*NN + (size_t)c*NN + m;
        g_vth[o] = hb;
        g_vtl[o] = __float2bfloat16(v - __bfloat162float(hb));
    }
}

// =====================================================================
// FLASH pass 1: per-row softmax stats
// grid (16 m-tiles, 28 z), 256 threads.
// =====================================================================
#define ST_SMEM (1024 + 65536 + 64 + 1088)

__global__ void __launch_bounds__(256, 1)
attn_stats()
{
#if HAS_TC
    extern __shared__ char sm[];
    uint32_t raw = smem_u32(sm);
    uint32_t base = (raw + 1023) & ~1023u;
    char* sb = sm + (base - raw);
    uint32_t ctrl = base + 65536;
    uint32_t mbar = ctrl + 8;
    float* mrg = (float*)(sb + 65536 + 64);   // 128 x {mx,sum}

    int t = threadIdx.x;
    int z = blockIdx.y;
    int b = z / HEADS, h = z - b*HEADS;
    int m0 = blockIdx.x * 128;

    if (t == 0) MBARRIER_INIT(mbar, 1);
    if (t < 32) { TCGEN05_ALLOC(ctrl, 128); TCGEN05_RELINQ(); }
    __syncthreads();
    uint32_t tmem;
    asm volatile("ld.shared.b32 %0, [%1];" : "=r"(tmem) : "r"(ctrl));

    const __nv_bfloat16* pQh = g_qh + ((size_t)(b*NN) + m0)*CO + h*32;
    const __nv_bfloat16* pQl = g_ql + ((size_t)(b*NN) + m0)*CO + h*32;
    const __nv_bfloat16* pKh = g_kh + ((size_t)b*NN)*CO + h*32;
    const __nv_bfloat16* pKl = g_kl + ((size_t)b*NN)*CO + h*32;

    int rb = t >> 4, kq = t & 15;
#pragma unroll
    for (int i = 0; i < 8; i++) {
        int r = rb + i*16;
        uint32_t so = swz((uint32_t)(r*128 + kq*8));
        *(uint2*)(sb + 0*16384 + so) = *(const uint2*)(pQh + (size_t)r*CO + kq*4);
        *(uint2*)(sb + 1*16384 + so) = *(const uint2*)(pQl + (size_t)r*CO + kq*4);
    }

    uint64_t dQh = make_desc(base + 0*16384);
    uint64_t dQl = make_desc(base + 1*16384);
    uint64_t dKh = make_desc(base + 2*16384);
    uint64_t dKl = make_desc(base + 3*16384);

    int w = t >> 5, lane = t & 31;
    int sub = w & 3, half = w >> 2;
    int rrow = sub*32 + lane;

    float mx = -FLT_MAX, sum = 0.0f;

    for (int nc = 0; nc < 16; nc++) {
        int n0 = nc*128;
#pragma unroll
        for (int i = 0; i < 8; i++) {
            int r = rb + i*16;
            uint32_t so = swz((uint32_t)(r*128 + kq*8));
            *(uint2*)(sb + 2*16384 + so) = *(const uint2*)(pKh + (size_t)(n0+r)*CO + kq*4);
            *(uint2*)(sb + 3*16384 + so) = *(const uint2*)(pKl + (size_t)(n0+r)*CO + kq*4);
        }
        __syncthreads();
        if (t < 32) {
            if (elect_one_pred()) {
                FENCE_ASYNC_SHARED();
#pragma unroll
                for (int ks = 0; ks < 4; ks++) {
                    uint64_t o = ks*2;
                    mma_f16_ss(tmem, dQh+o, dKh+o, IDESC_N128, (ks > 0) ? 1u : 0u);
                    mma_f16_ss(tmem, dQh+o, dKl+o, IDESC_N128, 1u);
                    mma_f16_ss(tmem, dQl+o, dKh+o, IDESC_N128, 1u);
                }
                TCGEN05_COMMIT(mbar);
            }
        }
        MBARRIER_WAIT_PARITY(mbar, nc & 1);
        TCGEN05_FENCE_AFTER();
#pragma unroll
        for (int gi = 0; gi < 2; gi++) {
            int g = half*2 + gi;
            uint32_t r[32];
            TCGEN05_LD_X32(r, tmem + g*32);
            TCGEN05_WAIT_LD();
            float gm = -FLT_MAX;
#pragma unroll
            for (int j = 0; j < 32; j++) gm = fmaxf(gm, __uint_as_float(r[j]));
            float gs = 0.0f;
#pragma unroll
            for (int j = 0; j < 32; j++) gs += __expf(__uint_as_float(r[j]) - gm);
            if (gm <= mx) sum += gs * __expf(gm - mx);
            else { sum = sum * __expf(mx - gm) + gs; mx = gm; }
        }
        __syncthreads();   // all LDTMs done before next MMA overwrites S
    }

    if (half == 0) { mrg[rrow*2] = mx; mrg[rrow*2+1] = sum; }
    __syncthreads();
    if (half == 1) {
        float m2 = mrg[rrow*2], s2 = mrg[rrow*2+1];
        float M = fmaxf(mx, m2);
        float S = s2 * __expf(m2 - M) + sum * __expf(mx - M);
        size_t row = (size_t)z*NN + m0 + rrow;
        g_rowstat[row*2]   = M;
        g_rowstat[row*2+1] = 1.0f / S;
    }
    __syncthreads();
    if (t < 32) TCGEN05_DEALLOC(tmem, 128);
#else
    int t = threadIdx.x;
    int z = blockIdx.y;
    int b = z / HEADS, h = z - b*HEADS;
    int m0 = blockIdx.x * 128;
    if (t >= 128) return;
    int m = m0 + t;
    const float* qp = g_q + ((size_t)(b*NN) + m)*CO + h*32;
    float mx = -FLT_MAX;
    for (int n = 0; n < NN; n++) {
        const float* kp = g_k + ((size_t)(b*NN) + n)*CO + h*32;
        float acc = 0.0f;
        for (int k = 0; k < 64; k++) acc = fmaf(qp[k], kp[k], acc);
        mx = fmaxf(mx, acc);
    }
    float sum = 0.0f;
    for (int n = 0; n < NN; n++) {
        const float* kp = g_k + ((size_t)(b*NN) + n)*CO + h*32;
        float acc = 0.0f;
        for (int k = 0; k < 64; k++) acc = fmaf(qp[k], kp[k], acc);
        sum += __expf(acc - mx);
    }
    size_t row = (size_t)z*NN + m;
    g_rowstat[row*2] = mx; g_rowstat[row*2+1] = 1.0f / sum;
#endif
}

// =====================================================================
// FLASH pass 2: recompute S, softmax, P·V in TMEM
// grid (16 m-tiles, 28 z), 256 threads.
// TMEM: S cols 0..127, O cols 128..191 (alloc 256)
// =====================================================================
#define FL_SMEM (1024 + 163840 + 64 + 1088)

__global__ void __launch_bounds__(256, 1)
attn_flash()
{
#if HAS_TC
    extern __shared__ char sm[];
    uint32_t raw = smem_u32(sm);
    uint32_t base = (raw + 1023) & ~1023u;
    char* sb = sm + (base - raw);
    const uint32_t off_Qh = 0, off_Ql = 16384, off_Kh = 32768, off_Kl = 49152;
    const uint32_t off_Vh = 65536, off_Vl = 81920, off_Ph = 98304, off_Pl = 131072;
    uint32_t ctrl = base + 163840;
    uint32_t mbar_s = ctrl + 8;
    uint32_t mbar_o = ctrl + 16;
    float* sst = (float*)(sb + 163840 + 64);

    int t = threadIdx.x;
    int z = blockIdx.y;
    int b = z / HEADS, h = z - b*HEADS;
    int m0 = blockIdx.x * 128;

    if (t == 0) { MBARRIER_INIT(mbar_s, 1); MBARRIER_INIT(mbar_o, 1); }
    if (t < 32) { TCGEN05_ALLOC(ctrl, 256); TCGEN05_RELINQ(); }
    sst[t] = g_rowstat[(size_t)(z*NN + m0)*2 + t];
    __syncthreads();
    uint32_t tmem;
    asm volatile("ld.shared.b32 %0, [%1];" : "=r"(tmem) : "r"(ctrl));
    uint32_t tmemO = tmem + 128;

    const __nv_bfloat16* pQh = g_qh + ((size_t)(b*NN) + m0)*CO + h*32;
    const __nv_bfloat16* pQl = g_ql + ((size_t)(b*NN) + m0)*CO + h*32;
    const __nv_bfloat16* pKh = g_kh + ((size_t)b*NN)*CO + h*32;
    const __nv_bfloat16* pKl = g_kl + ((size_t)b*NN)*CO + h*32;
    const __nv_bfloat16* Vh = g_vth + (size_t)z*WCH*NN;
    const __nv_bfloat16* Vl = g_vtl + (size_t)z*WCH*NN;

    int rb = t >> 4, kq = t & 15;
#pragma unroll
    for (int i = 0; i < 8; i++) {
        int r = rb + i*16;
        uint32_t so = swz((uint32_t)(r*128 + kq*8));
        *(uint2*)(sb + off_Qh + so) = *(const uint2*)(pQh + (size_t)r*CO + kq*4);
        *(uint2*)(sb + off_Ql + so) = *(const uint2*)(pQl + (size_t)r*CO + kq*4);
    }

    uint64_t dQh = make_desc(base + off_Qh);
    uint64_t dQl = make_desc(base + off_Ql);
    uint64_t dKh = make_desc(base + off_Kh);
    uint64_t dKl = make_desc(base + off_Kl);

    int w = t >> 5, lane = t & 31;
    int sub = w & 3, half = w >> 2;
    int rrow = sub*32 + lane;
    float mxr = sst[rrow*2], invr = sst[rrow*2+1];

    for (int nc = 0; nc < 16; nc++) {
        int n0 = nc*128;
        if (nc > 0) MBARRIER_WAIT_PARITY(mbar_o, (nc-1) & 1);

#pragma unroll
        for (int i = 0; i < 8; i++) {
            int r = rb + i*16;
            uint32_t so = swz((uint32_t)(r*128 + kq*8));
            *(uint2*)(sb + off_Kh + so) = *(const uint2*)(pKh + (size_t)(n0+r)*CO + kq*4);
            *(uint2*)(sb + off_Kl + so) = *(const uint2*)(pKl + (size_t)(n0+r)*CO + kq*4);
        }
#pragma unroll
        for (int i = 0; i < 4; i++) {
            int r = rb + i*16;
            uint32_t so = swz((uint32_t)(r*128 + kq*8));
#pragma unroll
            for (int j = 0; j < 2; j++) {
                size_t gk = (size_t)r*NN + n0 + j*64 + kq*4;
                *(uint2*)(sb + off_Vh + j*8192 + so) = *(const uint2*)(Vh + gk);
                *(uint2*)(sb + off_Vl + j*8192 + so) = *(const uint2*)(Vl + gk);
            }
        }
        __syncthreads();

        // S = Q K^T (fresh accumulator each chunk)
        if (t < 32) {
            if (elect_one_pred()) {
                FENCE_ASYNC_SHARED();
#pragma unroll
                for (int ks = 0; ks < 4; ks++) {
                    uint64_t o = ks*2;
                    mma_f16_ss(tmem, dQh+o, dKh+o, IDESC_N128, (ks > 0) ? 1u : 0u);
                    mma_f16_ss(tmem, dQh+o, dKl+o, IDESC_N128, 1u);
                    mma_f16_ss(tmem, dQl+o, dKh+o, IDESC_N128, 1u);
                }
                TCGEN05_COMMIT(mbar_s);
            }
        }
        MBARRIER_WAIT_PARITY(mbar_s, nc & 1);
        TCGEN05_FENCE_AFTER();

#pragma unroll
        for (int gi = 0; gi < 2; gi++) {
            int g = half*2 + gi;
            uint32_t r[32];
            TCGEN05_LD_X32(r, tmem + g*32);
            TCGEN05_WAIT_LD();
#pragma unroll
            for (int j = 0; j < 8; j++) {
                float v0 = __expf(__uint_as_float(r[j*4+0]) - mxr) * invr;
                float v1 = __expf(__uint_as_float(r[j*4+1]) - mxr) * invr;
                float v2 = __expf(__uint_as_float(r[j*4+2]) - mxr) * invr;
                float v3 = __expf(__uint_as_float(r[j*4+3]) - mxr) * invr;
                __nv_bfloat16 h0 = __float2bfloat16(v0);
                __nv_bfloat16 h1 = __float2bfloat16(v1);
                __nv_bfloat16 h2 = __float2bfloat16(v2);
                __nv_bfloat16 h3 = __float2bfloat16(v3);
                uint32_t so = swz((uint32_t)(rrow*128 + (gi*32 + j*4)*2));
                *(uint2*)(sb + off_Ph + half*16384 + so) = make_uint2(bpackh(h0,h1), bpackh(h2,h3));
                *(uint2*)(sb + off_Pl + half*16384 + so) = make_uint2(
                    bpackh(__float2bfloat16(v0 - __bfloat162float(h0)),
                           __float2bfloat16(v1 - __bfloat162float(h1))),
                    bpackh(__float2bfloat16(v2 - __bfloat162float(h2)),
                           __float2bfloat16(v3 - __bfloat162float(h3))));
            }
        }
        __syncthreads();

        // O += P V^T
        if (t < 32) {
            if (elect_one_pred()) {
                FENCE_ASYNC_SHARED();
#pragma unroll
                for (int kch = 0; kch < 2; kch++) {
                    uint64_t dPh = make_desc(base + off_Ph + kch*16384);
                    uint64_t dPl = make_desc(base + off_Pl + kch*16384);
                    uint64_t dVh2 = make_desc(base + off_Vh + kch*8192);
                    uint64_t dVl2 = make_desc(base + off_Vl + kch*8192);
#pragma unroll
                    for (int ks = 0; ks < 4; ks++) {
                        uint64_t o = ks*2;
                        mma_f16_ss(tmemO, dPh+o, dVh2+o, IDESC_N64,
                                   (nc > 0 || kch > 0 || ks > 0) ? 1u : 0u);
                        mma_f16_ss(tmemO, dPh+o, dVl2+o, IDESC_N64, 1u);
                        mma_f16_ss(tmemO, dPl+o, dVh2+o, IDESC_N64, 1u);
                    }
                }
                TCGEN05_COMMIT(mbar_o);
            }
        }
    }
    MBARRIER_WAIT_PARITY(mbar_o, 1);
    TCGEN05_FENCE_AFTER();

    size_t rbase = (size_t)(b*NN + m0 + rrow)*FUSC + h*64 + half*32;
    {
        uint32_t r[32];
        TCGEN05_LD_X32(r, tmemO + half*32);
        TCGEN05_WAIT_LD();
        TCGEN05_FENCE_BEFORE();
#pragma unroll
        for (int j = 0; j < 8; j++) {
            float v0 = __uint_as_float(r[j*4+0]);
            float v1 = __uint_as_float(r[j*4+1]);
            float v2 = __uint_as_float(r[j*4+2]);
            float v3 = __uint_as_float(r[j*4+3]);
            __nv_bfloat16 h0 = __float2bfloat16(v0);
            __nv_bfloat16 h1 = __float2bfloat16(v1);
            __nv_bfloat16 h2 = __float2bfloat16(v2);
            __nv_bfloat16 h3 = __float2bfloat16(v3);
            *(uint2*)(g_Oh + rbase + j*4) = make_uint2(bpackh(h0,h1), bpackh(h2,h3));
            *(uint2*)(g_Ol + rbase + j*4) = make_uint2(
                bpackh(__float2bfloat16(v0 - __bfloat162float(h0)),
                       __float2bfloat16(v1 - __bfloat162float(h1))),
                bpackh(__float2bfloat16(v2 - __bfloat162float(h2)),
                       __float2bfloat16(v3 - __bfloat162float(h3))));
        }
    }
    __syncthreads();
    if (t < 32) TCGEN05_DEALLOC(tmem, 256);
#else
    int t = threadIdx.x;
    int z = blockIdx.y;
    int b = z / HEADS, h = z - b*HEADS;
    int m0 = blockIdx.x * 128;
    if (t >= 128) return;
    int m = m0 + t;
    const float* qp = g_q + ((size_t)(b*NN) + m)*CO + h*32;
    float mxr = g_rowstat[(size_t)(z*NN + m)*2], invr = g_rowstat[(size_t)(z*NN + m)*2+1];
    for (int c = 0; c < 64; c++) {
        float acc = 0.0f;
        for (int n = 0; n < NN; n++) {
            const float* kp = g_k + ((size_t)(b*NN) + n)*CO + h*32;
            float s = 0.0f;
            for (int k = 0; k < 64; k++) s = fmaf(qp[k], kp[k], s);
            acc = fmaf(__expf(s - mxr)*invr, g_v[((size_t)(b*NN) + n)*CO + h*32 + c], acc);
        }
        size_t o = (size_t)(b*NN + m)*FUSC + h*64 + c;
        __nv_bfloat16 hb = __float2bfloat16(acc);
        g_Oh[o] = hb;
        g_Ol[o] = __float2bfloat16(acc - __bfloat162float(hb));
    }
#endif
}

// =====================================================================
// LayerNorm -> bf16 split
// =====================================================================
__global__ void layernorm_kernel(const float* __restrict__ X,
                                 const float* __restrict__ g, const float* __restrict__ b)
{
    int m = blockIdx.x, c = threadIdx.x;
    __shared__ float red[256];
    float v = X[(size_t)m*CO + c];
    red[c] = v; __syncthreads();
    for (int s = 128; s; s >>= 1) { if (c < s) red[c] += red[c+s]; __syncthreads(); }
    float mean = red[0] * (1.0f/CO); __syncthreads();
    float d = v - mean;
    red[c] = d*d; __syncthreads();
    for (int s = 128; s; s >>= 1) { if (c < s) red[c] += red[c+s]; __syncthreads(); }
    float var = red[0] * (1.0f/CO);
    float y = d * rsqrtf(var + EPSB) * g[c] + b[c];
    __nv_bfloat16 hb = __float2bfloat16(y);
    size_t i = (size_t)m*CO + c;
    g_yh[i] = hb;
    g_yl[i] = __float2bfloat16(y - __bfloat162float(hb));
}

// =====================================================================
// final output (transposed)
// =====================================================================
__global__ void final_out(const float* __restrict__ bias, float* __restrict__ out)
{
    __shared__ float tile[32][33];
    int b  = blockIdx.z;
    int n0 = blockIdx.x * 32;
    int c0 = blockIdx.y * 32;
    int tx = threadIdx.x, ty = threadIdx.y;
#pragma unroll
    for (int i = 0; i < 32; i += 8) {
        int n = n0 + ty + i, c = c0 + tx;
        size_t src = ((size_t)b*NN + n)*CO + c;
        tile[ty+i][tx] = g_f2[src] + g_fp[src] + bias[c];
    }
    __syncthreads();
#pragma unroll
    for (int i = 0; i < 32; i += 8) {
        int c = c0 + ty + i, n = n0 + tx;
        out[((size_t)b*CO + c)*NN + n] = tile[tx][ty+i];
    }
}

// =====================================================================
// host
// =====================================================================
extern "C" void kernel_launch(void* const* d_in, const int* in_sizes, int n_in,
                              void* d_out, int out_size)
{
    const float* xyz    = (const float*)d_in[0];
    const float* f      = (const float*)d_in[1];
    const float* W_geo  = (const float*)d_in[2];
    const float* gg     = (const float*)d_in[3];
    const float* bg     = (const float*)d_in[4];
    const float* W_feat = (const float*)d_in[5];
    const float* gf     = (const float*)d_in[6];
    const float* bf     = (const float*)d_in[7];
    const float* g_bn   = (const float*)d_in[8];
    const float* b_bn   = (const float*)d_in[9];
    const float* W_q    = (const float*)d_in[10];
    const float* gq     = (const float*)d_in[11];
    const float* bq     = (const float*)d_in[12];
    const float* W_k    = (const float*)d_in[13];
    const float* gk     = (const float*)d_in[14];
    const float* bk     = (const float*)d_in[15];
    const float* W_v    = (const float*)d_in[16];
    const float* gv     = (const float*)d_in[17];
    const float* bv     = (const float*)d_in[18];
    const float* W_fus  = (const float*)d_in[19];
    /* d_in[20] bias_fus: cancels inside BN */
    const float* gfu    = (const float*)d_in[21];
    const float* bfu    = (const float*)d_in[22];
    const float* g_ln   = (const float*)d_in[23];
    const float* b_ln   = (const float*)d_in[24];
    const float* W_mlp  = (const float*)d_in[25];
    const float* b_mlp  = (const float*)d_in[26];
    float* out = (float*)d_out;

    float *p_featv, *p_fp, *p_f2, *p_msc;
    __nv_bfloat16 *p_yh, *p_yl, *p_Oh, *p_Ol, *p_xh, *p_xl;
    __nv_bfloat16 *p_wfush, *p_wfusl, *p_wmh, *p_wml;
    cudaGetSymbolAddress((void**)&p_featv, g_featv);
    cudaGetSymbolAddress((void**)&p_fp,    g_fp);
    cudaGetSymbolAddress((void**)&p_f2,    g_f2);
    cudaGetSymbolAddress((void**)&p_msc,   g_msc);
    cudaGetSymbolAddress((void**)&p_xh,    g_xh);
    cudaGetSymbolAddress((void**)&p_xl,    g_xl);
    cudaGetSymbolAddress((void**)&p_yh,    g_yh);
    cudaGetSymbolAddress((void**)&p_yl,    g_yl);
    cudaGetSymbolAddress((void**)&p_Oh,    g_Oh);
    cudaGetSymbolAddress((void**)&p_Ol,    g_Ol);
    cudaGetSymbolAddress((void**)&p_wfush, g_wfush);
    cudaGetSymbolAddress((void**)&p_wfusl, g_wfusl);
    cudaGetSymbolAddress((void**)&p_wmh,   g_wmh);
    cudaGetSymbolAddress((void**)&p_wml,   g_wml);

    cudaFuncSetAttribute(attn_stats, cudaFuncAttributeMaxDynamicSharedMemorySize, ST_SMEM);
    cudaFuncSetAttribute(attn_flash, cudaFuncAttributeMaxDynamicSharedMemorySize, FL_SMEM);
    cudaFuncSetAttribute(tgemm,      cudaFuncAttributeMaxDynamicSharedMemorySize, TG_SMEM);
    cudaFuncSetAttribute(qkv_gemm,   cudaFuncAttributeMaxDynamicSharedMemorySize, TG_SMEM);
    cudaFuncSetAttribute(feat_gemm,  cudaFuncAttributeMaxDynamicSharedMemorySize, FEAT_SMEM);

    // ---- 0. weight splits
    split_weights<<<1536, 256>>>(W_feat, W_q, W_k, W_v, W_fus, W_mlp);

    // ---- 1. KNN + transpose + geo (max/min + fused stats)
    knn_kernel<<<MTOT, 256>>>(xyz);
    transpose_f<<<dim3(NN/32, CIN/32, BB), dim3(32,8)>>>(f);
    geo_pre<<<NGEOREG, 128>>>(xyz, W_geo);

    // ---- 2. feat GEMM (inline gather from L2-resident g_ft + fused stats)
    feat_gemm<<<dim3(1, NFEATCTA), 256, FEAT_SMEM>>>();

    // ---- 3. act stats (hierarchical combines) + branch apply
    act_combine<<<128, 128>>>();
    bn_stats_act<<<1, 256>>>(p_msc + 0*512);
    branch_apply<<<MTOT, 256>>>(p_msc + 0*512, gg, bg, gf, bf);

    // ---- 4. BatchNorm1d -> x split
    bn_stats_partial<<<32, 256>>>(p_featv, MTOT);
    bn_stats_final<<<1, 256>>>(32, MTOT, p_msc + 1*512);
    bn_apply_split<<<MTOT, 256>>>(p_featv, p_msc + 1*512, g_bn, b_bn, 0, p_xh, p_xl);

    // ---- 5. q/k/v merged GEMM + stats + apply
    qkv_gemm<<<dim3(2, MTOT/128, 3), 256, TG_SMEM>>>();
    bn_stats_qkv<<<dim3(64, 3), 256>>>();
    bn_final_qkv<<<3, 256>>>(p_msc);
    bn_apply_qkv<<<dim3(MTOT*CO/256, 3), 256>>>(p_msc, gq, bq, gk, bk, gv, bv);
    vt_convert<<<dim3(NN/32, 2, BB*HEADS), dim3(32,8)>>>();

    // ---- 6. flash attention (two kernels, no prefetch — measured best)
    attn_stats<<<dim3(16, BB*HEADS), 256, ST_SMEM>>>();
    attn_flash<<<dim3(16, BB*HEADS), 256, FL_SMEM>>>();

    // ---- 7. fus + residual
    tgemm<<<dim3(2, MTOT/128), 256, TG_SMEM>>>(p_Oh, p_Ol, p_wfush, p_wfusl,
                                               p_fp, FUSC, FUSC, CO, 7);
    bn_stats_partial<<<32, 256>>>(p_fp, MTOT);
    bn_stats_final<<<1, 256>>>(32, MTOT, p_msc + 5*512);
    bn_apply<<<MTOT, 256>>>(p_fp, p_f2, p_msc + 5*512, gfu, bfu, p_featv, 1);

    // ---- 8. layernorm + mlp + out
    layernorm_kernel<<<MTOT, 256>>>(p_f2, g_ln, b_ln);
    tgemm<<<dim3(2, MTOT/128), 256, TG_SMEM>>>(p_yh, p_yl, p_wmh, p_wml, p_fp, CO, CO, CO, 4);
    final_out<<<dim3(NN/32, CO/32, BB), dim3(32,8)>>>(b_mlp, out);

    (void)in_sizes; (void)n_in; (void)out_size;
}

// round 16
// speedup vs baseline: 1.6712x; 1.0271x over previous
#include <cuda_runtime.h>
#include <cuda_bf16.h>
#include <cfloat>
#include <math.h>
#include <cstdint>

#if defined(__CUDA_ARCH__) && defined(__CUDA_ARCH_FEAT_SM103_ALL)
#define HAS_TC 1
#else
#define HAS_TC 0
#endif

// ---------------- problem constants ----------------
#define BB    4
#define NN    2048
#define KNB   21
#define CIN   64
#define CO    256
#define HEADS 7
#define WCH   64
#define FUSC  (HEADS*WCH)          /* 448 */
#define MTOT  (BB*NN)              /* 8192 */
#define RTOT  (MTOT*KNB)           /* 172032 */
#define EPSB  1e-5f
#define NGEOREG  2048
#define NFEATCTA (RTOT/128)        /* 1344 */

// ---------------- scratch ----------------
__device__ int    g_idx[RTOT];
__device__ float  g_ft[MTOT*CIN];
__device__ float  g_zmx[MTOT*128];                   // geo pre-BN max over k
__device__ float  g_zmn[MTOT*128];                   // geo pre-BN min over k
__device__ float  g_fmx[(size_t)NFEATCTA*8*128];     // feat per-tile/point max
__device__ float  g_fmn[(size_t)NFEATCTA*8*128];     // feat per-tile/point min
__device__ float  g_featv[MTOT*CO];
__device__ float  g_q[MTOT*CO];
__device__ float  g_k[MTOT*CO];
__device__ float  g_v[MTOT*CO];
__device__ float  g_rowstat[BB*HEADS*NN*2];
__device__ float  g_fp[MTOT*CO];
__device__ float  g_f2[MTOT*CO];
__device__ float  g_partf[256*2*CO];
__device__ float  g_msc[6*2*CO];
__device__ float  g_geo_part[(size_t)NGEOREG*256];   // [region]{sum[128]|sq[128]}
__device__ float  g_feat_part[(size_t)NFEATCTA*256];
__device__ float  g_geo_c[64*256];
__device__ float  g_feat_c[64*256];
// bf16 hi/lo splits
__device__ __nv_bfloat16 g_xh[MTOT*CO],  g_xl[MTOT*CO];
__device__ __nv_bfloat16 g_qh[MTOT*CO],  g_ql[MTOT*CO];
__device__ __nv_bfloat16 g_kh[MTOT*CO],  g_kl[MTOT*CO];
__device__ __nv_bfloat16 g_yh[MTOT*CO],  g_yl[MTOT*CO];
__device__ __nv_bfloat16 g_Oh[MTOT*FUSC], g_Ol[MTOT*FUSC];
__device__ __nv_bfloat16 g_vth[(size_t)BB*HEADS*WCH*NN], g_vtl[(size_t)BB*HEADS*WCH*NN];
__device__ __nv_bfloat16 g_wfh[128*128],  g_wfl[128*128];
__device__ __nv_bfloat16 g_wqh[CO*CO],    g_wql[CO*CO];
__device__ __nv_bfloat16 g_wkh[CO*CO],    g_wkl[CO*CO];
__device__ __nv_bfloat16 g_wvh[CO*CO],    g_wvl[CO*CO];
__device__ __nv_bfloat16 g_wfush[CO*FUSC],g_wfusl[CO*FUSC];
__device__ __nv_bfloat16 g_wmh[CO*CO],    g_wml[CO*CO];

// ---------------- helpers ----------------
__device__ __forceinline__ uint32_t smem_u32(const void* p) {
    uint32_t a;
    asm("{ .reg .u64 t; cvta.to.shared.u64 t, %1; cvt.u32.u64 %0, t; }" : "=r"(a) : "l"(p));
    return a;
}
__device__ __forceinline__ uint32_t swz(uint32_t o) { return o ^ ((o >> 3) & 0x70); }
__device__ __forceinline__ uint32_t bpackh(__nv_bfloat16 a, __nv_bfloat16 b) {
    __nv_bfloat162 t = __halves2bfloat162(a, b);
    return *reinterpret_cast<uint32_t*>(&t);
}

#if HAS_TC
__device__ __forceinline__ uint32_t elect_one_pred() {
    uint32_t pred;
    asm volatile("{\n\t.reg .pred p;\n\telect.sync _|p, 0xFFFFFFFF;\n\tselp.b32 %0, 1, 0, p;\n\t}" : "=r"(pred));
    return pred;
}

#define MBARRIER_INIT(addr, cnt) \
    asm volatile("mbarrier.init.shared.b64 [%0], %1;" :: "r"((uint32_t)(addr)), "r"((uint32_t)(cnt)) : "memory")

#define MBARRIER_WAIT_PARITY(mbar_smem_addr, phase_parity) do { \
    uint32_t _mbar = (uint32_t)(mbar_smem_addr); \
    uint32_t _parity = (uint32_t)(phase_parity); \
    uint32_t _done; \
    asm volatile("{\n\t.reg .pred p;\n\t" \
        "mbarrier.try_wait.parity.acquire.cta.shared::cta.b64 p, [%1], %2;\n\t" \
        "selp.b32 %0, 1, 0, p;\n\t}" : "=r"(_done) : "r"(_mbar), "r"(_parity) : "memory"); \
    if (!_done) { \
        asm volatile("{\n\t.reg .pred P1;\n\t" \
            "WAIT_LOOP_%=:\n\t" \
            "mbarrier.try_wait.parity.acquire.cta.shared::cta.b64 P1, [%0], %1, 0x989680;\n\t" \
            "@P1 bra.uni WAIT_DONE_%=;\n\t" \
            "bra.uni WAIT_LOOP_%=;\n\t" \
            "WAIT_DONE_%=:\n\t}" :: "r"(_mbar), "r"(_parity) : "memory"); \
    } \
} while(0)

#define TCGEN05_ALLOC(sm, n) \
    asm volatile("tcgen05.alloc.cta_group::1.sync.aligned.shared::cta.b32 [%0], %1;" \
                 :: "r"((uint32_t)(sm)), "r"((uint32_t)(n)) : "memory")
#define TCGEN05_RELINQ() \
    asm volatile("tcgen05.relinquish_alloc_permit.cta_group::1.sync.aligned;")
#define TCGEN05_DEALLOC(t, n) \
    asm volatile("tcgen05.dealloc.cta_group::1.sync.aligned.b32 %0, %1;" :: "r"(t), "r"(n))
#define TCGEN05_COMMIT(mbar) \
    asm volatile("tcgen05.commit.cta_group::1.mbarrier::arrive::one.shared::cluster.b64 [%0];" \
                 :: "r"((uint32_t)(mbar)) : "memory")
#define TCGEN05_FENCE_AFTER()  asm volatile("tcgen05.fence::after_thread_sync;" ::: "memory")
#define TCGEN05_FENCE_BEFORE() asm volatile("tcgen05.fence::before_thread_sync;" ::: "memory")
#define TCGEN05_WAIT_LD()      asm volatile("tcgen05.wait::ld.sync.aligned;" ::: "memory")
#define FENCE_ASYNC_SHARED()   asm volatile("fence.proxy.async.shared::cta;" ::: "memory")

#define TCGEN05_LD_X32(r, addr) \
    asm volatile("tcgen05.ld.sync.aligned.32x32b.x32.b32 " \
        "{%0, %1, %2, %3, %4, %5, %6, %7, %8, %9, %10, %11, %12, %13, %14, %15, " \
        " %16, %17, %18, %19, %20, %21, %22, %23, %24, %25, %26, %27, %28, %29, %30, %31}, [%32];" \
        : "=r"((r)[0]),  "=r"((r)[1]),  "=r"((r)[2]),  "=r"((r)[3]), \
          "=r"((r)[4]),  "=r"((r)[5]),  "=r"((r)[6]),  "=r"((r)[7]), \
          "=r"((r)[8]),  "=r"((r)[9]),  "=r"((r)[10]), "=r"((r)[11]), \
          "=r"((r)[12]), "=r"((r)[13]), "=r"((r)[14]), "=r"((r)[15]), \
          "=r"((r)[16]), "=r"((r)[17]), "=r"((r)[18]), "=r"((r)[19]), \
          "=r"((r)[20]), "=r"((r)[21]), "=r"((r)[22]), "=r"((r)[23]), \
          "=r"((r)[24]), "=r"((r)[25]), "=r"((r)[26]), "=r"((r)[27]), \
          "=r"((r)[28]), "=r"((r)[29]), "=r"((r)[30]), "=r"((r)[31]) \
        : "r"(addr))

static __device__ __forceinline__ uint64_t make_desc(uint32_t addr) {
    const uint64_t base =
        (uint64_t(2) << 61) | (uint64_t(1) << 46) | (uint64_t(64) << 32) | (uint64_t(1) << 16);
    return base | ((uint64_t)(addr >> 4) & 0x3FFF);
}

__device__ __forceinline__ void mma_f16_ss(uint32_t d, uint64_t a, uint64_t b,
                                           uint32_t idesc, uint32_t en) {
    asm volatile(
        "{\n\t.reg .pred p;\n\tsetp.ne.u32 p, %5, 0;\n\t"
        "tcgen05.mma.cta_group::1.kind::f16 [%0], %1, %2, %3, {%4, %4, %4, %4}, p;\n\t}"
        :: "r"(d), "l"(a), "l"(b), "r"(idesc), "r"(0u), "r"(en) : "memory");
}

#define IDESC_N128 ((1u<<4)|(1u<<7)|(1u<<10)|((128u/8)<<17)|((128u/16)<<24))
#define IDESC_N64  ((1u<<4)|(1u<<7)|(1u<<10)|(( 64u/8)<<17)|((128u/16)<<24))

// ---- tensor-GEMM core (no register prefetch — measured best) ----
__device__ __forceinline__ void tgemm_core(char* sb, uint32_t base,
    const __nv_bfloat16* __restrict__ Ah, const __nv_bfloat16* __restrict__ Al,
    const __nv_bfloat16* __restrict__ Bh, const __nv_bfloat16* __restrict__ Bl,
    float* __restrict__ C, int lda, int ldb, int ldc, int nkc, int m0, int n0)
{
    uint32_t ctrl = base + 65536;
    uint32_t mbar = ctrl + 8;
    int t = threadIdx.x;

    if (t == 0) MBARRIER_INIT(mbar, 1);
    if (t < 32) { TCGEN05_ALLOC(ctrl, 128); TCGEN05_RELINQ(); }
    __syncthreads();
    uint32_t tmem;
    asm volatile("ld.shared.b32 %0, [%1];" : "=r"(tmem) : "r"(ctrl));

    Ah += (size_t)m0 * lda; Al += (size_t)m0 * lda;
    Bh += (size_t)n0 * ldb; Bl += (size_t)n0 * ldb;

    uint64_t dAh = make_desc(base + 0*16384);
    uint64_t dAl = make_desc(base + 1*16384);
    uint64_t dBh = make_desc(base + 2*16384);
    uint64_t dBl = make_desc(base + 3*16384);

    int rb = t >> 4, kq = t & 15;

    for (int kc = 0; kc < nkc; kc++) {
        if (kc > 0) MBARRIER_WAIT_PARITY(mbar, (kc-1) & 1);
        int k0 = kc*64;
#pragma unroll
        for (int i = 0; i < 8; i++) {
            int r = rb + i*16;
            uint32_t so = swz((uint32_t)(r*128 + kq*8));
            *(uint2*)(sb + 0*16384 + so) = *(const uint2*)(Ah + (size_t)r*lda + k0 + kq*4);
            *(uint2*)(sb + 1*16384 + so) = *(const uint2*)(Al + (size_t)r*lda + k0 + kq*4);
            *(uint2*)(sb + 2*16384 + so) = *(const uint2*)(Bh + (size_t)r*ldb + k0 + kq*4);
            *(uint2*)(sb + 3*16384 + so) = *(const uint2*)(Bl + (size_t)r*ldb + k0 + kq*4);
        }
        __syncthreads();
        if (t < 32) {
            if (elect_one_pred()) {
                FENCE_ASYNC_SHARED();
#pragma unroll
                for (int ks = 0; ks < 4; ks++) {
                    uint64_t o = ks*2;
                    mma_f16_ss(tmem, dAh+o, dBh+o, IDESC_N128, (kc > 0 || ks > 0) ? 1u : 0u);
                    mma_f16_ss(tmem, dAh+o, dBl+o, IDESC_N128, 1u);
                    mma_f16_ss(tmem, dAl+o, dBh+o, IDESC_N128, 1u);
                }
                TCGEN05_COMMIT(mbar);
            }
        }
    }
    MBARRIER_WAIT_PARITY(mbar, (nkc-1) & 1);
    TCGEN05_FENCE_AFTER();

    int w = t >> 5, lane = t & 31;
    int sub = w & 3, half = w >> 2;
    float* Crow = C + (size_t)(m0 + sub*32 + lane)*ldc + n0;
#pragma unroll
    for (int gi = 0; gi < 2; gi++) {
        int g = half*2 + gi;
        uint32_t r[32];
        TCGEN05_LD_X32(r, tmem + g*32);
        TCGEN05_WAIT_LD();
        TCGEN05_FENCE_BEFORE();
#pragma unroll
        for (int j = 0; j < 8; j++)
            *(float4*)(Crow + g*32 + j*4) = make_float4(
                __uint_as_float(r[j*4+0]), __uint_as_float(r[j*4+1]),
                __uint_as_float(r[j*4+2]), __uint_as_float(r[j*4+3]));
    }
    __syncthreads();
    if (t < 32) TCGEN05_DEALLOC(tmem, 128);
}
#else
__device__ __forceinline__ void tgemm_core_simt(
    const __nv_bfloat16* Ah, const __nv_bfloat16* Al,
    const __nv_bfloat16* Bh, const __nv_bfloat16* Bl,
    float* C, int lda, int ldb, int ldc, int nkc, int m0, int n0)
{
    int t = threadIdx.x;
    int m = m0 + (t >> 1);
    int nb = (t & 1) * 64;
    for (int n = nb; n < nb + 64; n++) {
        float acc = 0.0f;
        for (int k = 0; k < nkc*64; k++) {
            float a = __bfloat162float(Ah[(size_t)m*lda+k]) + __bfloat162float(Al[(size_t)m*lda+k]);
            float b = __bfloat162float(Bh[(size_t)(n0+n)*ldb+k]) + __bfloat162float(Bl[(size_t)(n0+n)*ldb+k]);
            acc = fmaf(a, b, acc);
        }
        C[(size_t)m*ldc + n0 + n] = acc;
    }
}
#endif // HAS_TC

#define TG_SMEM (1024 + 4*16384 + 64)

// =====================================================================
// KNN
// =====================================================================
__global__ void knn_kernel(const float* __restrict__ xyz)
{
    __shared__ float d2s[NN];
    __shared__ float rv[256];
    __shared__ int   ri[256];
    int m = blockIdx.x;
    int b = m >> 11;
    int t = threadIdx.x;
    const float* base = xyz + (size_t)(b << 11) * 3;

    float qx = xyz[m*3+0], qy = xyz[m*3+1], qz = xyz[m*3+2];
    float sqq = qx*qx + qy*qy + qz*qz;

    for (int j = t; j < NN; j += 256) {
        float px = base[j*3+0], py = base[j*3+1], pz = base[j*3+2];
        float sqp = px*px + py*py + pz*pz;
        float dot = qx*px + qy*py + qz*pz;
        d2s[j] = sqq + sqp - 2.0f*dot;
    }
    __syncthreads();

    for (int it = 0; it < KNB; it++) {
        float bv = FLT_MAX; int bi = 0x3fffffff;
        for (int j = t; j < NN; j += 256) {
            float v = d2s[j];
            if (v < bv) { bv = v; bi = j; }
        }
        rv[t] = bv; ri[t] = bi;
        __syncthreads();
        for (int s = 128; s; s >>= 1) {
            if (t < s) {
                float ov = rv[t+s]; int oi = ri[t+s];
                if (ov < rv[t] || (ov == rv[t] && oi < ri[t])) { rv[t] = ov; ri[t] = oi; }
            }
            __syncthreads();
        }
        if (t == 0) { g_idx[(size_t)m*KNB + it] = ri[0]; d2s[ri[0]] = FLT_MAX; }
        __syncthreads();
    }
}

// =====================================================================
// transpose f
// =====================================================================
__global__ void transpose_f(const float* __restrict__ f)
{
    __shared__ float tile[32][33];
    int b  = blockIdx.z;
    int n0 = blockIdx.x * 32;
    int c0 = blockIdx.y * 32;
    int tx = threadIdx.x, ty = threadIdx.y;
#pragma unroll
    for (int i = 0; i < 32; i += 8)
        tile[ty+i][tx] = f[((size_t)b*CIN + c0 + ty + i)*NN + n0 + tx];
    __syncthreads();
#pragma unroll
    for (int i = 0; i < 32; i += 8)
        g_ft[((size_t)b*NN + n0 + ty + i)*CIN + c0 + tx] = tile[tx][ty+i];
}

// =====================================================================
// geo pre-activation: store only max/min over k + fused stat partials
// =====================================================================
__global__ void geo_pre(const float* __restrict__ xyz, const float* __restrict__ Wg)
{
    __shared__ float nb3[KNB*3];
    int region = blockIdx.x;
    int c = threadIdx.x;
    float w0 = Wg[c*6+0], w1 = Wg[c*6+1], w2 = Wg[c*6+2];
    float w3 = Wg[c*6+3], w4 = Wg[c*6+4], w5 = Wg[c*6+5];
    float s = 0.0f, s2 = 0.0f;

    for (int p = 0; p < 4; p++) {
        int m = region*4 + p;
        int b = m >> 11;
        __syncthreads();
        if (c < KNB) {
            int nb = g_idx[(size_t)m*KNB + c];
            const float* pp = xyz + (size_t)((b << 11) + nb)*3;
            nb3[c*3+0] = pp[0]; nb3[c*3+1] = pp[1]; nb3[c*3+2] = pp[2];
        }
        __syncthreads();
        float cx = xyz[m*3+0], cy = xyz[m*3+1], cz = xyz[m*3+2];
        float base = w0*cx + w1*cy + w2*cz;
        float mx = -FLT_MAX, mn = FLT_MAX;
#pragma unroll 3
        for (int k = 0; k < KNB; k++) {
            float dx = nb3[k*3+0]-cx, dy = nb3[k*3+1]-cy, dz = nb3[k*3+2]-cz;
            float z = base + w3*dx + w4*dy + w5*dz;
            s += z; s2 = fmaf(z, z, s2);
            mx = fmaxf(mx, z); mn = fminf(mn, z);
        }
        g_zmx[(size_t)m*128 + c] = mx;
        g_zmn[(size_t)m*128 + c] = mn;
    }
    g_geo_part[(size_t)region*256 + c]       = s;
    g_geo_part[(size_t)region*256 + 128 + c] = s2;
}

// merged partial combine: blocks 0..63 geo (32 regions each),
// blocks 64..127 feat (21 tiles each)
__global__ void act_combine()
{
    int c = threadIdx.x;
    int blk = blockIdx.x;
    float s = 0.0f, s2 = 0.0f;
    if (blk < 64) {
        for (int r = blk*32; r < blk*32 + 32; r++) {
            s  += g_geo_part[(size_t)r*256 + c];
            s2 += g_geo_part[(size_t)r*256 + 128 + c];
        }
        g_geo_c[blk*256 + c]       = s;
        g_geo_c[blk*256 + 128 + c] = s2;
    } else {
        int fb = blk - 64;
        for (int r = fb*21; r < fb*21 + 21; r++) {
            s  += g_feat_part[(size_t)r*256 + c];
            s2 += g_feat_part[(size_t)r*256 + 128 + c];
        }
        g_feat_c[fb*256 + c]       = s;
        g_feat_c[fb*256 + 128 + c] = s2;
    }
}

// final act stats combine (double, fixed order)
__global__ void bn_stats_act(float* msc)
{
    int c = threadIdx.x;
    double s = 0.0, s2 = 0.0;
    if (c < 128) {
        for (int r = 0; r < 64; r++) {
            s  += (double)g_geo_c[r*256 + c];
            s2 += (double)g_geo_c[r*256 + 128 + c];
        }
    } else {
        int cc = c - 128;
        for (int r = 0; r < 64; r++) {
            s  += (double)g_feat_c[r*256 + cc];
            s2 += (double)g_feat_c[r*256 + 128 + cc];
        }
    }
    double mean = s / (double)RTOT;
    double var  = s2 / (double)RTOT - mean*mean;
    msc[c]      = (float)mean;
    msc[CO + c] = (float)(1.0 / sqrt(var + (double)EPSB));
}

// =====================================================================
// feat GEMM with INLINE gather+split (g_ft is L2-resident)
// epilogue: stats partials + per-(tile,point) max/min — g_actf deleted.
// grid (1, NFEATCTA), 256 threads.
// =====================================================================
#define FEAT_SMEM (1024 + 69632 + 64)

__global__ void __launch_bounds__(256, 1)
feat_gemm()
{
#if HAS_TC
    extern __shared__ char sm[];
    uint32_t raw = smem_u32(sm);
    uint32_t base = (raw + 1023) & ~1023u;
    char* sb = sm + (base - raw);
    uint32_t ctrl = base + 69632;
    uint32_t mbar = ctrl + 8;
    int t = threadIdx.x;
    int m0 = blockIdx.y * 128;

    if (t == 0) MBARRIER_INIT(mbar, 1);
    if (t < 32) { TCGEN05_ALLOC(ctrl, 128); TCGEN05_RELINQ(); }
    __syncthreads();
    uint32_t tmem;
    asm volatile("ld.shared.b32 %0, [%1];" : "=r"(tmem) : "r"(ctrl));

    uint64_t dAh = make_desc(base + 0*16384);
    uint64_t dAl = make_desc(base + 1*16384);
    uint64_t dBh = make_desc(base + 2*16384);
    uint64_t dBl = make_desc(base + 3*16384);

    int rb = t >> 4, kq = t & 15;
    for (int kc = 0; kc < 2; kc++) {
        if (kc > 0) MBARRIER_WAIT_PARITY(mbar, 0);
        int k0 = kc*64;
#pragma unroll
        for (int i = 0; i < 8; i++) {
            int r = rb + i*16;
            uint32_t R = (uint32_t)(m0 + r);
            uint32_t m = R / KNB;
            uint32_t b = m >> 11;
            const float* src;
            if (kc == 0) {
                uint32_t nb = (uint32_t)g_idx[R];
                src = g_ft + (size_t)((b << 11) + nb)*CIN + kq*4;
            } else {
                src = g_ft + (size_t)m*CIN + kq*4;
            }
            float4 v = *(const float4*)src;
            __nv_bfloat16 h0 = __float2bfloat16(v.x);
            __nv_bfloat16 h1 = __float2bfloat16(v.y);
            __nv_bfloat16 h2 = __float2bfloat16(v.z);
            __nv_bfloat16 h3 = __float2bfloat16(v.w);
            uint32_t so = swz((uint32_t)(r*128 + kq*8));
            *(uint2*)(sb + 0*16384 + so) = make_uint2(bpackh(h0,h1), bpackh(h2,h3));
            *(uint2*)(sb + 1*16384 + so) = make_uint2(
                bpackh(__float2bfloat16(v.x - __bfloat162float(h0)),
                       __float2bfloat16(v.y - __bfloat162float(h1))),
                bpackh(__float2bfloat16(v.z - __bfloat162float(h2)),
                       __float2bfloat16(v.w - __bfloat162float(h3))));
            *(uint2*)(sb + 2*16384 + so) = *(const uint2*)(g_wfh + (size_t)r*128 + k0 + kq*4);
            *(uint2*)(sb + 3*16384 + so) = *(const uint2*)(g_wfl + (size_t)r*128 + k0 + kq*4);
        }
        __syncthreads();
        if (t < 32) {
            if (elect_one_pred()) {
                FENCE_ASYNC_SHARED();
#pragma unroll
                for (int ks = 0; ks < 4; ks++) {
                    uint64_t o = ks*2;
                    mma_f16_ss(tmem, dAh+o, dBh+o, IDESC_N128, (kc > 0 || ks > 0) ? 1u : 0u);
                    mma_f16_ss(tmem, dAh+o, dBl+o, IDESC_N128, 1u);
                    mma_f16_ss(tmem, dAl+o, dBh+o, IDESC_N128, 1u);
                }
                TCGEN05_COMMIT(mbar);
            }
        }
    }
    MBARRIER_WAIT_PARITY(mbar, 1);
    TCGEN05_FENCE_AFTER();

    int w = t >> 5, lane = t & 31;
    int sub = w & 3, half = w >> 2;
    int row = sub*32 + lane;
    float* stile = (float*)sb;   // [128][132], inputs dead now
#pragma unroll
    for (int gi = 0; gi < 2; gi++) {
        int g = half*2 + gi;
        uint32_t r[32];
        TCGEN05_LD_X32(r, tmem + g*32);
        TCGEN05_WAIT_LD();
        TCGEN05_FENCE_BEFORE();
#pragma unroll
        for (int j = 0; j < 8; j++) {
            float4 v = make_float4(
                __uint_as_float(r[j*4+0]), __uint_as_float(r[j*4+1]),
                __uint_as_float(r[j*4+2]), __uint_as_float(r[j*4+3]));
            *(float4*)(stile + row*132 + g*32 + j*4) = v;
        }
    }
    __syncthreads();
    if (t < 128) {
        // single ordered scan: stats sum/sq + per-point max/min segments
        float s = 0.0f, q = 0.0f;
        int pfirst = m0 / KNB;
        int pcur = pfirst;
        float mx = -FLT_MAX, mn = FLT_MAX;
        for (int rr = 0; rr < 128; rr++) {
            int p = (m0 + rr) / KNB;
            if (p != pcur) {
                size_t o = ((size_t)blockIdx.y*8 + (pcur - pfirst))*128 + t;
                g_fmx[o] = mx; g_fmn[o] = mn;
                mx = -FLT_MAX; mn = FLT_MAX; pcur = p;
            }
            float v = stile[rr*132 + t];
            s += v; q = fmaf(v, v, q);
            mx = fmaxf(mx, v); mn = fminf(mn, v);
        }
        size_t o = ((size_t)blockIdx.y*8 + (pcur - pfirst))*128 + t;
        g_fmx[o] = mx; g_fmn[o] = mn;
        g_feat_part[(size_t)blockIdx.y*256 + t]       = s;
        g_feat_part[(size_t)blockIdx.y*256 + 128 + t] = q;
    }
    __syncthreads();
    if (t < 32) TCGEN05_DEALLOC(tmem, 128);
#else
    extern __shared__ char sm[];
    float* stile = (float*)sm;   // [128][132]
    int t = threadIdx.x;
    int m0 = blockIdx.y*128;
    {
        int r = t >> 1;
        int R = m0 + r;
        int m = R / KNB;
        int b = m >> 11;
        int nbr = g_idx[R];
        int nb0 = (t & 1) * 64;
        for (int n = nb0; n < nb0 + 64; n++) {
            float acc = 0.0f;
            for (int k = 0; k < 128; k++) {
                float a = (k < 64) ? g_ft[(size_t)((b<<11)+nbr)*CIN + k]
                                   : g_ft[(size_t)m*CIN + (k-64)];
                float bw = __bfloat162float(g_wfh[(size_t)n*128+k]) + __bfloat162float(g_wfl[(size_t)n*128+k]);
                acc = fmaf(a, bw, acc);
            }
            stile[r*132 + n] = acc;
        }
    }
    __syncthreads();
    if (t < 128) {
        float s = 0.0f, q = 0.0f;
        int pfirst = m0 / KNB;
        int pcur = pfirst;
        float mx = -FLT_MAX, mn = FLT_MAX;
        for (int rr = 0; rr < 128; rr++) {
            int p = (m0 + rr) / KNB;
            if (p != pcur) {
                size_t o = ((size_t)blockIdx.y*8 + (pcur - pfirst))*128 + t;
                g_fmx[o] = mx; g_fmn[o] = mn;
                mx = -FLT_MAX; mn = FLT_MAX; pcur = p;
            }
            float v = stile[rr*132 + t];
            s += v; q = fmaf(v, v, q);
            mx = fmaxf(mx, v); mn = fminf(mn, v);
        }
        size_t o = ((size_t)blockIdx.y*8 + (pcur - pfirst))*128 + t;
        g_fmx[o] = mx; g_fmn[o] = mn;
        g_feat_part[(size_t)blockIdx.y*256 + t]       = s;
        g_feat_part[(size_t)blockIdx.y*256 + 128 + t] = q;
    }
#endif
}

// =====================================================================
// tensor GEMM wrappers
// =====================================================================
__global__ void __launch_bounds__(256, 1)
tgemm(const __nv_bfloat16* __restrict__ Ah, const __nv_bfloat16* __restrict__ Al,
      const __nv_bfloat16* __restrict__ Bh, const __nv_bfloat16* __restrict__ Bl,
      float* __restrict__ C, int lda, int ldb, int ldc, int nkc)
{
#if HAS_TC
    extern __shared__ char sm[];
    uint32_t raw = smem_u32(sm);
    uint32_t base = (raw + 1023) & ~1023u;
    tgemm_core(sm + (base - raw), base, Ah, Al, Bh, Bl, C, lda, ldb, ldc, nkc,
               blockIdx.y*128, blockIdx.x*128);
#else
    tgemm_core_simt(Ah, Al, Bh, Bl, C, lda, ldb, ldc, nkc, blockIdx.y*128, blockIdx.x*128);
#endif
}

__global__ void __launch_bounds__(256, 1)
qkv_gemm()
{
    int z = blockIdx.z;
    const __nv_bfloat16* Bh = (z==0) ? g_wqh : (z==1) ? g_wkh : g_wvh;
    const __nv_bfloat16* Bl = (z==0) ? g_wql : (z==1) ? g_wkl : g_wvl;
    float* C = (z==0) ? g_q : (z==1) ? g_k : g_v;
#if HAS_TC
    extern __shared__ char sm[];
    uint32_t raw = smem_u32(sm);
    uint32_t base = (raw + 1023) & ~1023u;
    tgemm_core(sm + (base - raw), base, g_xh, g_xl, Bh, Bl, C, CO, CO, CO, 4,
               blockIdx.y*128, blockIdx.x*128);
#else
    tgemm_core_simt(g_xh, g_xl, Bh, Bl, C, CO, CO, CO, 4, blockIdx.y*128, blockIdx.x*128);
#endif
}

// =====================================================================
// BN stats (fp32 partials, double combine) — small tensors
// =====================================================================
__device__ __forceinline__ void bn_partial_region(const float* X, long rows,
                                                  int nblk, int blk, int region)
{
    int c = threadIdx.x;
    long per = (rows + nblk - 1) / nblk;
    long r0 = (long)blk * per;
    long r1 = r0 + per; if (r1 > rows) r1 = rows;
    float a0=0,a1=0,a2=0,a3=0, q0=0,q1=0,q2=0,q3=0;
    long r = r0;
    for (; r + 4 <= r1; r += 4) {
        float v0 = X[(r+0)*CO + c], v1 = X[(r+1)*CO + c];
        float v2 = X[(r+2)*CO + c], v3 = X[(r+3)*CO + c];
        a0 += v0; q0 = fmaf(v0,v0,q0);
        a1 += v1; q1 = fmaf(v1,v1,q1);
        a2 += v2; q2 = fmaf(v2,v2,q2);
        a3 += v3; q3 = fmaf(v3,v3,q3);
    }
    for (; r < r1; r++) { float v = X[r*CO + c]; a0 += v; q0 = fmaf(v,v,q0); }
    g_partf[((size_t)region*2 + 0)*CO + c] = (a0+a1) + (a2+a3);
    g_partf[((size_t)region*2 + 1)*CO + c] = (q0+q1) + (q2+q3);
}

__global__ void bn_stats_partial(const float* __restrict__ X, long rows)
{
    bn_partial_region(X, rows, gridDim.x, blockIdx.x, blockIdx.x);
}

__global__ void bn_stats_final(int nblocks, long rows, float* msc)
{
    int c = threadIdx.x;
    double s = 0.0, s2 = 0.0;
    for (int i = 0; i < nblocks; i++) {
        s  += (double)g_partf[((size_t)i*2 + 0)*CO + c];
        s2 += (double)g_partf[((size_t)i*2 + 1)*CO + c];
    }
    double mean = s / (double)rows;
    double var  = s2 / (double)rows - mean*mean;
    msc[c]      = (float)mean;
    msc[CO + c] = (float)(1.0 / sqrt(var + (double)EPSB));
}

__global__ void bn_stats_qkv()
{
    const float* X = (blockIdx.y==0) ? g_q : (blockIdx.y==1) ? g_k : g_v;
    bn_partial_region(X, MTOT, 64, blockIdx.x, blockIdx.y*64 + blockIdx.x);
}
__global__ void bn_final_qkv(float* msc)
{
    int y = blockIdx.x;
    int c = threadIdx.x;
    double s = 0.0, s2 = 0.0;
    for (int i = y*64; i < y*64 + 64; i++) {
        s  += (double)g_partf[((size_t)i*2 + 0)*CO + c];
        s2 += (double)g_partf[((size_t)i*2 + 1)*CO + c];
    }
    double mean = s / (double)MTOT;
    double var  = s2 / (double)MTOT - mean*mean;
    msc[(2+y)*512 + c]      = (float)mean;
    msc[(2+y)*512 + CO + c] = (float)(1.0 / sqrt(var + (double)EPSB));
}

// =====================================================================
// branch BN + relu + maxpool
// geo half: monotonicity on zmax/zmin
// feat half: monotonicity on per-tile partial max/min (<=2 tiles/point)
// =====================================================================
__global__ void branch_apply(const float* msc,
                             const float* __restrict__ g_geo, const float* __restrict__ b_geo,
                             const float* __restrict__ g_fea, const float* __restrict__ b_fea)
{
    int m = blockIdx.x;
    int c = threadIdx.x;
    float mean = msc[c], istd = msc[CO + c];
    float ga = (c < 128) ? g_geo[c] : g_fea[c - 128];
    float be = (c < 128) ? b_geo[c] : b_fea[c - 128];
    float sc = istd * ga;
    float best;
    if (c < 128) {
        float zv = (sc >= 0.0f) ? g_zmx[(size_t)m*128 + c] : g_zmn[(size_t)m*128 + c];
        best = fmaxf((zv - mean) * sc + be, 0.0f);
    } else {
        int cc = c - 128;
        int r0 = m * KNB;
        int t1 = r0 / 128,        s1 = m - (t1*128)/KNB;
        int t2 = (r0 + KNB-1)/128, s2 = m - (t2*128)/KNB;
        size_t o1 = ((size_t)t1*8 + s1)*128 + cc;
        size_t o2 = ((size_t)t2*8 + s2)*128 + cc;
        float zv;
        if (sc >= 0.0f) zv = fmaxf(g_fmx[o1], g_fmx[o2]);
        else            zv = fminf(g_fmn[o1], g_fmn[o2]);
        best = fmaxf((zv - mean) * sc + be, 0.0f);
    }
    g_featv[(size_t)m*CO + c] = best;
}

// =====================================================================
// BN apply variants
// =====================================================================
__global__ void bn_apply(const float* __restrict__ in, float* __restrict__ out,
                         const float* msc,
                         const float* __restrict__ gamma, const float* __restrict__ beta,
                         const float* __restrict__ res, int do_relu)
{
    size_t i = (size_t)blockIdx.x * blockDim.x + threadIdx.x;
    int c = (int)(i & (CO-1));
    float y = (in[i] - msc[c]) * msc[CO + c] * gamma[c] + beta[c];
    if (do_relu) y = fmaxf(y, 0.0f);
    if (res) y += res[i];
    out[i] = y;
}

__global__ void bn_apply_split(const float* __restrict__ in,
                               const float* msc,
                               const float* __restrict__ gamma, const float* __restrict__ beta,
                               int do_relu,
                               __nv_bfloat16* __restrict__ oh, __nv_bfloat16* __restrict__ ol)
{
    size_t i = (size_t)blockIdx.x * blockDim.x + threadIdx.x;
    int c = (int)(i & (CO-1));
    float y = (in[i] - msc[c]) * msc[CO + c] * gamma[c] + beta[c];
    if (do_relu) y = fmaxf(y, 0.0f);
    __nv_bfloat16 hb = __float2bfloat16(y);
    oh[i] = hb;
    ol[i] = __float2bfloat16(y - __bfloat162float(hb));
}

__global__ void bn_apply_qkv(const float* msc,
                             const float* __restrict__ gq, const float* __restrict__ bq,
                             const float* __restrict__ gk, const float* __restrict__ bk,
                             const float* __restrict__ gv, const float* __restrict__ bv)
{
    int y = blockIdx.y;
    size_t i = (size_t)blockIdx.x * 256 + threadIdx.x;
    int c = (int)(i & (CO-1));
    const float* in = (y==0) ? g_q : (y==1) ? g_k : g_v;
    const float* ga = (y==0) ? gq : (y==1) ? gk : gv;
    const float* be = (y==0) ? bq : (y==1) ? bk : bv;
    const float* ms = msc + (2+y)*512;
    float v = fmaxf((in[i] - ms[c]) * ms[CO + c] * ga[c] + be[c], 0.0f);
    if (y == 2) { g_v[i] = v; return; }
    __nv_bfloat16 hb = __float2bfloat16(v);
    __nv_bfloat16 lb = __float2bfloat16(v - __bfloat162float(hb));
    if (y == 0) { g_qh[i] = hb; g_ql[i] = lb; }
    else        { g_kh[i] = hb; g_kl[i] = lb; }
}

// =====================================================================
// fused weight splits
// =====================================================================
__global__ void split_weights(const float* __restrict__ Wf, const float* __restrict__ Wq,
                              const float* __restrict__ Wk, const float* __restrict__ Wv,
                              const float* __restrict__ Wfus, const float* __restrict__ Wm)
{
    int i = blockIdx.x*256 + threadIdx.x;
    const float* src; __nv_bfloat16 *dh, *dl; int off;
    if      (i < 16384)  { src = Wf;   dh = g_wfh;   dl = g_wfl;   off = i; }
    else if (i < 81920)  { src = Wq;   dh = g_wqh;   dl = g_wql;   off = i - 16384; }
    else if (i < 147456) { src = Wk;   dh = g_wkh;   dl = g_wkl;   off = i - 81920; }
    else if (i < 212992) { src = Wv;   dh = g_wvh;   dl = g_wvl;   off = i - 147456; }
    else if (i < 327680) { src = Wfus; dh = g_wfush; dl = g_wfusl; off = i - 212992; }
    else                 { src = Wm;   dh = g_wmh;   dl = g_wml;   off = i - 327680; }
    float v = src[off];
    __nv_bfloat16 hb = __float2bfloat16(v);
    dh[off] = hb;
    dl[off] = __float2bfloat16(v - __bfloat162float(hb));
}

// =====================================================================
// v -> per-head transposed bf16 split
// =====================================================================
__global__ void vt_convert()
{
    __shared__ float tile[32][33];
    int z  = blockIdx.z;
    int b  = z / HEADS, h = z - b*HEADS;
    int m0 = blockIdx.x * 32;
    int c0 = blockIdx.y * 32;
    int tx = threadIdx.x, ty = threadIdx.y;
#pragma unroll
    for (int i = 0; i < 32; i += 8)
        tile[ty+i][tx] = g_v[((size_t)(b*NN) + m0 + ty + i)*CO + h*32 + c0 + tx];
    __syncthreads();
#pragma unroll
    for (int i = 0; i < 32; i += 8) {
        int c = c0 + ty + i, m = m0 + tx;
        float v = tile[tx][ty+i];
        __nv_bfloat16 hb = __float2bfloat16(v);
        size_t o = (size_t)z*WCH*NN + (size_t)c*NN + m;
        g_vth[o] = hb;
        g_vtl[o] = __float2bfloat16(v - __bfloat162float(hb));
    }
}

// =====================================================================
// FLASH pass 1: per-row softmax stats
// grid (16 m-tiles, 28 z), 256 threads.
// =====================================================================
#define ST_SMEM (1024 + 65536 + 64 + 1088)

__global__ void __launch_bounds__(256, 1)
attn_stats()
{
#if HAS_TC
    extern __shared__ char sm[];
    uint32_t raw = smem_u32(sm);
    uint32_t base = (raw + 1023) & ~1023u;
    char* sb = sm + (base - raw);
    uint32_t ctrl = base + 65536;
    uint32_t mbar = ctrl + 8;
    float* mrg = (float*)(sb + 65536 + 64);   // 128 x {mx,sum}

    int t = threadIdx.x;
    int z = blockIdx.y;
    int b = z / HEADS, h = z - b*HEADS;
    int m0 = blockIdx.x * 128;

    if (t == 0) MBARRIER_INIT(mbar, 1);
    if (t < 32) { TCGEN05_ALLOC(ctrl, 128); TCGEN05_RELINQ(); }
    __syncthreads();
    uint32_t tmem;
    asm volatile("ld.shared.b32 %0, [%1];" : "=r"(tmem) : "r"(ctrl));

    const __nv_bfloat16* pQh = g_qh + ((size_t)(b*NN) + m0)*CO + h*32;
    const __nv_bfloat16* pQl = g_ql + ((size_t)(b*NN) + m0)*CO + h*32;
    const __nv_bfloat16* pKh = g_kh + ((size_t)b*NN)*CO + h*32;
    const __nv_bfloat16* pKl = g_kl + ((size_t)b*NN)*CO + h*32;

    int rb = t >> 4, kq = t & 15;
#pragma unroll
    for (int i = 0; i < 8; i++) {
        int r = rb + i*16;
        uint32_t so = swz((uint32_t)(r*128 + kq*8));
        *(uint2*)(sb + 0*16384 + so) = *(const uint2*)(pQh + (size_t)r*CO + kq*4);
        *(uint2*)(sb + 1*16384 + so) = *(const uint2*)(pQl + (size_t)r*CO + kq*4);
    }

    uint64_t dQh = make_desc(base + 0*16384);
    uint64_t dQl = make_desc(base + 1*16384);
    uint64_t dKh = make_desc(base + 2*16384);
    uint64_t dKl = make_desc(base + 3*16384);

    int w = t >> 5, lane = t & 31;
    int sub = w & 3, half = w >> 2;
    int rrow = sub*32 + lane;

    float mx = -FLT_MAX, sum = 0.0f;

    for (int nc = 0; nc < 16; nc++) {
        int n0 = nc*128;
#pragma unroll
        for (int i = 0; i < 8; i++) {
            int r = rb + i*16;
            uint32_t so = swz((uint32_t)(r*128 + kq*8));
            *(uint2*)(sb + 2*16384 + so) = *(const uint2*)(pKh + (size_t)(n0+r)*CO + kq*4);
            *(uint2*)(sb + 3*16384 + so) = *(const uint2*)(pKl + (size_t)(n0+r)*CO + kq*4);
        }
        __syncthreads();
        if (t < 32) {
            if (elect_one_pred()) {
                FENCE_ASYNC_SHARED();
#pragma unroll
                for (int ks = 0; ks < 4; ks++) {
                    uint64_t o = ks*2;
                    mma_f16_ss(tmem, dQh+o, dKh+o, IDESC_N128, (ks > 0) ? 1u : 0u);
                    mma_f16_ss(tmem, dQh+o, dKl+o, IDESC_N128, 1u);
                    mma_f16_ss(tmem, dQl+o, dKh+o, IDESC_N128, 1u);
                }
                TCGEN05_COMMIT(mbar);
            }
        }
        MBARRIER_WAIT_PARITY(mbar, nc & 1);
        TCGEN05_FENCE_AFTER();
#pragma unroll
        for (int gi = 0; gi < 2; gi++) {
            int g = half*2 + gi;
            uint32_t r[32];
            TCGEN05_LD_X32(r, tmem + g*32);
            TCGEN05_WAIT_LD();
            float gm = -FLT_MAX;
#pragma unroll
            for (int j = 0; j < 32; j++) gm = fmaxf(gm, __uint_as_float(r[j]));
            float gs = 0.0f;
#pragma unroll
            for (int j = 0; j < 32; j++) gs += __expf(__uint_as_float(r[j]) - gm);
            if (gm <= mx) sum += gs * __expf(gm - mx);
            else { sum = sum * __expf(mx - gm) + gs; mx = gm; }
        }
        __syncthreads();   // all LDTMs done before next MMA overwrites S
    }

    if (half == 0) { mrg[rrow*2] = mx; mrg[rrow*2+1] = sum; }
    __syncthreads();
    if (half == 1) {
        float m2 = mrg[rrow*2], s2 = mrg[rrow*2+1];
        float M = fmaxf(mx, m2);
        float S = s2 * __expf(m2 - M) + sum * __expf(mx - M);
        size_t row = (size_t)z*NN + m0 + rrow;
        g_rowstat[row*2]   = M;
        g_rowstat[row*2+1] = 1.0f / S;
    }
    __syncthreads();
    if (t < 32) TCGEN05_DEALLOC(tmem, 128);
#else
    int t = threadIdx.x;
    int z = blockIdx.y;
    int b = z / HEADS, h = z - b*HEADS;
    int m0 = blockIdx.x * 128;
    if (t >= 128) return;
    int m = m0 + t;
    const float* qp = g_q + ((size_t)(b*NN) + m)*CO + h*32;
    float mx = -FLT_MAX;
    for (int n = 0; n < NN; n++) {
        const float* kp = g_k + ((size_t)(b*NN) + n)*CO + h*32;
        float acc = 0.0f;
        for (int k = 0; k < 64; k++) acc = fmaf(qp[k], kp[k], acc);
        mx = fmaxf(mx, acc);
    }
    float sum = 0.0f;
    for (int n = 0; n < NN; n++) {
        const float* kp = g_k + ((size_t)(b*NN) + n)*CO + h*32;
        float acc = 0.0f;
        for (int k = 0; k < 64; k++) acc = fmaf(qp[k], kp[k], acc);
        sum += __expf(acc - mx);
    }
    size_t row = (size_t)z*NN + m;
    g_rowstat[row*2] = mx; g_rowstat[row*2+1] = 1.0f / sum;
#endif
}

// =====================================================================
// FLASH pass 2: recompute S, softmax, P·V in TMEM
// grid (16 m-tiles, 28 z), 256 threads.
// TMEM: S cols 0..127, O cols 128..191 (alloc 256)
// =====================================================================
#define FL_SMEM (1024 + 163840 + 64 + 1088)

__global__ void __launch_bounds__(256, 1)
attn_flash()
{
#if HAS_TC
    extern __shared__ char sm[];
    uint32_t raw = smem_u32(sm);
    uint32_t base = (raw + 1023) & ~1023u;
    char* sb = sm + (base - raw);
    const uint32_t off_Qh = 0, off_Ql = 16384, off_Kh = 32768, off_Kl = 49152;
    const uint32_t off_Vh = 65536, off_Vl = 81920, off_Ph = 98304, off_Pl = 131072;
    uint32_t ctrl = base + 163840;
    uint32_t mbar_s = ctrl + 8;
    uint32_t mbar_o = ctrl + 16;
    float* sst = (float*)(sb + 163840 + 64);

    int t = threadIdx.x;
    int z = blockIdx.y;
    int b = z / HEADS, h = z - b*HEADS;
    int m0 = blockIdx.x * 128;

    if (t == 0) { MBARRIER_INIT(mbar_s, 1); MBARRIER_INIT(mbar_o, 1); }
    if (t < 32) { TCGEN05_ALLOC(ctrl, 256); TCGEN05_RELINQ(); }
    sst[t] = g_rowstat[(size_t)(z*NN + m0)*2 + t];
    __syncthreads();
    uint32_t tmem;
    asm volatile("ld.shared.b32 %0, [%1];" : "=r"(tmem) : "r"(ctrl));
    uint32_t tmemO = tmem + 128;

    const __nv_bfloat16* pQh = g_qh + ((size_t)(b*NN) + m0)*CO + h*32;
    const __nv_bfloat16* pQl = g_ql + ((size_t)(b*NN) + m0)*CO + h*32;
    const __nv_bfloat16* pKh = g_kh + ((size_t)b*NN)*CO + h*32;
    const __nv_bfloat16* pKl = g_kl + ((size_t)b*NN)*CO + h*32;
    const __nv_bfloat16* Vh = g_vth + (size_t)z*WCH*NN;
    const __nv_bfloat16* Vl = g_vtl + (size_t)z*WCH*NN;

    int rb = t >> 4, kq = t & 15;
#pragma unroll
    for (int i = 0; i < 8; i++) {
        int r = rb + i*16;
        uint32_t so = swz((uint32_t)(r*128 + kq*8));
        *(uint2*)(sb + off_Qh + so) = *(const uint2*)(pQh + (size_t)r*CO + kq*4);
        *(uint2*)(sb + off_Ql + so) = *(const uint2*)(pQl + (size_t)r*CO + kq*4);
    }

    uint64_t dQh = make_desc(base + off_Qh);
    uint64_t dQl = make_desc(base + off_Ql);
    uint64_t dKh = make_desc(base + off_Kh);
    uint64_t dKl = make_desc(base + off_Kl);

    int w = t >> 5, lane = t & 31;
    int sub = w & 3, half = w >> 2;
    int rrow = sub*32 + lane;
    float mxr = sst[rrow*2], invr = sst[rrow*2+1];

    for (int nc = 0; nc < 16; nc++) {
        int n0 = nc*128;
        if (nc > 0) MBARRIER_WAIT_PARITY(mbar_o, (nc-1) & 1);

#pragma unroll
        for (int i = 0; i < 8; i++) {
            int r = rb + i*16;
            uint32_t so = swz((uint32_t)(r*128 + kq*8));
            *(uint2*)(sb + off_Kh + so) = *(const uint2*)(pKh + (size_t)(n0+r)*CO + kq*4);
            *(uint2*)(sb + off_Kl + so) = *(const uint2*)(pKl + (size_t)(n0+r)*CO + kq*4);
        }
#pragma unroll
        for (int i = 0; i < 4; i++) {
            int r = rb + i*16;
            uint32_t so = swz((uint32_t)(r*128 + kq*8));
#pragma unroll
            for (int j = 0; j < 2; j++) {
                size_t gk = (size_t)r*NN + n0 + j*64 + kq*4;
                *(uint2*)(sb + off_Vh + j*8192 + so) = *(const uint2*)(Vh + gk);
                *(uint2*)(sb + off_Vl + j*8192 + so) = *(const uint2*)(Vl + gk);
            }
        }
        __syncthreads();

        // S = Q K^T (fresh accumulator each chunk)
        if (t < 32) {
            if (elect_one_pred()) {
                FENCE_ASYNC_SHARED();
#pragma unroll
                for (int ks = 0; ks < 4; ks++) {
                    uint64_t o = ks*2;
                    mma_f16_ss(tmem, dQh+o, dKh+o, IDESC_N128, (ks > 0) ? 1u : 0u);
                    mma_f16_ss(tmem, dQh+o, dKl+o, IDESC_N128, 1u);
                    mma_f16_ss(tmem, dQl+o, dKh+o, IDESC_N128, 1u);
                }
                TCGEN05_COMMIT(mbar_s);
            }
        }
        MBARRIER_WAIT_PARITY(mbar_s, nc & 1);
        TCGEN05_FENCE_AFTER();

#pragma unroll
        for (int gi = 0; gi < 2; gi++) {
            int g = half*2 + gi;
            uint32_t r[32];
            TCGEN05_LD_X32(r, tmem + g*32);
            TCGEN05_WAIT_LD();
#pragma unroll
            for (int j = 0; j < 8; j++) {
                float v0 = __expf(__uint_as_float(r[j*4+0]) - mxr) * invr;
                float v1 = __expf(__uint_as_float(r[j*4+1]) - mxr) * invr;
                float v2 = __expf(__uint_as_float(r[j*4+2]) - mxr) * invr;
                float v3 = __expf(__uint_as_float(r[j*4+3]) - mxr) * invr;
                __nv_bfloat16 h0 = __float2bfloat16(v0);
                __nv_bfloat16 h1 = __float2bfloat16(v1);
                __nv_bfloat16 h2 = __float2bfloat16(v2);
                __nv_bfloat16 h3 = __float2bfloat16(v3);
                uint32_t so = swz((uint32_t)(rrow*128 + (gi*32 + j*4)*2));
                *(uint2*)(sb + off_Ph + half*16384 + so) = make_uint2(bpackh(h0,h1), bpackh(h2,h3));
                *(uint2*)(sb + off_Pl + half*16384 + so) = make_uint2(
                    bpackh(__float2bfloat16(v0 - __bfloat162float(h0)),
                           __float2bfloat16(v1 - __bfloat162float(h1))),
                    bpackh(__float2bfloat16(v2 - __bfloat162float(h2)),
                           __float2bfloat16(v3 - __bfloat162float(h3))));
            }
        }
        __syncthreads();

        // O += P V^T
        if (t < 32) {
            if (elect_one_pred()) {
                FENCE_ASYNC_SHARED();
#pragma unroll
                for (int kch = 0; kch < 2; kch++) {
                    uint64_t dPh = make_desc(base + off_Ph + kch*16384);
                    uint64_t dPl = make_desc(base + off_Pl + kch*16384);
                    uint64_t dVh2 = make_desc(base + off_Vh + kch*8192);
                    uint64_t dVl2 = make_desc(base + off_Vl + kch*8192);
#pragma unroll
                    for (int ks = 0; ks < 4; ks++) {
                        uint64_t o = ks*2;
                        mma_f16_ss(tmemO, dPh+o, dVh2+o, IDESC_N64,
                                   (nc > 0 || kch > 0 || ks > 0) ? 1u : 0u);
                        mma_f16_ss(tmemO, dPh+o, dVl2+o, IDESC_N64, 1u);
                        mma_f16_ss(tmemO, dPl+o, dVh2+o, IDESC_N64, 1u);
                    }
                }
                TCGEN05_COMMIT(mbar_o);
            }
        }
    }
    MBARRIER_WAIT_PARITY(mbar_o, 1);
    TCGEN05_FENCE_AFTER();

    size_t rbase = (size_t)(b*NN + m0 + rrow)*FUSC + h*64 + half*32;
    {
        uint32_t r[32];
        TCGEN05_LD_X32(r, tmemO + half*32);
        TCGEN05_WAIT_LD();
        TCGEN05_FENCE_BEFORE();
#pragma unroll
        for (int j = 0; j < 8; j++) {
            float v0 = __uint_as_float(r[j*4+0]);
            float v1 = __uint_as_float(r[j*4+1]);
            float v2 = __uint_as_float(r[j*4+2]);
            float v3 = __uint_as_float(r[j*4+3]);
            __nv_bfloat16 h0 = __float2bfloat16(v0);
            __nv_bfloat16 h1 = __float2bfloat16(v1);
            __nv_bfloat16 h2 = __float2bfloat16(v2);
            __nv_bfloat16 h3 = __float2bfloat16(v3);
            *(uint2*)(g_Oh + rbase + j*4) = make_uint2(bpackh(h0,h1), bpackh(h2,h3));
            *(uint2*)(g_Ol + rbase + j*4) = make_uint2(
                bpackh(__float2bfloat16(v0 - __bfloat162float(h0)),
                       __float2bfloat16(v1 - __bfloat162float(h1))),
                bpackh(__float2bfloat16(v2 - __bfloat162float(h2)),
                       __float2bfloat16(v3 - __bfloat162float(h3))));
        }
    }
    __syncthreads();
    if (t < 32) TCGEN05_DEALLOC(tmem, 256);
#else
    int t = threadIdx.x;
    int z = blockIdx.y;
    int b = z / HEADS, h = z - b*HEADS;
    int m0 = blockIdx.x * 128;
    if (t >= 128) return;
    int m = m0 + t;
    const float* qp = g_q + ((size_t)(b*NN) + m)*CO + h*32;
    float mxr = g_rowstat[(size_t)(z*NN + m)*2], invr = g_rowstat[(size_t)(z*NN + m)*2+1];
    for (int c = 0; c < 64; c++) {
        float acc = 0.0f;
        for (int n = 0; n < NN; n++) {
            const float* kp = g_k + ((size_t)(b*NN) + n)*CO + h*32;
            float s = 0.0f;
            for (int k = 0; k < 64; k++) s = fmaf(qp[k], kp[k], s);
            acc = fmaf(__expf(s - mxr)*invr, g_v[((size_t)(b*NN) + n)*CO + h*32 + c], acc);
        }
        size_t o = (size_t)(b*NN + m)*FUSC + h*64 + c;
        __nv_bfloat16 hb = __float2bfloat16(acc);
        g_Oh[o] = hb;
        g_Ol[o] = __float2bfloat16(acc - __bfloat162float(hb));
    }
#endif
}

// =====================================================================
// LayerNorm -> bf16 split
// =====================================================================
__global__ void layernorm_kernel(const float* __restrict__ X,
                                 const float* __restrict__ g, const float* __restrict__ b)
{
    int m = blockIdx.x, c = threadIdx.x;
    __shared__ float red[256];
    float v = X[(size_t)m*CO + c];
    red[c] = v; __syncthreads();
    for (int s = 128; s; s >>= 1) { if (c < s) red[c] += red[c+s]; __syncthreads(); }
    float mean = red[0] * (1.0f/CO); __syncthreads();
    float d = v - mean;
    red[c] = d*d; __syncthreads();
    for (int s = 128; s; s >>= 1) { if (c < s) red[c] += red[c+s]; __syncthreads(); }
    float var = red[0] * (1.0f/CO);
    float y = d * rsqrtf(var + EPSB) * g[c] + b[c];
    __nv_bfloat16 hb = __float2bfloat16(y);
    size_t i = (size_t)m*CO + c;
    g_yh[i] = hb;
    g_yl[i] = __float2bfloat16(y - __bfloat162float(hb));
}

// =====================================================================
// final output (transposed)
// =====================================================================
__global__ void final_out(const float* __restrict__ bias, float* __restrict__ out)
{
    __shared__ float tile[32][33];
    int b  = blockIdx.z;
    int n0 = blockIdx.x * 32;
    int c0 = blockIdx.y * 32;
    int tx = threadIdx.x, ty = threadIdx.y;
#pragma unroll
    for (int i = 0; i < 32; i += 8) {
        int n = n0 + ty + i, c = c0 + tx;
        size_t src = ((size_t)b*NN + n)*CO + c;
        tile[ty+i][tx] = g_f2[src] + g_fp[src] + bias[c];
    }
    __syncthreads();
#pragma unroll
    for (int i = 0; i < 32; i += 8) {
        int c = c0 + ty + i, n = n0 + tx;
        out[((size_t)b*CO + c)*NN + n] = tile[tx][ty+i];
    }
}

// =====================================================================
// host
// =====================================================================
extern "C" void kernel_launch(void* const* d_in, const int* in_sizes, int n_in,
                              void* d_out, int out_size)
{
    const float* xyz    = (const float*)d_in[0];
    const float* f      = (const float*)d_in[1];
    const float* W_geo  = (const float*)d_in[2];
    const float* gg     = (const float*)d_in[3];
    const float* bg     = (const float*)d_in[4];
    const float* W_feat = (const float*)d_in[5];
    const float* gf     = (const float*)d_in[6];
    const float* bf     = (const float*)d_in[7];
    const float* g_bn   = (const float*)d_in[8];
    const float* b_bn   = (const float*)d_in[9];
    const float* W_q    = (const float*)d_in[10];
    const float* gq     = (const float*)d_in[11];
    const float* bq     = (const float*)d_in[12];
    const float* W_k    = (const float*)d_in[13];
    const float* gk     = (const float*)d_in[14];
    const float* bk     = (const float*)d_in[15];
    const float* W_v    = (const float*)d_in[16];
    const float* gv     = (const float*)d_in[17];
    const float* bv     = (const float*)d_in[18];
    const float* W_fus  = (const float*)d_in[19];
    /* d_in[20] bias_fus: cancels inside BN */
    const float* gfu    = (const float*)d_in[21];
    const float* bfu    = (const float*)d_in[22];
    const float* g_ln   = (const float*)d_in[23];
    const float* b_ln   = (const float*)d_in[24];
    const float* W_mlp  = (const float*)d_in[25];
    const float* b_mlp  = (const float*)d_in[26];
    float* out = (float*)d_out;

    float *p_featv, *p_fp, *p_f2, *p_msc;
    __nv_bfloat16 *p_yh, *p_yl, *p_Oh, *p_Ol, *p_xh, *p_xl;
    __nv_bfloat16 *p_wfush, *p_wfusl, *p_wmh, *p_wml;
    cudaGetSymbolAddress((void**)&p_featv, g_featv);
    cudaGetSymbolAddress((void**)&p_fp,    g_fp);
    cudaGetSymbolAddress((void**)&p_f2,    g_f2);
    cudaGetSymbolAddress((void**)&p_msc,   g_msc);
    cudaGetSymbolAddress((void**)&p_xh,    g_xh);
    cudaGetSymbolAddress((void**)&p_xl,    g_xl);
    cudaGetSymbolAddress((void**)&p_yh,    g_yh);
    cudaGetSymbolAddress((void**)&p_yl,    g_yl);
    cudaGetSymbolAddress((void**)&p_Oh,    g_Oh);
    cudaGetSymbolAddress((void**)&p_Ol,    g_Ol);
    cudaGetSymbolAddress((void**)&p_wfush, g_wfush);
    cudaGetSymbolAddress((void**)&p_wfusl, g_wfusl);
    cudaGetSymbolAddress((void**)&p_wmh,   g_wmh);
    cudaGetSymbolAddress((void**)&p_wml,   g_wml);

    cudaFuncSetAttribute(attn_stats, cudaFuncAttributeMaxDynamicSharedMemorySize, ST_SMEM);
    cudaFuncSetAttribute(attn_flash, cudaFuncAttributeMaxDynamicSharedMemorySize, FL_SMEM);
    cudaFuncSetAttribute(tgemm,      cudaFuncAttributeMaxDynamicSharedMemorySize, TG_SMEM);
    cudaFuncSetAttribute(qkv_gemm,   cudaFuncAttributeMaxDynamicSharedMemorySize, TG_SMEM);
    cudaFuncSetAttribute(feat_gemm,  cudaFuncAttributeMaxDynamicSharedMemorySize, FEAT_SMEM);

    // ---- 0. weight splits
    split_weights<<<1536, 256>>>(W_feat, W_q, W_k, W_v, W_fus, W_mlp);

    // ---- 1. KNN + transpose + geo (max/min + fused stats)
    knn_kernel<<<MTOT, 256>>>(xyz);
    transpose_f<<<dim3(NN/32, CIN/32, BB), dim3(32,8)>>>(f);
    geo_pre<<<NGEOREG, 128>>>(xyz, W_geo);

    // ---- 2. feat GEMM (inline gather; epilogue -> max/min partials + stats)
    feat_gemm<<<dim3(1, NFEATCTA), 256, FEAT_SMEM>>>();

    // ---- 3. act stats (hierarchical combines) + branch apply
    act_combine<<<128, 128>>>();
    bn_stats_act<<<1, 256>>>(p_msc + 0*512);
    branch_apply<<<MTOT, 256>>>(p_msc + 0*512, gg, bg, gf, bf);

    // ---- 4. BatchNorm1d -> x split
    bn_stats_partial<<<32, 256>>>(p_featv, MTOT);
    bn_stats_final<<<1, 256>>>(32, MTOT, p_msc + 1*512);
    bn_apply_split<<<MTOT, 256>>>(p_featv, p_msc + 1*512, g_bn, b_bn, 0, p_xh, p_xl);

    // ---- 5. q/k/v merged GEMM + stats + apply
    qkv_gemm<<<dim3(2, MTOT/128, 3), 256, TG_SMEM>>>();
    bn_stats_qkv<<<dim3(64, 3), 256>>>();
    bn_final_qkv<<<3, 256>>>(p_msc);
    bn_apply_qkv<<<dim3(MTOT*CO/256, 3), 256>>>(p_msc, gq, bq, gk, bk, gv, bv);
    vt_convert<<<dim3(NN/32, 2, BB*HEADS), dim3(32,8)>>>();

    // ---- 6. flash attention (two kernels, no prefetch — measured best)
    attn_stats<<<dim3(16, BB*HEADS), 256, ST_SMEM>>>();
    attn_flash<<<dim3(16, BB*HEADS), 256, FL_SMEM>>>();

    // ---- 7. fus + residual
    tgemm<<<dim3(2, MTOT/128), 256, TG_SMEM>>>(p_Oh, p_Ol, p_wfush, p_wfusl,
                                               p_fp, FUSC, FUSC, CO, 7);
    bn_stats_partial<<<32, 256>>>(p_fp, MTOT);
    bn_stats_final<<<1, 256>>>(32, MTOT, p_msc + 5*512);
    bn_apply<<<MTOT, 256>>>(p_fp, p_f2, p_msc + 5*512, gfu, bfu, p_featv, 1);

    // ---- 8. layernorm + mlp + out
    layernorm_kernel<<<MTOT, 256>>>(p_f2, g_ln, b_ln);
    tgemm<<<dim3(2, MTOT/128), 256, TG_SMEM>>>(p_yh, p_yl, p_wmh, p_wml, p_fp, CO, CO, CO, 4);
    final_out<<<dim3(NN/32, CO/32, BB), dim3(32,8)>>>(b_mlp, out);

    (void)in_sizes; (void)n_in; (void)out_size;
}

// round 17
// speedup vs baseline: 1.7780x; 1.0639x over previous
#include <cuda_runtime.h>
#include <cuda_bf16.h>
#include <cfloat>
#include <math.h>
#include <cstdint>

#if defined(__CUDA_ARCH__) && defined(__CUDA_ARCH_FEAT_SM103_ALL)
#define HAS_TC 1
#else
#define HAS_TC 0
#endif

// ---------------- problem constants ----------------
#define BB    4
#define NN    2048
#define KNB   21
#define CIN   64
#define CO    256
#define HEADS 7
#define WCH   64
#define FUSC  (HEADS*WCH)          /* 448 */
#define MTOT  (BB*NN)              /* 8192 */
#define RTOT  (MTOT*KNB)           /* 172032 */
#define EPSB  1e-5f
#define NGEOREG  2048
#define NFEATCTA (RTOT/128)        /* 1344 */

// ---------------- scratch ----------------
__device__ int    g_idx[RTOT];
__device__ float  g_ft[MTOT*CIN];
__device__ float  g_zmx[MTOT*128];                   // geo pre-BN max over k
__device__ float  g_zmn[MTOT*128];                   // geo pre-BN min over k
__device__ float  g_fmx[(size_t)NFEATCTA*8*128];     // feat per-tile/point max
__device__ float  g_fmn[(size_t)NFEATCTA*8*128];     // feat per-tile/point min
__device__ float  g_featv[MTOT*CO];
__device__ float  g_q[MTOT*CO];
__device__ float  g_k[MTOT*CO];
__device__ float  g_v[MTOT*CO];
__device__ float  g_rowstat[BB*HEADS*NN*2];
__device__ float  g_fp[MTOT*CO];
__device__ float  g_f2[MTOT*CO];
__device__ float  g_partf[256*2*CO];
__device__ float  g_msc[6*2*CO];
__device__ float  g_geo_part[(size_t)NGEOREG*256];   // [region]{sum[128]|sq[128]}
__device__ float  g_feat_part[(size_t)NFEATCTA*256];
__device__ float  g_geo_c[64*256];
__device__ float  g_feat_c[64*256];
// bf16 hi/lo splits
__device__ __nv_bfloat16 g_xh[MTOT*CO],  g_xl[MTOT*CO];
__device__ __nv_bfloat16 g_qh[MTOT*CO],  g_ql[MTOT*CO];
__device__ __nv_bfloat16 g_kh[MTOT*CO],  g_kl[MTOT*CO];
__device__ __nv_bfloat16 g_yh[MTOT*CO],  g_yl[MTOT*CO];
__device__ __nv_bfloat16 g_Oh[MTOT*FUSC], g_Ol[MTOT*FUSC];
__device__ __nv_bfloat16 g_vth[(size_t)BB*HEADS*WCH*NN], g_vtl[(size_t)BB*HEADS*WCH*NN];
__device__ __nv_bfloat16 g_wfh[128*128],  g_wfl[128*128];
__device__ __nv_bfloat16 g_wqh[CO*CO],    g_wql[CO*CO];
__device__ __nv_bfloat16 g_wkh[CO*CO],    g_wkl[CO*CO];
__device__ __nv_bfloat16 g_wvh[CO*CO],    g_wvl[CO*CO];
__device__ __nv_bfloat16 g_wfush[CO*FUSC],g_wfusl[CO*FUSC];
__device__ __nv_bfloat16 g_wmh[CO*CO],    g_wml[CO*CO];

// ---------------- helpers ----------------
__device__ __forceinline__ uint32_t smem_u32(const void* p) {
    uint32_t a;
    asm("{ .reg .u64 t; cvta.to.shared.u64 t, %1; cvt.u32.u64 %0, t; }" : "=r"(a) : "l"(p));
    return a;
}
__device__ __forceinline__ uint32_t swz(uint32_t o) { return o ^ ((o >> 3) & 0x70); }
__device__ __forceinline__ uint32_t bpackh(__nv_bfloat16 a, __nv_bfloat16 b) {
    __nv_bfloat162 t = __halves2bfloat162(a, b);
    return *reinterpret_cast<uint32_t*>(&t);
}

#if HAS_TC
__device__ __forceinline__ uint32_t elect_one_pred() {
    uint32_t pred;
    asm volatile("{\n\t.reg .pred p;\n\telect.sync _|p, 0xFFFFFFFF;\n\tselp.b32 %0, 1, 0, p;\n\t}" : "=r"(pred));
    return pred;
}

#define MBARRIER_INIT(addr, cnt) \
    asm volatile("mbarrier.init.shared.b64 [%0], %1;" :: "r"((uint32_t)(addr)), "r"((uint32_t)(cnt)) : "memory")

#define MBARRIER_WAIT_PARITY(mbar_smem_addr, phase_parity) do { \
    uint32_t _mbar = (uint32_t)(mbar_smem_addr); \
    uint32_t _parity = (uint32_t)(phase_parity); \
    uint32_t _done; \
    asm volatile("{\n\t.reg .pred p;\n\t" \
        "mbarrier.try_wait.parity.acquire.cta.shared::cta.b64 p, [%1], %2;\n\t" \
        "selp.b32 %0, 1, 0, p;\n\t}" : "=r"(_done) : "r"(_mbar), "r"(_parity) : "memory"); \
    if (!_done) { \
        asm volatile("{\n\t.reg .pred P1;\n\t" \
            "WAIT_LOOP_%=:\n\t" \
            "mbarrier.try_wait.parity.acquire.cta.shared::cta.b64 P1, [%0], %1, 0x989680;\n\t" \
            "@P1 bra.uni WAIT_DONE_%=;\n\t" \
            "bra.uni WAIT_LOOP_%=;\n\t" \
            "WAIT_DONE_%=:\n\t}" :: "r"(_mbar), "r"(_parity) : "memory"); \
    } \
} while(0)

#define TCGEN05_ALLOC(sm, n) \
    asm volatile("tcgen05.alloc.cta_group::1.sync.aligned.shared::cta.b32 [%0], %1;" \
                 :: "r"((uint32_t)(sm)), "r"((uint32_t)(n)) : "memory")
#define TCGEN05_RELINQ() \
    asm volatile("tcgen05.relinquish_alloc_permit.cta_group::1.sync.aligned;")
#define TCGEN05_DEALLOC(t, n) \
    asm volatile("tcgen05.dealloc.cta_group::1.sync.aligned.b32 %0, %1;" :: "r"(t), "r"(n))
#define TCGEN05_COMMIT(mbar) \
    asm volatile("tcgen05.commit.cta_group::1.mbarrier::arrive::one.shared::cluster.b64 [%0];" \
                 :: "r"((uint32_t)(mbar)) : "memory")
#define TCGEN05_FENCE_AFTER()  asm volatile("tcgen05.fence::after_thread_sync;" ::: "memory")
#define TCGEN05_FENCE_BEFORE() asm volatile("tcgen05.fence::before_thread_sync;" ::: "memory")
#define TCGEN05_WAIT_LD()      asm volatile("tcgen05.wait::ld.sync.aligned;" ::: "memory")
#define FENCE_ASYNC_SHARED()   asm volatile("fence.proxy.async.shared::cta;" ::: "memory")

#define TCGEN05_LD_X32(r, addr) \
    asm volatile("tcgen05.ld.sync.aligned.32x32b.x32.b32 " \
        "{%0, %1, %2, %3, %4, %5, %6, %7, %8, %9, %10, %11, %12, %13, %14, %15, " \
        " %16, %17, %18, %19, %20, %21, %22, %23, %24, %25, %26, %27, %28, %29, %30, %31}, [%32];" \
        : "=r"((r)[0]),  "=r"((r)[1]),  "=r"((r)[2]),  "=r"((r)[3]), \
          "=r"((r)[4]),  "=r"((r)[5]),  "=r"((r)[6]),  "=r"((r)[7]), \
          "=r"((r)[8]),  "=r"((r)[9]),  "=r"((r)[10]), "=r"((r)[11]), \
          "=r"((r)[12]), "=r"((r)[13]), "=r"((r)[14]), "=r"((r)[15]), \
          "=r"((r)[16]), "=r"((r)[17]), "=r"((r)[18]), "=r"((r)[19]), \
          "=r"((r)[20]), "=r"((r)[21]), "=r"((r)[22]), "=r"((r)[23]), \
          "=r"((r)[24]), "=r"((r)[25]), "=r"((r)[26]), "=r"((r)[27]), \
          "=r"((r)[28]), "=r"((r)[29]), "=r"((r)[30]), "=r"((r)[31]) \
        : "r"(addr))

static __device__ __forceinline__ uint64_t make_desc(uint32_t addr) {
    const uint64_t base =
        (uint64_t(2) << 61) | (uint64_t(1) << 46) | (uint64_t(64) << 32) | (uint64_t(1) << 16);
    return base | ((uint64_t)(addr >> 4) & 0x3FFF);
}

__device__ __forceinline__ void mma_f16_ss(uint32_t d, uint64_t a, uint64_t b,
                                           uint32_t idesc, uint32_t en) {
    asm volatile(
        "{\n\t.reg .pred p;\n\tsetp.ne.u32 p, %5, 0;\n\t"
        "tcgen05.mma.cta_group::1.kind::f16 [%0], %1, %2, %3, {%4, %4, %4, %4}, p;\n\t}"
        :: "r"(d), "l"(a), "l"(b), "r"(idesc), "r"(0u), "r"(en) : "memory");
}

#define IDESC_N128 ((1u<<4)|(1u<<7)|(1u<<10)|((128u/8)<<17)|((128u/16)<<24))
#define IDESC_N64  ((1u<<4)|(1u<<7)|(1u<<10)|(( 64u/8)<<17)|((128u/16)<<24))

// ---- tensor-GEMM core (no register prefetch — measured best) ----
__device__ __forceinline__ void tgemm_core(char* sb, uint32_t base,
    const __nv_bfloat16* __restrict__ Ah, const __nv_bfloat16* __restrict__ Al,
    const __nv_bfloat16* __restrict__ Bh, const __nv_bfloat16* __restrict__ Bl,
    float* __restrict__ C, int lda, int ldb, int ldc, int nkc, int m0, int n0)
{
    uint32_t ctrl = base + 65536;
    uint32_t mbar = ctrl + 8;
    int t = threadIdx.x;

    if (t == 0) MBARRIER_INIT(mbar, 1);
    if (t < 32) { TCGEN05_ALLOC(ctrl, 128); TCGEN05_RELINQ(); }
    __syncthreads();
    uint32_t tmem;
    asm volatile("ld.shared.b32 %0, [%1];" : "=r"(tmem) : "r"(ctrl));

    Ah += (size_t)m0 * lda; Al += (size_t)m0 * lda;
    Bh += (size_t)n0 * ldb; Bl += (size_t)n0 * ldb;

    uint64_t dAh = make_desc(base + 0*16384);
    uint64_t dAl = make_desc(base + 1*16384);
    uint64_t dBh = make_desc(base + 2*16384);
    uint64_t dBl = make_desc(base + 3*16384);

    int rb = t >> 4, kq = t & 15;

    for (int kc = 0; kc < nkc; kc++) {
        if (kc > 0) MBARRIER_WAIT_PARITY(mbar, (kc-1) & 1);
        int k0 = kc*64;
#pragma unroll
        for (int i = 0; i < 8; i++) {
            int r = rb + i*16;
            uint32_t so = swz((uint32_t)(r*128 + kq*8));
            *(uint2*)(sb + 0*16384 + so) = *(const uint2*)(Ah + (size_t)r*lda + k0 + kq*4);
            *(uint2*)(sb + 1*16384 + so) = *(const uint2*)(Al + (size_t)r*lda + k0 + kq*4);
            *(uint2*)(sb + 2*16384 + so) = *(const uint2*)(Bh + (size_t)r*ldb + k0 + kq*4);
            *(uint2*)(sb + 3*16384 + so) = *(const uint2*)(Bl + (size_t)r*ldb + k0 + kq*4);
        }
        __syncthreads();
        if (t < 32) {
            if (elect_one_pred()) {
                FENCE_ASYNC_SHARED();
#pragma unroll
                for (int ks = 0; ks < 4; ks++) {
                    uint64_t o = ks*2;
                    mma_f16_ss(tmem, dAh+o, dBh+o, IDESC_N128, (kc > 0 || ks > 0) ? 1u : 0u);
                    mma_f16_ss(tmem, dAh+o, dBl+o, IDESC_N128, 1u);
                    mma_f16_ss(tmem, dAl+o, dBh+o, IDESC_N128, 1u);
                }
                TCGEN05_COMMIT(mbar);
            }
        }
    }
    MBARRIER_WAIT_PARITY(mbar, (nkc-1) & 1);
    TCGEN05_FENCE_AFTER();

    int w = t >> 5, lane = t & 31;
    int sub = w & 3, half = w >> 2;
    float* Crow = C + (size_t)(m0 + sub*32 + lane)*ldc + n0;
#pragma unroll
    for (int gi = 0; gi < 2; gi++) {
        int g = half*2 + gi;
        uint32_t r[32];
        TCGEN05_LD_X32(r, tmem + g*32);
        TCGEN05_WAIT_LD();
        TCGEN05_FENCE_BEFORE();
#pragma unroll
        for (int j = 0; j < 8; j++)
            *(float4*)(Crow + g*32 + j*4) = make_float4(
                __uint_as_float(r[j*4+0]), __uint_as_float(r[j*4+1]),
                __uint_as_float(r[j*4+2]), __uint_as_float(r[j*4+3]));
    }
    __syncthreads();
    if (t < 32) TCGEN05_DEALLOC(tmem, 128);
}
#else
__device__ __forceinline__ void tgemm_core_simt(
    const __nv_bfloat16* Ah, const __nv_bfloat16* Al,
    const __nv_bfloat16* Bh, const __nv_bfloat16* Bl,
    float* C, int lda, int ldb, int ldc, int nkc, int m0, int n0)
{
    int t = threadIdx.x;
    int m = m0 + (t >> 1);
    int nb = (t & 1) * 64;
    for (int n = nb; n < nb + 64; n++) {
        float acc = 0.0f;
        for (int k = 0; k < nkc*64; k++) {
            float a = __bfloat162float(Ah[(size_t)m*lda+k]) + __bfloat162float(Al[(size_t)m*lda+k]);
            float b = __bfloat162float(Bh[(size_t)(n0+n)*ldb+k]) + __bfloat162float(Bl[(size_t)(n0+n)*ldb+k]);
            acc = fmaf(a, b, acc);
        }
        C[(size_t)m*ldc + n0 + n] = acc;
    }
}
#endif // HAS_TC

#define TG_SMEM (1024 + 4*16384 + 64)

// =====================================================================
// KNN — register-resident distances, shuffle reduction, 2 syncs/iter
// =====================================================================
__global__ void knn_kernel(const float* __restrict__ xyz)
{
    __shared__ float wv[8];
    __shared__ int   wi[8];
    __shared__ int   s_win;
    int m = blockIdx.x;
    int b = m >> 11;
    int t = threadIdx.x;
    int lane = t & 31, warp = t >> 5;
    const float* base = xyz + (size_t)(b << 11) * 3;

    float qx = xyz[m*3+0], qy = xyz[m*3+1], qz = xyz[m*3+2];
    float sqq = qx*qx + qy*qy + qz*qz;

    float d[8];
#pragma unroll
    for (int i = 0; i < 8; i++) {
        int j = t + i*256;
        float px = base[j*3+0], py = base[j*3+1], pz = base[j*3+2];
        float sqp = px*px + py*py + pz*pz;
        float dot = qx*px + qy*py + qz*pz;
        d[i] = sqq + sqp - 2.0f*dot;
    }

    for (int it = 0; it < KNB; it++) {
        // thread-local argmin (ascending i => ascending j; strict < keeps lowest idx)
        float bv = FLT_MAX; int bi = 0x3fffffff;
#pragma unroll
        for (int i = 0; i < 8; i++) {
            if (d[i] < bv) { bv = d[i]; bi = t + i*256; }
        }
        // warp shuffle reduce, tie -> lower index
#pragma unroll
        for (int o = 16; o; o >>= 1) {
            float ov = __shfl_down_sync(0xffffffffu, bv, o);
            int   oi = __shfl_down_sync(0xffffffffu, bi, o);
            if (ov < bv || (ov == bv && oi < bi)) { bv = ov; bi = oi; }
        }
        if (lane == 0) { wv[warp] = bv; wi[warp] = bi; }
        __syncthreads();
        if (t == 0) {
            float fv = wv[0]; int fi = wi[0];
#pragma unroll
            for (int w8 = 1; w8 < 8; w8++) {
                float ov = wv[w8]; int oi = wi[w8];
                if (ov < fv || (ov == fv && oi < fi)) { fv = ov; fi = oi; }
            }
            s_win = fi;
            g_idx[(size_t)m*KNB + it] = fi;
        }
        __syncthreads();
        int win = s_win;
        if ((win & 255) == t) d[win >> 8] = FLT_MAX;   // evict winner
    }
}

// =====================================================================
// transpose f
// =====================================================================
__global__ void transpose_f(const float* __restrict__ f)
{
    __shared__ float tile[32][33];
    int b  = blockIdx.z;
    int n0 = blockIdx.x * 32;
    int c0 = blockIdx.y * 32;
    int tx = threadIdx.x, ty = threadIdx.y;
#pragma unroll
    for (int i = 0; i < 32; i += 8)
        tile[ty+i][tx] = f[((size_t)b*CIN + c0 + ty + i)*NN + n0 + tx];
    __syncthreads();
#pragma unroll
    for (int i = 0; i < 32; i += 8)
        g_ft[((size_t)b*NN + n0 + ty + i)*CIN + c0 + tx] = tile[tx][ty+i];
}

// =====================================================================
// geo pre-activation: store only max/min over k + fused stat partials
// =====================================================================
__global__ void geo_pre(const float* __restrict__ xyz, const float* __restrict__ Wg)
{
    __shared__ float nb3[KNB*3];
    int region = blockIdx.x;
    int c = threadIdx.x;
    float w0 = Wg[c*6+0], w1 = Wg[c*6+1], w2 = Wg[c*6+2];
    float w3 = Wg[c*6+3], w4 = Wg[c*6+4], w5 = Wg[c*6+5];
    float s = 0.0f, s2 = 0.0f;

    for (int p = 0; p < 4; p++) {
        int m = region*4 + p;
        int b = m >> 11;
        __syncthreads();
        if (c < KNB) {
            int nb = g_idx[(size_t)m*KNB + c];
            const float* pp = xyz + (size_t)((b << 11) + nb)*3;
            nb3[c*3+0] = pp[0]; nb3[c*3+1] = pp[1]; nb3[c*3+2] = pp[2];
        }
        __syncthreads();
        float cx = xyz[m*3+0], cy = xyz[m*3+1], cz = xyz[m*3+2];
        float base = w0*cx + w1*cy + w2*cz;
        float mx = -FLT_MAX, mn = FLT_MAX;
#pragma unroll 3
        for (int k = 0; k < KNB; k++) {
            float dx = nb3[k*3+0]-cx, dy = nb3[k*3+1]-cy, dz = nb3[k*3+2]-cz;
            float z = base + w3*dx + w4*dy + w5*dz;
            s += z; s2 = fmaf(z, z, s2);
            mx = fmaxf(mx, z); mn = fminf(mn, z);
        }
        g_zmx[(size_t)m*128 + c] = mx;
        g_zmn[(size_t)m*128 + c] = mn;
    }
    g_geo_part[(size_t)region*256 + c]       = s;
    g_geo_part[(size_t)region*256 + 128 + c] = s2;
}

// merged partial combine: blocks 0..63 geo (32 regions each),
// blocks 64..127 feat (21 tiles each)
__global__ void act_combine()
{
    int c = threadIdx.x;
    int blk = blockIdx.x;
    float s = 0.0f, s2 = 0.0f;
    if (blk < 64) {
        for (int r = blk*32; r < blk*32 + 32; r++) {
            s  += g_geo_part[(size_t)r*256 + c];
            s2 += g_geo_part[(size_t)r*256 + 128 + c];
        }
        g_geo_c[blk*256 + c]       = s;
        g_geo_c[blk*256 + 128 + c] = s2;
    } else {
        int fb = blk - 64;
        for (int r = fb*21; r < fb*21 + 21; r++) {
            s  += g_feat_part[(size_t)r*256 + c];
            s2 += g_feat_part[(size_t)r*256 + 128 + c];
        }
        g_feat_c[fb*256 + c]       = s;
        g_feat_c[fb*256 + 128 + c] = s2;
    }
}

// final act stats combine (double, fixed order)
__global__ void bn_stats_act(float* msc)
{
    int c = threadIdx.x;
    double s = 0.0, s2 = 0.0;
    if (c < 128) {
        for (int r = 0; r < 64; r++) {
            s  += (double)g_geo_c[r*256 + c];
            s2 += (double)g_geo_c[r*256 + 128 + c];
        }
    } else {
        int cc = c - 128;
        for (int r = 0; r < 64; r++) {
            s  += (double)g_feat_c[r*256 + cc];
            s2 += (double)g_feat_c[r*256 + 128 + cc];
        }
    }
    double mean = s / (double)RTOT;
    double var  = s2 / (double)RTOT - mean*mean;
    msc[c]      = (float)mean;
    msc[CO + c] = (float)(1.0 / sqrt(var + (double)EPSB));
}

// =====================================================================
// feat GEMM with INLINE gather+split (g_ft is L2-resident)
// epilogue: stats partials + per-(tile,point) max/min.
// grid (1, NFEATCTA), 256 threads.
// =====================================================================
#define FEAT_SMEM (1024 + 69632 + 64)

__global__ void __launch_bounds__(256, 1)
feat_gemm()
{
#if HAS_TC
    extern __shared__ char sm[];
    uint32_t raw = smem_u32(sm);
    uint32_t base = (raw + 1023) & ~1023u;
    char* sb = sm + (base - raw);
    uint32_t ctrl = base + 69632;
    uint32_t mbar = ctrl + 8;
    int t = threadIdx.x;
    int m0 = blockIdx.y * 128;

    if (t == 0) MBARRIER_INIT(mbar, 1);
    if (t < 32) { TCGEN05_ALLOC(ctrl, 128); TCGEN05_RELINQ(); }
    __syncthreads();
    uint32_t tmem;
    asm volatile("ld.shared.b32 %0, [%1];" : "=r"(tmem) : "r"(ctrl));

    uint64_t dAh = make_desc(base + 0*16384);
    uint64_t dAl = make_desc(base + 1*16384);
    uint64_t dBh = make_desc(base + 2*16384);
    uint64_t dBl = make_desc(base + 3*16384);

    int rb = t >> 4, kq = t & 15;
    for (int kc = 0; kc < 2; kc++) {
        if (kc > 0) MBARRIER_WAIT_PARITY(mbar, 0);
        int k0 = kc*64;
#pragma unroll
        for (int i = 0; i < 8; i++) {
            int r = rb + i*16;
            uint32_t R = (uint32_t)(m0 + r);
            uint32_t m = R / KNB;
            uint32_t b = m >> 11;
            const float* src;
            if (kc == 0) {
                uint32_t nb = (uint32_t)g_idx[R];
                src = g_ft + (size_t)((b << 11) + nb)*CIN + kq*4;
            } else {
                src = g_ft + (size_t)m*CIN + kq*4;
            }
            float4 v = *(const float4*)src;
            __nv_bfloat16 h0 = __float2bfloat16(v.x);
            __nv_bfloat16 h1 = __float2bfloat16(v.y);
            __nv_bfloat16 h2 = __float2bfloat16(v.z);
            __nv_bfloat16 h3 = __float2bfloat16(v.w);
            uint32_t so = swz((uint32_t)(r*128 + kq*8));
            *(uint2*)(sb + 0*16384 + so) = make_uint2(bpackh(h0,h1), bpackh(h2,h3));
            *(uint2*)(sb + 1*16384 + so) = make_uint2(
                bpackh(__float2bfloat16(v.x - __bfloat162float(h0)),
                       __float2bfloat16(v.y - __bfloat162float(h1))),
                bpackh(__float2bfloat16(v.z - __bfloat162float(h2)),
                       __float2bfloat16(v.w - __bfloat162float(h3))));
            *(uint2*)(sb + 2*16384 + so) = *(const uint2*)(g_wfh + (size_t)r*128 + k0 + kq*4);
            *(uint2*)(sb + 3*16384 + so) = *(const uint2*)(g_wfl + (size_t)r*128 + k0 + kq*4);
        }
        __syncthreads();
        if (t < 32) {
            if (elect_one_pred()) {
                FENCE_ASYNC_SHARED();
#pragma unroll
                for (int ks = 0; ks < 4; ks++) {
                    uint64_t o = ks*2;
                    mma_f16_ss(tmem, dAh+o, dBh+o, IDESC_N128, (kc > 0 || ks > 0) ? 1u : 0u);
                    mma_f16_ss(tmem, dAh+o, dBl+o, IDESC_N128, 1u);
                    mma_f16_ss(tmem, dAl+o, dBh+o, IDESC_N128, 1u);
                }
                TCGEN05_COMMIT(mbar);
            }
        }
    }
    MBARRIER_WAIT_PARITY(mbar, 1);
    TCGEN05_FENCE_AFTER();

    int w = t >> 5, lane = t & 31;
    int sub = w & 3, half = w >> 2;
    int row = sub*32 + lane;
    float* stile = (float*)sb;   // [128][132], inputs dead now
#pragma unroll
    for (int gi = 0; gi < 2; gi++) {
        int g = half*2 + gi;
        uint32_t r[32];
        TCGEN05_LD_X32(r, tmem + g*32);
        TCGEN05_WAIT_LD();
        TCGEN05_FENCE_BEFORE();
#pragma unroll
        for (int j = 0; j < 8; j++) {
            float4 v = make_float4(
                __uint_as_float(r[j*4+0]), __uint_as_float(r[j*4+1]),
                __uint_as_float(r[j*4+2]), __uint_as_float(r[j*4+3]));
            *(float4*)(stile + row*132 + g*32 + j*4) = v;
        }
    }
    __syncthreads();
    if (t < 128) {
        float s = 0.0f, q = 0.0f;
        int pfirst = m0 / KNB;
        int pcur = pfirst;
        float mx = -FLT_MAX, mn = FLT_MAX;
        for (int rr = 0; rr < 128; rr++) {
            int p = (m0 + rr) / KNB;
            if (p != pcur) {
                size_t o = ((size_t)blockIdx.y*8 + (pcur - pfirst))*128 + t;
                g_fmx[o] = mx; g_fmn[o] = mn;
                mx = -FLT_MAX; mn = FLT_MAX; pcur = p;
            }
            float v = stile[rr*132 + t];
            s += v; q = fmaf(v, v, q);
            mx = fmaxf(mx, v); mn = fminf(mn, v);
        }
        size_t o = ((size_t)blockIdx.y*8 + (pcur - pfirst))*128 + t;
        g_fmx[o] = mx; g_fmn[o] = mn;
        g_feat_part[(size_t)blockIdx.y*256 + t]       = s;
        g_feat_part[(size_t)blockIdx.y*256 + 128 + t] = q;
    }
    __syncthreads();
    if (t < 32) TCGEN05_DEALLOC(tmem, 128);
#else
    extern __shared__ char sm[];
    float* stile = (float*)sm;   // [128][132]
    int t = threadIdx.x;
    int m0 = blockIdx.y*128;
    {
        int r = t >> 1;
        int R = m0 + r;
        int m = R / KNB;
        int b = m >> 11;
        int nbr = g_idx[R];
        int nb0 = (t & 1) * 64;
        for (int n = nb0; n < nb0 + 64; n++) {
            float acc = 0.0f;
            for (int k = 0; k < 128; k++) {
                float a = (k < 64) ? g_ft[(size_t)((b<<11)+nbr)*CIN + k]
                                   : g_ft[(size_t)m*CIN + (k-64)];
                float bw = __bfloat162float(g_wfh[(size_t)n*128+k]) + __bfloat162float(g_wfl[(size_t)n*128+k]);
                acc = fmaf(a, bw, acc);
            }
            stile[r*132 + n] = acc;
        }
    }
    __syncthreads();
    if (t < 128) {
        float s = 0.0f, q = 0.0f;
        int pfirst = m0 / KNB;
        int pcur = pfirst;
        float mx = -FLT_MAX, mn = FLT_MAX;
        for (int rr = 0; rr < 128; rr++) {
            int p = (m0 + rr) / KNB;
            if (p != pcur) {
                size_t o = ((size_t)blockIdx.y*8 + (pcur - pfirst))*128 + t;
                g_fmx[o] = mx; g_fmn[o] = mn;
                mx = -FLT_MAX; mn = FLT_MAX; pcur = p;
            }
            float v = stile[rr*132 + t];
            s += v; q = fmaf(v, v, q);
            mx = fmaxf(mx, v); mn = fminf(mn, v);
        }
        size_t o = ((size_t)blockIdx.y*8 + (pcur - pfirst))*128 + t;
        g_fmx[o] = mx; g_fmn[o] = mn;
        g_feat_part[(size_t)blockIdx.y*256 + t]       = s;
        g_feat_part[(size_t)blockIdx.y*256 + 128 + t] = q;
    }
#endif
}

// =====================================================================
// tensor GEMM wrappers
// =====================================================================
__global__ void __launch_bounds__(256, 1)
tgemm(const __nv_bfloat16* __restrict__ Ah, const __nv_bfloat16* __restrict__ Al,
      const __nv_bfloat16* __restrict__ Bh, const __nv_bfloat16* __restrict__ Bl,
      float* __restrict__ C, int lda, int ldb, int ldc, int nkc)
{
#if HAS_TC
    extern __shared__ char sm[];
    uint32_t raw = smem_u32(sm);
    uint32_t base = (raw + 1023) & ~1023u;
    tgemm_core(sm + (base - raw), base, Ah, Al, Bh, Bl, C, lda, ldb, ldc, nkc,
               blockIdx.y*128, blockIdx.x*128);
#else
    tgemm_core_simt(Ah, Al, Bh, Bl, C, lda, ldb, ldc, nkc, blockIdx.y*128, blockIdx.x*128);
#endif
}

__global__ void __launch_bounds__(256, 1)
qkv_gemm()
{
    int z = blockIdx.z;
    const __nv_bfloat16* Bh = (z==0) ? g_wqh : (z==1) ? g_wkh : g_wvh;
    const __nv_bfloat16* Bl = (z==0) ? g_wql : (z==1) ? g_wkl : g_wvl;
    float* C = (z==0) ? g_q : (z==1) ? g_k : g_v;
#if HAS_TC
    extern __shared__ char sm[];
    uint32_t raw = smem_u32(sm);
    uint32_t base = (raw + 1023) & ~1023u;
    tgemm_core(sm + (base - raw), base, g_xh, g_xl, Bh, Bl, C, CO, CO, CO, 4,
               blockIdx.y*128, blockIdx.x*128);
#else
    tgemm_core_simt(g_xh, g_xl, Bh, Bl, C, CO, CO, CO, 4, blockIdx.y*128, blockIdx.x*128);
#endif
}

// =====================================================================
// BN stats (fp32 partials, double combine) — small tensors
// =====================================================================
__device__ __forceinline__ void bn_partial_region(const float* X, long rows,
                                                  int nblk, int blk, int region)
{
    int c = threadIdx.x;
    long per = (rows + nblk - 1) / nblk;
    long r0 = (long)blk * per;
    long r1 = r0 + per; if (r1 > rows) r1 = rows;
    float a0=0,a1=0,a2=0,a3=0, q0=0,q1=0,q2=0,q3=0;
    long r = r0;
    for (; r + 4 <= r1; r += 4) {
        float v0 = X[(r+0)*CO + c], v1 = X[(r+1)*CO + c];
        float v2 = X[(r+2)*CO + c], v3 = X[(r+3)*CO + c];
        a0 += v0; q0 = fmaf(v0,v0,q0);
        a1 += v1; q1 = fmaf(v1,v1,q1);
        a2 += v2; q2 = fmaf(v2,v2,q2);
        a3 += v3; q3 = fmaf(v3,v3,q3);
    }
    for (; r < r1; r++) { float v = X[r*CO + c]; a0 += v; q0 = fmaf(v,v,q0); }
    g_partf[((size_t)region*2 + 0)*CO + c] = (a0+a1) + (a2+a3);
    g_partf[((size_t)region*2 + 1)*CO + c] = (q0+q1) + (q2+q3);
}

__global__ void bn_stats_partial(const float* __restrict__ X, long rows)
{
    bn_partial_region(X, rows, gridDim.x, blockIdx.x, blockIdx.x);
}

__global__ void bn_stats_final(int nblocks, long rows, float* msc)
{
    int c = threadIdx.x;
    double s = 0.0, s2 = 0.0;
    for (int i = 0; i < nblocks; i++) {
        s  += (double)g_partf[((size_t)i*2 + 0)*CO + c];
        s2 += (double)g_partf[((size_t)i*2 + 1)*CO + c];
    }
    double mean = s / (double)rows;
    double var  = s2 / (double)rows - mean*mean;
    msc[c]      = (float)mean;
    msc[CO + c] = (float)(1.0 / sqrt(var + (double)EPSB));
}

__global__ void bn_stats_qkv()
{
    const float* X = (blockIdx.y==0) ? g_q : (blockIdx.y==1) ? g_k : g_v;
    bn_partial_region(X, MTOT, 64, blockIdx.x, blockIdx.y*64 + blockIdx.x);
}
__global__ void bn_final_qkv(float* msc)
{
    int y = blockIdx.x;
    int c = threadIdx.x;
    double s = 0.0, s2 = 0.0;
    for (int i = y*64; i < y*64 + 64; i++) {
        s  += (double)g_partf[((size_t)i*2 + 0)*CO + c];
        s2 += (double)g_partf[((size_t)i*2 + 1)*CO + c];
    }
    double mean = s / (double)MTOT;
    double var  = s2 / (double)MTOT - mean*mean;
    msc[(2+y)*512 + c]      = (float)mean;
    msc[(2+y)*512 + CO + c] = (float)(1.0 / sqrt(var + (double)EPSB));
}

// =====================================================================
// branch BN + relu + maxpool (monotonicity, both halves)
// =====================================================================
__global__ void branch_apply(const float* msc,
                             const float* __restrict__ g_geo, const float* __restrict__ b_geo,
                             const float* __restrict__ g_fea, const float* __restrict__ b_fea)
{
    int m = blockIdx.x;
    int c = threadIdx.x;
    float mean = msc[c], istd = msc[CO + c];
    float ga = (c < 128) ? g_geo[c] : g_fea[c - 128];
    float be = (c < 128) ? b_geo[c] : b_fea[c - 128];
    float sc = istd * ga;
    float best;
    if (c < 128) {
        float zv = (sc >= 0.0f) ? g_zmx[(size_t)m*128 + c] : g_zmn[(size_t)m*128 + c];
        best = fmaxf((zv - mean) * sc + be, 0.0f);
    } else {
        int cc = c - 128;
        int r0 = m * KNB;
        int t1 = r0 / 128,        s1 = m - (t1*128)/KNB;
        int t2 = (r0 + KNB-1)/128, s2 = m - (t2*128)/KNB;
        size_t o1 = ((size_t)t1*8 + s1)*128 + cc;
        size_t o2 = ((size_t)t2*8 + s2)*128 + cc;
        float zv;
        if (sc >= 0.0f) zv = fmaxf(g_fmx[o1], g_fmx[o2]);
        else            zv = fminf(g_fmn[o1], g_fmn[o2]);
        best = fmaxf((zv - mean) * sc + be, 0.0f);
    }
    g_featv[(size_t)m*CO + c] = best;
}

// =====================================================================
// BN apply variants
// =====================================================================
__global__ void bn_apply(const float* __restrict__ in, float* __restrict__ out,
                         const float* msc,
                         const float* __restrict__ gamma, const float* __restrict__ beta,
                         const float* __restrict__ res, int do_relu)
{
    size_t i = (size_t)blockIdx.x * blockDim.x + threadIdx.x;
    int c = (int)(i & (CO-1));
    float y = (in[i] - msc[c]) * msc[CO + c] * gamma[c] + beta[c];
    if (do_relu) y = fmaxf(y, 0.0f);
    if (res) y += res[i];
    out[i] = y;
}

__global__ void bn_apply_split(const float* __restrict__ in,
                               const float* msc,
                               const float* __restrict__ gamma, const float* __restrict__ beta,
                               int do_relu,
                               __nv_bfloat16* __restrict__ oh, __nv_bfloat16* __restrict__ ol)
{
    size_t i = (size_t)blockIdx.x * blockDim.x + threadIdx.x;
    int c = (int)(i & (CO-1));
    float y = (in[i] - msc[c]) * msc[CO + c] * gamma[c] + beta[c];
    if (do_relu) y = fmaxf(y, 0.0f);
    __nv_bfloat16 hb = __float2bfloat16(y);
    oh[i] = hb;
    ol[i] = __float2bfloat16(y - __bfloat162float(hb));
}

__global__ void bn_apply_qkv(const float* msc,
                             const float* __restrict__ gq, const float* __restrict__ bq,
                             const float* __restrict__ gk, const float* __restrict__ bk,
                             const float* __restrict__ gv, const float* __restrict__ bv)
{
    int y = blockIdx.y;
    size_t i = (size_t)blockIdx.x * 256 + threadIdx.x;
    int c = (int)(i & (CO-1));
    const float* in = (y==0) ? g_q : (y==1) ? g_k : g_v;
    const float* ga = (y==0) ? gq : (y==1) ? gk : gv;
    const float* be = (y==0) ? bq : (y==1) ? bk : bv;
    const float* ms = msc + (2+y)*512;
    float v = fmaxf((in[i] - ms[c]) * ms[CO + c] * ga[c] + be[c], 0.0f);
    if (y == 2) { g_v[i] = v; return; }
    __nv_bfloat16 hb = __float2bfloat16(v);
    __nv_bfloat16 lb = __float2bfloat16(v - __bfloat162float(hb));
    if (y == 0) { g_qh[i] = hb; g_ql[i] = lb; }
    else        { g_kh[i] = hb; g_kl[i] = lb; }
}

// =====================================================================
// fused weight splits
// =====================================================================
__global__ void split_weights(const float* __restrict__ Wf, const float* __restrict__ Wq,
                              const float* __restrict__ Wk, const float* __restrict__ Wv,
                              const float* __restrict__ Wfus, const float* __restrict__ Wm)
{
    int i = blockIdx.x*256 + threadIdx.x;
    const float* src; __nv_bfloat16 *dh, *dl; int off;
    if      (i < 16384)  { src = Wf;   dh = g_wfh;   dl = g_wfl;   off = i; }
    else if (i < 81920)  { src = Wq;   dh = g_wqh;   dl = g_wql;   off = i - 16384; }
    else if (i < 147456) { src = Wk;   dh = g_wkh;   dl = g_wkl;   off = i - 81920; }
    else if (i < 212992) { src = Wv;   dh = g_wvh;   dl = g_wvl;   off = i - 147456; }
    else if (i < 327680) { src = Wfus; dh = g_wfush; dl = g_wfusl; off = i - 212992; }
    else                 { src = Wm;   dh = g_wmh;   dl = g_wml;   off = i - 327680; }
    float v = src[off];
    __nv_bfloat16 hb = __float2bfloat16(v);
    dh[off] = hb;
    dl[off] = __float2bfloat16(v - __bfloat162float(hb));
}

// =====================================================================
// v -> per-head transposed bf16 split
// =====================================================================
__global__ void vt_convert()
{
    __shared__ float tile[32][33];
    int z  = blockIdx.z;
    int b  = z / HEADS, h = z - b*HEADS;
    int m0 = blockIdx.x * 32;
    int c0 = blockIdx.y * 32;
    int tx = threadIdx.x, ty = threadIdx.y;
#pragma unroll
    for (int i = 0; i < 32; i += 8)
        tile[ty+i][tx] = g_v[((size_t)(b*NN) + m0 + ty + i)*CO + h*32 + c0 + tx];
    __syncthreads();
#pragma unroll
    for (int i = 0; i < 32; i += 8) {
        int c = c0 + ty + i, m = m0 + tx;
        float v = tile[tx][ty+i];
        __nv_bfloat16 hb = __float2bfloat16(v);
        size_t o = (size_t)z*WCH*NN + (size_t)c*NN + m;
        g_vth[o] = hb;
        g_vtl[o] = __float2bfloat16(v - __bfloat162float(hb));
    }
}

// =====================================================================
// FLASH pass 1: per-row softmax stats
// grid (16 m-tiles, 28 z), 256 threads.
// =====================================================================
#define ST_SMEM (1024 + 65536 + 64 + 1088)

__global__ void __launch_bounds__(256, 1)
attn_stats()
{
#if HAS_TC
    extern __shared__ char sm[];
    uint32_t raw = smem_u32(sm);
    uint32_t base = (raw + 1023) & ~1023u;
    char* sb = sm + (base - raw);
    uint32_t ctrl = base + 65536;
    uint32_t mbar = ctrl + 8;
    float* mrg = (float*)(sb + 65536 + 64);   // 128 x {mx,sum}

    int t = threadIdx.x;
    int z = blockIdx.y;
    int b = z / HEADS, h = z - b*HEADS;
    int m0 = blockIdx.x * 128;

    if (t == 0) MBARRIER_INIT(mbar, 1);
    if (t < 32) { TCGEN05_ALLOC(ctrl, 128); TCGEN05_RELINQ(); }
    __syncthreads();
    uint32_t tmem;
    asm volatile("ld.shared.b32 %0, [%1];" : "=r"(tmem) : "r"(ctrl));

    const __nv_bfloat16* pQh = g_qh + ((size_t)(b*NN) + m0)*CO + h*32;
    const __nv_bfloat16* pQl = g_ql + ((size_t)(b*NN) + m0)*CO + h*32;
    const __nv_bfloat16* pKh = g_kh + ((size_t)b*NN)*CO + h*32;
    const __nv_bfloat16* pKl = g_kl + ((size_t)b*NN)*CO + h*32;

    int rb = t >> 4, kq = t & 15;
#pragma unroll
    for (int i = 0; i < 8; i++) {
        int r = rb + i*16;
        uint32_t so = swz((uint32_t)(r*128 + kq*8));
        *(uint2*)(sb + 0*16384 + so) = *(const uint2*)(pQh + (size_t)r*CO + kq*4);
        *(uint2*)(sb + 1*16384 + so) = *(const uint2*)(pQl + (size_t)r*CO + kq*4);
    }

    uint64_t dQh = make_desc(base + 0*16384);
    uint64_t dQl = make_desc(base + 1*16384);
    uint64_t dKh = make_desc(base + 2*16384);
    uint64_t dKl = make_desc(base + 3*16384);

    int w = t >> 5, lane = t & 31;
    int sub = w & 3, half = w >> 2;
    int rrow = sub*32 + lane;

    float mx = -FLT_MAX, sum = 0.0f;

    for (int nc = 0; nc < 16; nc++) {
        int n0 = nc*128;
#pragma unroll
        for (int i = 0; i < 8; i++) {
            int r = rb + i*16;
            uint32_t so = swz((uint32_t)(r*128 + kq*8));
            *(uint2*)(sb + 2*16384 + so) = *(const uint2*)(pKh + (size_t)(n0+r)*CO + kq*4);
            *(uint2*)(sb + 3*16384 + so) = *(const uint2*)(pKl + (size_t)(n0+r)*CO + kq*4);
        }
        __syncthreads();
        if (t < 32) {
            if (elect_one_pred()) {
                FENCE_ASYNC_SHARED();
#pragma unroll
                for (int ks = 0; ks < 4; ks++) {
                    uint64_t o = ks*2;
                    mma_f16_ss(tmem, dQh+o, dKh+o, IDESC_N128, (ks > 0) ? 1u : 0u);
                    mma_f16_ss(tmem, dQh+o, dKl+o, IDESC_N128, 1u);
                    mma_f16_ss(tmem, dQl+o, dKh+o, IDESC_N128, 1u);
                }
                TCGEN05_COMMIT(mbar);
            }
        }
        MBARRIER_WAIT_PARITY(mbar, nc & 1);
        TCGEN05_FENCE_AFTER();
#pragma unroll
        for (int gi = 0; gi < 2; gi++) {
            int g = half*2 + gi;
            uint32_t r[32];
            TCGEN05_LD_X32(r, tmem + g*32);
            TCGEN05_WAIT_LD();
            float gm = -FLT_MAX;
#pragma unroll
            for (int j = 0; j < 32; j++) gm = fmaxf(gm, __uint_as_float(r[j]));
            float gs = 0.0f;
#pragma unroll
            for (int j = 0; j < 32; j++) gs += __expf(__uint_as_float(r[j]) - gm);
            if (gm <= mx) sum += gs * __expf(gm - mx);
            else { sum = sum * __expf(mx - gm) + gs; mx = gm; }
        }
        __syncthreads();   // all LDTMs done before next MMA overwrites S
    }

    if (half == 0) { mrg[rrow*2] = mx; mrg[rrow*2+1] = sum; }
    __syncthreads();
    if (half == 1) {
        float m2 = mrg[rrow*2], s2 = mrg[rrow*2+1];
        float M = fmaxf(mx, m2);
        float S = s2 * __expf(m2 - M) + sum * __expf(mx - M);
        size_t row = (size_t)z*NN + m0 + rrow;
        g_rowstat[row*2]   = M;
        g_rowstat[row*2+1] = 1.0f / S;
    }
    __syncthreads();
    if (t < 32) TCGEN05_DEALLOC(tmem, 128);
#else
    int t = threadIdx.x;
    int z = blockIdx.y;
    int b = z / HEADS, h = z - b*HEADS;
    int m0 = blockIdx.x * 128;
    if (t >= 128) return;
    int m = m0 + t;
    const float* qp = g_q + ((size_t)(b*NN) + m)*CO + h*32;
    float mx = -FLT_MAX;
    for (int n = 0; n < NN; n++) {
        const float* kp = g_k + ((size_t)(b*NN) + n)*CO + h*32;
        float acc = 0.0f;
        for (int k = 0; k < 64; k++) acc = fmaf(qp[k], kp[k], acc);
        mx = fmaxf(mx, acc);
    }
    float sum = 0.0f;
    for (int n = 0; n < NN; n++) {
        const float* kp = g_k + ((size_t)(b*NN) + n)*CO + h*32;
        float acc = 0.0f;
        for (int k = 0; k < 64; k++) acc = fmaf(qp[k], kp[k], acc);
        sum += __expf(acc - mx);
    }
    size_t row = (size_t)z*NN + m;
    g_rowstat[row*2] = mx; g_rowstat[row*2+1] = 1.0f / sum;
#endif
}

// =====================================================================
// FLASH pass 2: recompute S, softmax, P·V in TMEM
// grid (16 m-tiles, 28 z), 256 threads.
// TMEM: S cols 0..127, O cols 128..191 (alloc 256)
// =====================================================================
#define FL_SMEM (1024 + 163840 + 64 + 1088)

__global__ void __launch_bounds__(256, 1)
attn_flash()
{
#if HAS_TC
    extern __shared__ char sm[];
    uint32_t raw = smem_u32(sm);
    uint32_t base = (raw + 1023) & ~1023u;
    char* sb = sm + (base - raw);
    const uint32_t off_Qh = 0, off_Ql = 16384, off_Kh = 32768, off_Kl = 49152;
    const uint32_t off_Vh = 65536, off_Vl = 81920, off_Ph = 98304, off_Pl = 131072;
    uint32_t ctrl = base + 163840;
    uint32_t mbar_s = ctrl + 8;
    uint32_t mbar_o = ctrl + 16;
    float* sst = (float*)(sb + 163840 + 64);

    int t = threadIdx.x;
    int z = blockIdx.y;
    int b = z / HEADS, h = z - b*HEADS;
    int m0 = blockIdx.x * 128;

    if (t == 0) { MBARRIER_INIT(mbar_s, 1); MBARRIER_INIT(mbar_o, 1); }
    if (t < 32) { TCGEN05_ALLOC(ctrl, 256); TCGEN05_RELINQ(); }
    sst[t] = g_rowstat[(size_t)(z*NN + m0)*2 + t];
    __syncthreads();
    uint32_t tmem;
    asm volatile("ld.shared.b32 %0, [%1];" : "=r"(tmem) : "r"(ctrl));
    uint32_t tmemO = tmem + 128;

    const __nv_bfloat16* pQh = g_qh + ((size_t)(b*NN) + m0)*CO + h*32;
    const __nv_bfloat16* pQl = g_ql + ((size_t)(b*NN) + m0)*CO + h*32;
    const __nv_bfloat16* pKh = g_kh + ((size_t)b*NN)*CO + h*32;
    const __nv_bfloat16* pKl = g_kl + ((size_t)b*NN)*CO + h*32;
    const __nv_bfloat16* Vh = g_vth + (size_t)z*WCH*NN;
    const __nv_bfloat16* Vl = g_vtl + (size_t)z*WCH*NN;

    int rb = t >> 4, kq = t & 15;
#pragma unroll
    for (int i = 0; i < 8; i++) {
        int r = rb + i*16;
        uint32_t so = swz((uint32_t)(r*128 + kq*8));
        *(uint2*)(sb + off_Qh + so) = *(const uint2*)(pQh + (size_t)r*CO + kq*4);
        *(uint2*)(sb + off_Ql + so) = *(const uint2*)(pQl + (size_t)r*CO + kq*4);
    }

    uint64_t dQh = make_desc(base + off_Qh);
    uint64_t dQl = make_desc(base + off_Ql);
    uint64_t dKh = make_desc(base + off_Kh);
    uint64_t dKl = make_desc(base + off_Kl);

    int w = t >> 5, lane = t & 31;
    int sub = w & 3, half = w >> 2;
    int rrow = sub*32 + lane;
    float mxr = sst[rrow*2], invr = sst[rrow*2+1];

    for (int nc = 0; nc < 16; nc++) {
        int n0 = nc*128;
        if (nc > 0) MBARRIER_WAIT_PARITY(mbar_o, (nc-1) & 1);

#pragma unroll
        for (int i = 0; i < 8; i++) {
            int r = rb + i*16;
            uint32_t so = swz((uint32_t)(r*128 + kq*8));
            *(uint2*)(sb + off_Kh + so) = *(const uint2*)(pKh + (size_t)(n0+r)*CO + kq*4);
            *(uint2*)(sb + off_Kl + so) = *(const uint2*)(pKl + (size_t)(n0+r)*CO + kq*4);
        }
#pragma unroll
        for (int i = 0; i < 4; i++) {
            int r = rb + i*16;
            uint32_t so = swz((uint32_t)(r*128 + kq*8));
#pragma unroll
            for (int j = 0; j < 2; j++) {
                size_t gk = (size_t)r*NN + n0 + j*64 + kq*4;
                *(uint2*)(sb + off_Vh + j*8192 + so) = *(const uint2*)(Vh + gk);
                *(uint2*)(sb + off_Vl + j*8192 + so) = *(const uint2*)(Vl + gk);
            }
        }
        __syncthreads();

        // S = Q K^T (fresh accumulator each chunk)
        if (t < 32) {
            if (elect_one_pred()) {
                FENCE_ASYNC_SHARED();
#pragma unroll
                for (int ks = 0; ks < 4; ks++) {
                    uint64_t o = ks*2;
                    mma_f16_ss(tmem, dQh+o, dKh+o, IDESC_N128, (ks > 0) ? 1u : 0u);
                    mma_f16_ss(tmem, dQh+o, dKl+o, IDESC_N128, 1u);
                    mma_f16_ss(tmem, dQl+o, dKh+o, IDESC_N128, 1u);
                }
                TCGEN05_COMMIT(mbar_s);
            }
        }
        MBARRIER_WAIT_PARITY(mbar_s, nc & 1);
        TCGEN05_FENCE_AFTER();

#pragma unroll
        for (int gi = 0; gi < 2; gi++) {
            int g = half*2 + gi;
            uint32_t r[32];
            TCGEN05_LD_X32(r, tmem + g*32);
            TCGEN05_WAIT_LD();
#pragma unroll
            for (int j = 0; j < 8; j++) {
                float v0 = __expf(__uint_as_float(r[j*4+0]) - mxr) * invr;
                float v1 = __expf(__uint_as_float(r[j*4+1]) - mxr) * invr;
                float v2 = __expf(__uint_as_float(r[j*4+2]) - mxr) * invr;
                float v3 = __expf(__uint_as_float(r[j*4+3]) - mxr) * invr;
                __nv_bfloat16 h0 = __float2bfloat16(v0);
                __nv_bfloat16 h1 = __float2bfloat16(v1);
                __nv_bfloat16 h2 = __float2bfloat16(v2);
                __nv_bfloat16 h3 = __float2bfloat16(v3);
                uint32_t so = swz((uint32_t)(rrow*128 + (gi*32 + j*4)*2));
                *(uint2*)(sb + off_Ph + half*16384 + so) = make_uint2(bpackh(h0,h1), bpackh(h2,h3));
                *(uint2*)(sb + off_Pl + half*16384 + so) = make_uint2(
                    bpackh(__float2bfloat16(v0 - __bfloat162float(h0)),
                           __float2bfloat16(v1 - __bfloat162float(h1))),
                    bpackh(__float2bfloat16(v2 - __bfloat162float(h2)),
                           __float2bfloat16(v3 - __bfloat162float(h3))));
            }
        }
        __syncthreads();

        // O += P V^T
        if (t < 32) {
            if (elect_one_pred()) {
                FENCE_ASYNC_SHARED();
#pragma unroll
                for (int kch = 0; kch < 2; kch++) {
                    uint64_t dPh = make_desc(base + off_Ph + kch*16384);
                    uint64_t dPl = make_desc(base + off_Pl + kch*16384);
                    uint64_t dVh2 = make_desc(base + off_Vh + kch*8192);
                    uint64_t dVl2 = make_desc(base + off_Vl + kch*8192);
#pragma unroll
                    for (int ks = 0; ks < 4; ks++) {
                        uint64_t o = ks*2;
                        mma_f16_ss(tmemO, dPh+o, dVh2+o, IDESC_N64,
                                   (nc > 0 || kch > 0 || ks > 0) ? 1u : 0u);
                        mma_f16_ss(tmemO, dPh+o, dVl2+o, IDESC_N64, 1u);
                        mma_f16_ss(tmemO, dPl+o, dVh2+o, IDESC_N64, 1u);
                    }
                }
                TCGEN05_COMMIT(mbar_o);
            }
        }
    }
    MBARRIER_WAIT_PARITY(mbar_o, 1);
    TCGEN05_FENCE_AFTER();

    size_t rbase = (size_t)(b*NN + m0 + rrow)*FUSC + h*64 + half*32;
    {
        uint32_t r[32];
        TCGEN05_LD_X32(r, tmemO + half*32);
        TCGEN05_WAIT_LD();
        TCGEN05_FENCE_BEFORE();
#pragma unroll
        for (int j = 0; j < 8; j++) {
            float v0 = __uint_as_float(r[j*4+0]);
            float v1 = __uint_as_float(r[j*4+1]);
            float v2 = __uint_as_float(r[j*4+2]);
            float v3 = __uint_as_float(r[j*4+3]);
            __nv_bfloat16 h0 = __float2bfloat16(v0);
            __nv_bfloat16 h1 = __float2bfloat16(v1);
            __nv_bfloat16 h2 = __float2bfloat16(v2);
            __nv_bfloat16 h3 = __float2bfloat16(v3);
            *(uint2*)(g_Oh + rbase + j*4) = make_uint2(bpackh(h0,h1), bpackh(h2,h3));
            *(uint2*)(g_Ol + rbase + j*4) = make_uint2(
                bpackh(__float2bfloat16(v0 - __bfloat162float(h0)),
                       __float2bfloat16(v1 - __bfloat162float(h1))),
                bpackh(__float2bfloat16(v2 - __bfloat162float(h2)),
                       __float2bfloat16(v3 - __bfloat162float(h3))));
        }
    }
    __syncthreads();
    if (t < 32) TCGEN05_DEALLOC(tmem, 256);
#else
    int t = threadIdx.x;
    int z = blockIdx.y;
    int b = z / HEADS, h = z - b*HEADS;
    int m0 = blockIdx.x * 128;
    if (t >= 128) return;
    int m = m0 + t;
    const float* qp = g_q + ((size_t)(b*NN) + m)*CO + h*32;
    float mxr = g_rowstat[(size_t)(z*NN + m)*2], invr = g_rowstat[(size_t)(z*NN + m)*2+1];
    for (int c = 0; c < 64; c++) {
        float acc = 0.0f;
        for (int n = 0; n < NN; n++) {
            const float* kp = g_k + ((size_t)(b*NN) + n)*CO + h*32;
            float s = 0.0f;
            for (int k = 0; k < 64; k++) s = fmaf(qp[k], kp[k], s);
            acc = fmaf(__expf(s - mxr)*invr, g_v[((size_t)(b*NN) + n)*CO + h*32 + c], acc);
        }
        size_t o = (size_t)(b*NN + m)*FUSC + h*64 + c;
        __nv_bfloat16 hb = __float2bfloat16(acc);
        g_Oh[o] = hb;
        g_Ol[o] = __float2bfloat16(acc - __bfloat162float(hb));
    }
#endif
}

// =====================================================================
// LayerNorm -> bf16 split
// =====================================================================
__global__ void layernorm_kernel(const float* __restrict__ X,
                                 const float* __restrict__ g, const float* __restrict__ b)
{
    int m = blockIdx.x, c = threadIdx.x;
    __shared__ float red[256];
    float v = X[(size_t)m*CO + c];
    red[c] = v; __syncthreads();
    for (int s = 128; s; s >>= 1) { if (c < s) red[c] += red[c+s]; __syncthreads(); }
    float mean = red[0] * (1.0f/CO); __syncthreads();
    float d = v - mean;
    red[c] = d*d; __syncthreads();
    for (int s = 128; s; s >>= 1) { if (c < s) red[c] += red[c+s]; __syncthreads(); }
    float var = red[0] * (1.0f/CO);
    float y = d * rsqrtf(var + EPSB) * g[c] + b[c];
    __nv_bfloat16 hb = __float2bfloat16(y);
    size_t i = (size_t)m*CO + c;
    g_yh[i] = hb;
    g_yl[i] = __float2bfloat16(y - __bfloat162float(hb));
}

// =====================================================================
// final output (transposed)
// =====================================================================
__global__ void final_out(const float* __restrict__ bias, float* __restrict__ out)
{
    __shared__ float tile[32][33];
    int b  = blockIdx.z;
    int n0 = blockIdx.x * 32;
    int c0 = blockIdx.y * 32;
    int tx = threadIdx.x, ty = threadIdx.y;
#pragma unroll
    for (int i = 0; i < 32; i += 8) {
        int n = n0 + ty + i, c = c0 + tx;
        size_t src = ((size_t)b*NN + n)*CO + c;
        tile[ty+i][tx] = g_f2[src] + g_fp[src] + bias[c];
    }
    __syncthreads();
#pragma unroll
    for (int i = 0; i < 32; i += 8) {
        int c = c0 + ty + i, n = n0 + tx;
        out[((size_t)b*CO + c)*NN + n] = tile[tx][ty+i];
    }
}

// =====================================================================
// host
// =====================================================================
extern "C" void kernel_launch(void* const* d_in, const int* in_sizes, int n_in,
                              void* d_out, int out_size)
{
    const float* xyz    = (const float*)d_in[0];
    const float* f      = (const float*)d_in[1];
    const float* W_geo  = (const float*)d_in[2];
    const float* gg     = (const float*)d_in[3];
    const float* bg     = (const float*)d_in[4];
    const float* W_feat = (const float*)d_in[5];
    const float* gf     = (const float*)d_in[6];
    const float* bf     = (const float*)d_in[7];
    const float* g_bn   = (const float*)d_in[8];
    const float* b_bn   = (const float*)d_in[9];
    const float* W_q    = (const float*)d_in[10];
    const float* gq     = (const float*)d_in[11];
    const float* bq     = (const float*)d_in[12];
    const float* W_k    = (const float*)d_in[13];
    const float* gk     = (const float*)d_in[14];
    const float* bk     = (const float*)d_in[15];
    const float* W_v    = (const float*)d_in[16];
    const float* gv     = (const float*)d_in[17];
    const float* bv     = (const float*)d_in[18];
    const float* W_fus  = (const float*)d_in[19];
    /* d_in[20] bias_fus: cancels inside BN */
    const float* gfu    = (const float*)d_in[21];
    const float* bfu    = (const float*)d_in[22];
    const float* g_ln   = (const float*)d_in[23];
    const float* b_ln   = (const float*)d_in[24];
    const float* W_mlp  = (const float*)d_in[25];
    const float* b_mlp  = (const float*)d_in[26];
    float* out = (float*)d_out;

    float *p_featv, *p_fp, *p_f2, *p_msc;
    __nv_bfloat16 *p_yh, *p_yl, *p_Oh, *p_Ol, *p_xh, *p_xl;
    __nv_bfloat16 *p_wfush, *p_wfusl, *p_wmh, *p_wml;
    cudaGetSymbolAddress((void**)&p_featv, g_featv);
    cudaGetSymbolAddress((void**)&p_fp,    g_fp);
    cudaGetSymbolAddress((void**)&p_f2,    g_f2);
    cudaGetSymbolAddress((void**)&p_msc,   g_msc);
    cudaGetSymbolAddress((void**)&p_xh,    g_xh);
    cudaGetSymbolAddress((void**)&p_xl,    g_xl);
    cudaGetSymbolAddress((void**)&p_yh,    g_yh);
    cudaGetSymbolAddress((void**)&p_yl,    g_yl);
    cudaGetSymbolAddress((void**)&p_Oh,    g_Oh);
    cudaGetSymbolAddress((void**)&p_Ol,    g_Ol);
    cudaGetSymbolAddress((void**)&p_wfush, g_wfush);
    cudaGetSymbolAddress((void**)&p_wfusl, g_wfusl);
    cudaGetSymbolAddress((void**)&p_wmh,   g_wmh);
    cudaGetSymbolAddress((void**)&p_wml,   g_wml);

    cudaFuncSetAttribute(attn_stats, cudaFuncAttributeMaxDynamicSharedMemorySize, ST_SMEM);
    cudaFuncSetAttribute(attn_flash, cudaFuncAttributeMaxDynamicSharedMemorySize, FL_SMEM);
    cudaFuncSetAttribute(tgemm,      cudaFuncAttributeMaxDynamicSharedMemorySize, TG_SMEM);
    cudaFuncSetAttribute(qkv_gemm,   cudaFuncAttributeMaxDynamicSharedMemorySize, TG_SMEM);
    cudaFuncSetAttribute(feat_gemm,  cudaFuncAttributeMaxDynamicSharedMemorySize, FEAT_SMEM);

    // ---- 0. weight splits
    split_weights<<<1536, 256>>>(W_feat, W_q, W_k, W_v, W_fus, W_mlp);

    // ---- 1. KNN + transpose + geo (max/min + fused stats)
    knn_kernel<<<MTOT, 256>>>(xyz);
    transpose_f<<<dim3(NN/32, CIN/32, BB), dim3(32,8)>>>(f);
    geo_pre<<<NGEOREG, 128>>>(xyz, W_geo);

    // ---- 2. feat GEMM (inline gather; epilogue -> max/min partials + stats)
    feat_gemm<<<dim3(1, NFEATCTA), 256, FEAT_SMEM>>>();

    // ---- 3. act stats (hierarchical combines) + branch apply
    act_combine<<<128, 128>>>();
    bn_stats_act<<<1, 256>>>(p_msc + 0*512);
    branch_apply<<<MTOT, 256>>>(p_msc + 0*512, gg, bg, gf, bf);

    // ---- 4. BatchNorm1d -> x split
    bn_stats_partial<<<32, 256>>>(p_featv, MTOT);
    bn_stats_final<<<1, 256>>>(32, MTOT, p_msc + 1*512);
    bn_apply_split<<<MTOT, 256>>>(p_featv, p_msc + 1*512, g_bn, b_bn, 0, p_xh, p_xl);

    // ---- 5. q/k/v merged GEMM + stats + apply
    qkv_gemm<<<dim3(2, MTOT/128, 3), 256, TG_SMEM>>>();
    bn_stats_qkv<<<dim3(64, 3), 256>>>();
    bn_final_qkv<<<3, 256>>>(p_msc);
    bn_apply_qkv<<<dim3(MTOT*CO/256, 3), 256>>>(p_msc, gq, bq, gk, bk, gv, bv);
    vt_convert<<<dim3(NN/32, 2, BB*HEADS), dim3(32,8)>>>();

    // ---- 6. flash attention (two kernels, no prefetch — measured best)
    attn_stats<<<dim3(16, BB*HEADS), 256, ST_SMEM>>>();
    attn_flash<<<dim3(16, BB*HEADS), 256, FL_SMEM>>>();

    // ---- 7. fus + residual
    tgemm<<<dim3(2, MTOT/128), 256, TG_SMEM>>>(p_Oh, p_Ol, p_wfush, p_wfusl,
                                               p_fp, FUSC, FUSC, CO, 7);
    bn_stats_partial<<<32, 256>>>(p_fp, MTOT);
    bn_stats_final<<<1, 256>>>(32, MTOT, p_msc + 5*512);
    bn_apply<<<MTOT, 256>>>(p_fp, p_f2, p_msc + 5*512, gfu, bfu, p_featv, 1);

    // ---- 8. layernorm + mlp + out
    layernorm_kernel<<<MTOT, 256>>>(p_f2, g_ln, b_ln);
    tgemm<<<dim3(2, MTOT/128), 256, TG_SMEM>>>(p_yh, p_yl, p_wmh, p_wml, p_fp, CO, CO, CO, 4);
    final_out<<<dim3(NN/32, CO/32, BB), dim3(32,8)>>>(b_mlp, out);

    (void)in_sizes; (void)n_in; (void)out_size;
}